// round 10
// baseline (speedup 1.0000x reference)
#include <cuda_runtime.h>
#include <cuda_fp16.h>
#include <math.h>
#include <stdint.h>

// ---------------- problem constants ----------------
#define BB 4
#define QQ 600
#define LL 2048
#define DD 256
#define HH 8
#define HD 32
#define DFF 2048
#define KD 32
#define SCALE 0.17677669529663687f   // 32^-0.5
#define NQT 10                       // ceil(600/64) 64-query tiles

typedef unsigned long long u64;

// ---------------- helpers ----------------
__device__ __forceinline__ uint32_t f2tf32(float x) {
    uint32_t u; asm("cvt.rna.tf32.f32 %0, %1;" : "=r"(u) : "f"(x)); return u;
}
__device__ __forceinline__ void mma8(float c[4], uint32_t a0, uint32_t a1,
                                     uint32_t a2, uint32_t a3,
                                     uint32_t b0, uint32_t b1) {
    asm("mma.sync.aligned.m16n8k8.row.col.f32.tf32.tf32.f32 "
        "{%0,%1,%2,%3},{%4,%5,%6,%7},{%8,%9},{%0,%1,%2,%3};"
        : "+f"(c[0]), "+f"(c[1]), "+f"(c[2]), "+f"(c[3])
        : "r"(a0), "r"(a1), "r"(a2), "r"(a3), "r"(b0), "r"(b1));
}
__device__ __forceinline__ void mma16h(float c[4], uint32_t a0, uint32_t a1,
                                       uint32_t a2, uint32_t a3,
                                       uint32_t b0, uint32_t b1) {
    asm("mma.sync.aligned.m16n8k16.row.col.f32.f16.f16.f32 "
        "{%0,%1,%2,%3},{%4,%5,%6,%7},{%8,%9},{%0,%1,%2,%3};"
        : "+f"(c[0]), "+f"(c[1]), "+f"(c[2]), "+f"(c[3])
        : "r"(a0), "r"(a1), "r"(a2), "r"(a3), "r"(b0), "r"(b1));
}
__device__ __forceinline__ void ldsm4(uint32_t& r0, uint32_t& r1,
                                      uint32_t& r2, uint32_t& r3, uint32_t addr) {
    asm volatile("ldmatrix.sync.aligned.m8n8.x4.shared.b16 {%0,%1,%2,%3}, [%4];"
                 : "=r"(r0), "=r"(r1), "=r"(r2), "=r"(r3) : "r"(addr));
}
__device__ __forceinline__ void cp16(uint32_t dst, const void* src, int srcsize) {
    asm volatile("cp.async.ca.shared.global [%0], [%1], 16, %2;"
                 :: "r"(dst), "l"(src), "r"(srcsize));
}
__device__ __forceinline__ void cp_commit() {
    asm volatile("cp.async.commit_group;");
}
template<int N>
__device__ __forceinline__ void cp_wait() {
    asm volatile("cp.async.wait_group %0;" :: "n"(N));
}

// ---------------- scratch (device globals) ----------------
__device__ float s_qkv [BB*QQ*3*DD];
__device__ float s_x1  [BB*QQ*DD];
__device__ float s_x2  [BB*QQ*DD];
__device__ float s_q   [BB*QQ*DD];
__device__ float s_k   [BB*LL*DD];
__device__ float s_v   [BB*LL*DD];
__device__ float s_bias[BB*LL*QQ];
__device__ float s_part[4*BB*QQ*DD];
__device__ float s_pm  [BB*HH*8*QQ];
__device__ float s_pl  [BB*HH*8*QQ];
__device__ float s_pacc[BB*HH*8*QQ*HD];
// fp16 copies
__device__ __half h_queries[BB*QQ*DD];
__device__ __half h_memory [BB*LL*DD];
__device__ __half h_sa_in_w[3*DD*DD];
__device__ __half h_sa_out_w[DD*DD];
__device__ __half h_q_w[DD*DD];
__device__ __half h_k_w[DD*DD];
__device__ __half h_v_w[DD*DD];
__device__ __half h_o_w[DD*DD];
__device__ __half h_ffn_w1[DFF*DD];
__device__ __half h_ffn_w2[DD*DFF];
__device__ __half h_sa [BB*QQ*DD];
__device__ __half h_ca [BB*QQ*DD];
__device__ __half h_x1 [BB*QQ*DD];
__device__ __half h_x2 [BB*QQ*DD];
__device__ __half h_ffn[BB*QQ*DFF];

// ---------------- fp32 -> fp16 convert (8 elts/thread) ----------------
__global__ __launch_bounds__(256) void f2h_kernel(
    const float* __restrict__ src, __half* __restrict__ dst, int n)
{
    int i = (blockIdx.x * 256 + threadIdx.x) * 8;
    if (i >= n) return;
    float4 x0 = *reinterpret_cast<const float4*>(src + i);
    float4 x1 = *reinterpret_cast<const float4*>(src + i + 4);
    __half2 h0 = __floats2half2_rn(x0.x, x0.y);
    __half2 h1 = __floats2half2_rn(x0.z, x0.w);
    __half2 h2 = __floats2half2_rn(x1.x, x1.y);
    __half2 h3 = __floats2half2_rn(x1.z, x1.w);
    uint4 u;
    u.x = *reinterpret_cast<uint32_t*>(&h0);
    u.y = *reinterpret_cast<uint32_t*>(&h1);
    u.z = *reinterpret_cast<uint32_t*>(&h2);
    u.w = *reinterpret_cast<uint32_t*>(&h3);
    *reinterpret_cast<uint4*>(dst + i) = u;
}

// ---------------- FP16 tensor-core GEMM (cp.async + ldmatrix, 32k stages) --
#define KP 40      // halves per smem row (80B pitch: 16B segs conflict-free)
#define NST 3

template<int MF>
__global__ __launch_bounds__(256) void gemm_f16_kernel(
    const __half* __restrict__ A, const __half* __restrict__ W,
    const float* __restrict__ bias, float* C, __half* Ch,
    int M, int N, int K, int relu,
    const __half* __restrict__ W2 = nullptr,
    const float* __restrict__ bias2 = nullptr,
    float* C2 = nullptr, __half* C2h = nullptr)
{
    __shared__ __align__(16) __half As[NST][64 * MF][KP];
    __shared__ __align__(16) __half Ws[NST][64][KP];

    const int tid = threadIdx.x;
    const int lane = tid & 31;
    const int w = tid >> 5;
    const int wm = w & 3;
    const int wn = w >> 2;
    const int g = lane >> 2;
    const int t = lane & 3;

    int bx = blockIdx.x;
    const int nblk = N / 64;
    if (W2 != nullptr && bx >= nblk) {
        bx -= nblk;
        W = W2; bias = bias2; C = C2; Ch = C2h;
    }

    const int m0 = blockIdx.y * (64 * MF);
    const int n0 = bx * 64;

    const int nsplit = gridDim.z;
    const int Klen = K / nsplit;
    const int kstart = blockIdx.z * Klen;
    float* Cout = (C && nsplit > 1) ? (C + (size_t)blockIdx.z * M * N) : C;

    const uint32_t as_base = (uint32_t)__cvta_generic_to_shared(&As[0][0][0]);
    const uint32_t ws_base = (uint32_t)__cvta_generic_to_shared(&Ws[0][0][0]);

    float acc[MF][4][4];
    #pragma unroll
    for (int i = 0; i < MF; i++)
        #pragma unroll
        for (int j = 0; j < 4; j++)
            #pragma unroll
            for (int e = 0; e < 4; e++) acc[i][j][e] = 0.f;

    const int m_warp = wm * (16 * MF);
    const int n_warp = wn * 32;
    const int nIter = Klen / 32;          // 32-k stages

    // ldmatrix lane addressing (koff within a 16-k sub-chunk)
    const int lr8 = lane & 7;
    const int lb1 = (lane >> 3) & 1;
    const int lb2 = (lane >> 4) & 1;
    uint32_t aAddr[MF];
    #pragma unroll
    for (int mi = 0; mi < MF; mi++) {
        int row = m_warp + mi * 16 + lr8 + lb1 * 8;
        aAddr[mi] = as_base + (row * KP + lb2 * 8) * 2;
    }
    uint32_t bAddr[2];
    #pragma unroll
    for (int p = 0; p < 2; p++) {
        int row = n_warp + p * 16 + lb2 * 8 + lr8;
        bAddr[p] = ws_base + (row * KP + lb1 * 8) * 2;
    }
    const uint32_t aStride = (64 * MF) * KP * 2;
    const uint32_t bStride = 64 * KP * 2;

    // stage loader: 32 halves (64B) per row = 4 cp16 per row
    auto load_stage = [&](int st, int it) {
        const int kg = kstart + it * 32;
        if (MF == 2) {
            #pragma unroll
            for (int s = 0; s < 2; s++) {
                int idx = tid + s * 256;
                int r = idx >> 2, kc = (idx & 3) * 8;
                int arow = m0 + r;
                uint32_t dst = as_base + ((st * 128 + r) * KP + kc) * 2;
                cp16(dst, A + (size_t)arow * K + kg + kc, (arow < M) ? 16 : 0);
            }
            {
                int r = tid >> 2, kc = (tid & 3) * 8;
                uint32_t dst = ws_base + ((st * 64 + r) * KP + kc) * 2;
                cp16(dst, W + (size_t)(n0 + r) * K + kg + kc, 16);
            }
        } else {
            int r = tid >> 2, kc = (tid & 3) * 8;
            int arow = m0 + r;
            uint32_t dst = as_base + ((st * 64 + r) * KP + kc) * 2;
            cp16(dst, A + (size_t)arow * K + kg + kc, (arow < M) ? 16 : 0);
            uint32_t dst2 = ws_base + ((st * 64 + r) * KP + kc) * 2;
            cp16(dst2, W + (size_t)(n0 + r) * K + kg + kc, 16);
        }
        cp_commit();
    };

    load_stage(0, 0);
    load_stage(1, 1);

    for (int it = 0; it < nIter; it++) {
        cp_wait<NST - 2>();
        __syncthreads();
        if (it + NST - 1 < nIter) load_stage((it + NST - 1) % NST, it + NST - 1);
        else cp_commit();

        const int st = it % NST;
        #pragma unroll
        for (int kk = 0; kk < 32; kk += 16) {
            uint32_t b0[4], b1[4];
            ldsm4(b0[0], b1[0], b0[1], b1[1], bAddr[0] + st * bStride + kk * 2);
            ldsm4(b0[2], b1[2], b0[3], b1[3], bAddr[1] + st * bStride + kk * 2);
            #pragma unroll
            for (int mi = 0; mi < MF; mi++) {
                uint32_t a0, a1, a2, a3;
                ldsm4(a0, a1, a2, a3, aAddr[mi] + st * aStride + kk * 2);
                #pragma unroll
                for (int ni = 0; ni < 4; ni++)
                    mma16h(acc[mi][ni], a0, a1, a2, a3, b0[ni], b1[ni]);
            }
        }
    }

    #pragma unroll
    for (int mi = 0; mi < MF; mi++) {
        #pragma unroll
        for (int ni = 0; ni < 4; ni++) {
            int col = n0 + n_warp + ni * 8 + 2 * t;
            float bz0 = 0.f, bz1 = 0.f;
            if (nsplit == 1) { bz0 = bias[col]; bz1 = bias[col + 1]; }
            int r0 = m0 + m_warp + mi * 16 + g;
            int r1 = r0 + 8;
            float v0 = acc[mi][ni][0] + bz0, v1 = acc[mi][ni][1] + bz1;
            float v2 = acc[mi][ni][2] + bz0, v3 = acc[mi][ni][3] + bz1;
            if (relu) {
                v0 = fmaxf(v0, 0.f); v1 = fmaxf(v1, 0.f);
                v2 = fmaxf(v2, 0.f); v3 = fmaxf(v3, 0.f);
            }
            if (Cout) {
                if (r0 < M) *reinterpret_cast<float2*>(Cout + (size_t)r0 * N + col) = make_float2(v0, v1);
                if (r1 < M) *reinterpret_cast<float2*>(Cout + (size_t)r1 * N + col) = make_float2(v2, v3);
            }
            if (Ch) {
                if (r0 < M) {
                    __half2 hv = __floats2half2_rn(v0, v1);
                    *reinterpret_cast<uint32_t*>(Ch + (size_t)r0 * N + col) =
                        *reinterpret_cast<uint32_t*>(&hv);
                }
                if (r1 < M) {
                    __half2 hv = __floats2half2_rn(v2, v3);
                    *reinterpret_cast<uint32_t*>(Ch + (size_t)r1 * N + col) =
                        *reinterpret_cast<uint32_t*>(&hv);
                }
            }
        }
    }
}

// ---------------- warp-per-row LayerNorm core ----------------
__device__ __forceinline__ void lnw_finish(
    float v[8], int lane, const float* g, const float* bt,
    float* out, __half* outh, size_t row)
{
    float s1 = 0.f, s2 = 0.f;
    #pragma unroll
    for (int i = 0; i < 8; i++) { s1 += v[i]; s2 += v[i] * v[i]; }
    #pragma unroll
    for (int o = 16; o > 0; o >>= 1) {
        s1 += __shfl_xor_sync(0xffffffffu, s1, o);
        s2 += __shfl_xor_sync(0xffffffffu, s2, o);
    }
    float mean = s1 * (1.f / DD);
    float var = s2 * (1.f / DD) - mean * mean;
    float rstd = rsqrtf(var + 1e-5f);
    int c0 = lane * 8;
    float r[8];
    #pragma unroll
    for (int i = 0; i < 8; i++)
        r[i] = (v[i] - mean) * rstd * g[c0 + i] + bt[c0 + i];
    if (out) {
        *reinterpret_cast<float4*>(out + row * DD + c0) = make_float4(r[0], r[1], r[2], r[3]);
        *reinterpret_cast<float4*>(out + row * DD + c0 + 4) = make_float4(r[4], r[5], r[6], r[7]);
    }
    if (outh) {
        __half2 h0 = __floats2half2_rn(r[0], r[1]);
        __half2 h1 = __floats2half2_rn(r[2], r[3]);
        __half2 h2 = __floats2half2_rn(r[4], r[5]);
        __half2 h3 = __floats2half2_rn(r[6], r[7]);
        uint4 u;
        u.x = *reinterpret_cast<uint32_t*>(&h0);
        u.y = *reinterpret_cast<uint32_t*>(&h1);
        u.z = *reinterpret_cast<uint32_t*>(&h2);
        u.w = *reinterpret_cast<uint32_t*>(&h3);
        *reinterpret_cast<uint4*>(outh + row * DD + c0) = u;
    }
}

// LN over (X + sum_s parts[s] + fbias) -> out (fp32) / outh (fp16, optional)
__global__ __launch_bounds__(256) void ln_split_kernel(
    const float* __restrict__ X, const float* __restrict__ parts,
    const float* __restrict__ fbias,
    const float* __restrict__ g, const float* __restrict__ bt,
    float* out, __half* outh, int nsplit)
{
    const int lane = threadIdx.x & 31;
    const size_t row = blockIdx.x * 8 + (threadIdx.x >> 5);
    const size_t stride = (size_t)BB * QQ * DD;
    int c0 = lane * 8;
    float v[8];
    float4 x0 = *reinterpret_cast<const float4*>(X + row * DD + c0);
    float4 x1 = *reinterpret_cast<const float4*>(X + row * DD + c0 + 4);
    float4 f0 = *reinterpret_cast<const float4*>(fbias + c0);
    float4 f1 = *reinterpret_cast<const float4*>(fbias + c0 + 4);
    v[0] = x0.x + f0.x; v[1] = x0.y + f0.y; v[2] = x0.z + f0.z; v[3] = x0.w + f0.w;
    v[4] = x1.x + f1.x; v[5] = x1.y + f1.y; v[6] = x1.z + f1.z; v[7] = x1.w + f1.w;
    for (int s = 0; s < nsplit; s++) {
        float4 p0 = *reinterpret_cast<const float4*>(parts + s * stride + row * DD + c0);
        float4 p1 = *reinterpret_cast<const float4*>(parts + s * stride + row * DD + c0 + 4);
        v[0] += p0.x; v[1] += p0.y; v[2] += p0.z; v[3] += p0.w;
        v[4] += p1.x; v[5] += p1.y; v[6] += p1.z; v[7] += p1.w;
    }
    lnw_finish(v, lane, g, bt, out, outh, row);
}

// ---------------- GASA geometric bias: block per (b,l) ----------------
__global__ __launch_bounds__(128) void gasa_bias_kernel(
    const float* __restrict__ qpos, const float* __restrict__ mpos,
    const float* __restrict__ w1, const float* __restrict__ b1,
    const float* __restrict__ w2, const float* __restrict__ b2,
    const float* __restrict__ betap, float* __restrict__ biasT)
{
    const int l = blockIdx.x;
    const int b = blockIdx.y;
    const int tid = threadIdx.x;

    __shared__ float sw1[KD], sb1[KD], sw2[KD], smp[3], sb2, sbeta;
    if (tid < KD) {
        sw1[tid] = w1[tid];
        sb1[tid] = b1[tid];
        sw2[tid] = w2[tid];
    }
    if (tid < 3) smp[tid] = mpos[((size_t)b * LL + l) * 3 + tid];
    if (tid == 3) sb2 = b2[0];
    if (tid == 4) sbeta = betap[0];
    __syncthreads();

    const float mx = smp[0], my = smp[1], mz = smp[2];
    const float bb2 = sb2, bet = sbeta;
    float* orow = biasT + ((size_t)b * LL + l) * QQ;

    for (int q = tid; q < QQ; q += 128) {
        const float* qp = qpos + ((size_t)b * QQ + q) * 3;
        float dx = qp[0] - mx, dy = qp[1] - my, dz = qp[2] - mz;
        float dist = sqrtf(fmaxf(dx * dx + dy * dy + dz * dz, 0.f));
        float s = 0.f;
        #pragma unroll
        for (int k = 0; k < KD; k++) {
            float h = fmaxf(dist * sw1[k] + sb1[k], 0.f);
            s += h * sw2[k];
        }
        s += bb2;
        s = fminf(fmaxf(s, -10.f), 0.f);
        orow[q] = s * bet;
    }
}

// ---------------- tensor-core flash attention partials ----------------
// If dout != nullptr (requires S == 1), writes normalized fp16 output
// directly and skips partial buffers.
__global__ __launch_bounds__(128) void attn_mma_kernel(
    const float* __restrict__ Qp, int qstride,
    const float* __restrict__ Kp, const float* __restrict__ Vp, int kvstride,
    const float* __restrict__ biasT, int Lk, int S, int step,
    float* __restrict__ pm, float* __restrict__ pl, float* __restrict__ pacc,
    int useBias, __half* __restrict__ dout)
{
    const int b = blockIdx.z, h = blockIdx.y;
    const int sp = blockIdx.x / NQT;
    const int qt = blockIdx.x % NQT;
    const int tid = threadIdx.x;
    const int lane = tid & 31;
    const int warp = tid >> 5;
    const int g = lane >> 2;
    const int t = lane & 3;

    const int q0 = qt * 64 + warp * 16;
    const int qg  = q0 + g;
    const int qg8 = q0 + g + 8;
    const int qgc  = min(qg, QQ - 1);
    const int qg8c = min(qg8, QQ - 1);

    const int ls = sp * step;
    const int le = min(ls + step, Lk);

    uint32_t qa[4][4];
    {
        const float* q0p = Qp + ((size_t)(b * QQ + qgc)) * qstride + h * HD;
        const float* q1p = Qp + ((size_t)(b * QQ + qg8c)) * qstride + h * HD;
        #pragma unroll
        for (int ks = 0; ks < 4; ks++) {
            qa[ks][0] = f2tf32(q0p[ks * 8 + t] * SCALE);
            qa[ks][1] = f2tf32(q1p[ks * 8 + t] * SCALE);
            qa[ks][2] = f2tf32(q0p[ks * 8 + t + 4] * SCALE);
            qa[ks][3] = f2tf32(q1p[ks * 8 + t + 4] * SCALE);
        }
    }

    __shared__ uint32_t Ks[16][36];
    __shared__ uint32_t Vt[HD][17];
    __shared__ float    Bsm[16][68];

    float oacc[4][4];
    #pragma unroll
    for (int i = 0; i < 4; i++)
        #pragma unroll
        for (int j = 0; j < 4; j++) oacc[i][j] = 0.f;
    float om0 = -INFINITY, om1 = -INFINITY;
    float ol0 = 0.f, ol1 = 0.f;

    const int key_l = tid >> 3;
    const int d0 = (tid & 7) * 4;
    const int bq0 = (tid & 7) * 8;
    const bool qtail = (qt == NQT - 1);

    float4 kreg, vreg, breg0, breg1;

    auto prefetch = [&](int l0) {
        int grow = b * Lk + min(l0 + key_l, Lk - 1);
        kreg = *reinterpret_cast<const float4*>(
            Kp + (size_t)grow * kvstride + h * HD + d0);
        vreg = *reinterpret_cast<const float4*>(
            Vp + (size_t)grow * kvstride + h * HD + d0);
        if (useBias) {
            const float* brow = biasT + ((size_t)(b * Lk + l0 + key_l)) * QQ
                                + qt * 64 + bq0;
            if (!qtail) {
                breg0 = *reinterpret_cast<const float4*>(brow);
                breg1 = *reinterpret_cast<const float4*>(brow + 4);
            } else {
                int qb = qt * 64 + bq0;
                float e[8];
                #pragma unroll
                for (int i = 0; i < 8; i++)
                    e[i] = (qb + i < QQ) ? brow[i] : 0.f;
                breg0 = make_float4(e[0], e[1], e[2], e[3]);
                breg1 = make_float4(e[4], e[5], e[6], e[7]);
            }
        }
    };

    prefetch(ls);

    for (int l0 = ls; l0 < le; l0 += 16) {
        __syncthreads();
        {
            uint4 ku = make_uint4(f2tf32(kreg.x), f2tf32(kreg.y),
                                  f2tf32(kreg.z), f2tf32(kreg.w));
            *reinterpret_cast<uint4*>(&Ks[key_l][d0]) = ku;
            Vt[d0 + 0][key_l] = f2tf32(vreg.x);
            Vt[d0 + 1][key_l] = f2tf32(vreg.y);
            Vt[d0 + 2][key_l] = f2tf32(vreg.z);
            Vt[d0 + 3][key_l] = f2tf32(vreg.w);
            if (useBias) {
                *reinterpret_cast<float4*>(&Bsm[key_l][bq0]) = breg0;
                *reinterpret_cast<float4*>(&Bsm[key_l][bq0 + 4]) = breg1;
            }
        }
        if (l0 + 16 < le) prefetch(l0 + 16);
        __syncthreads();

        float sc[2][4];
        #pragma unroll
        for (int nf = 0; nf < 2; nf++) {
            sc[nf][0] = sc[nf][1] = sc[nf][2] = sc[nf][3] = 0.f;
            #pragma unroll
            for (int ks = 0; ks < 4; ks++) {
                uint32_t b0 = Ks[nf * 8 + g][ks * 8 + t];
                uint32_t b1 = Ks[nf * 8 + g][ks * 8 + t + 4];
                mma8(sc[nf], qa[ks][0], qa[ks][1], qa[ks][2], qa[ks][3], b0, b1);
            }
        }

        #pragma unroll
        for (int nf = 0; nf < 2; nf++) {
            if (useBias) {
                int brow = nf * 8 + 2 * t;
                int c0 = warp * 16 + g;
                sc[nf][0] += Bsm[brow][c0];
                sc[nf][1] += Bsm[brow + 1][c0];
                sc[nf][2] += Bsm[brow][c0 + 8];
                sc[nf][3] += Bsm[brow + 1][c0 + 8];
            }
            int kc = l0 + nf * 8 + 2 * t;
            if (kc >= le)     { sc[nf][0] = -1e30f; sc[nf][2] = -1e30f; }
            if (kc + 1 >= le) { sc[nf][1] = -1e30f; sc[nf][3] = -1e30f; }
        }

        float mx0 = fmaxf(fmaxf(sc[0][0], sc[0][1]), fmaxf(sc[1][0], sc[1][1]));
        float mx1 = fmaxf(fmaxf(sc[0][2], sc[0][3]), fmaxf(sc[1][2], sc[1][3]));
        mx0 = fmaxf(mx0, __shfl_xor_sync(0xffffffffu, mx0, 1));
        mx0 = fmaxf(mx0, __shfl_xor_sync(0xffffffffu, mx0, 2));
        mx1 = fmaxf(mx1, __shfl_xor_sync(0xffffffffu, mx1, 1));
        mx1 = fmaxf(mx1, __shfl_xor_sync(0xffffffffu, mx1, 2));

        float nm0 = fmaxf(om0, mx0), nm1 = fmaxf(om1, mx1);
        float cr0 = __expf(om0 - nm0), cr1 = __expf(om1 - nm1);
        om0 = nm0; om1 = nm1;
        ol0 *= cr0; ol1 *= cr1;
        #pragma unroll
        for (int nd = 0; nd < 4; nd++) {
            oacc[nd][0] *= cr0; oacc[nd][1] *= cr0;
            oacc[nd][2] *= cr1; oacc[nd][3] *= cr1;
        }

        #pragma unroll
        for (int nf = 0; nf < 2; nf++) {
            sc[nf][0] = __expf(sc[nf][0] - nm0);
            sc[nf][1] = __expf(sc[nf][1] - nm0);
            sc[nf][2] = __expf(sc[nf][2] - nm1);
            sc[nf][3] = __expf(sc[nf][3] - nm1);
            ol0 += sc[nf][0] + sc[nf][1];
            ol1 += sc[nf][2] + sc[nf][3];
        }

        #pragma unroll
        for (int ks = 0; ks < 2; ks++) {
            int src0 = t >> 1, src1 = (t >> 1) + 2;
            float v0 = __shfl_sync(0xffffffffu, sc[ks][0], src0, 4);
            float v1 = __shfl_sync(0xffffffffu, sc[ks][1], src0, 4);
            float v2 = __shfl_sync(0xffffffffu, sc[ks][2], src0, 4);
            float v3 = __shfl_sync(0xffffffffu, sc[ks][3], src0, 4);
            float w0 = __shfl_sync(0xffffffffu, sc[ks][0], src1, 4);
            float w1 = __shfl_sync(0xffffffffu, sc[ks][1], src1, 4);
            float w2 = __shfl_sync(0xffffffffu, sc[ks][2], src1, 4);
            float w3 = __shfl_sync(0xffffffffu, sc[ks][3], src1, 4);
            bool odd = (t & 1);
            uint32_t pa0 = f2tf32(odd ? v1 : v0);
            uint32_t pa1 = f2tf32(odd ? v3 : v2);
            uint32_t pa2 = f2tf32(odd ? w1 : w0);
            uint32_t pa3 = f2tf32(odd ? w3 : w2);
            #pragma unroll
            for (int nd = 0; nd < 4; nd++) {
                uint32_t b0 = Vt[nd * 8 + g][ks * 8 + t];
                uint32_t b1 = Vt[nd * 8 + g][ks * 8 + t + 4];
                mma8(oacc[nd], pa0, pa1, pa2, pa3, b0, b1);
            }
        }
    }

    ol0 += __shfl_xor_sync(0xffffffffu, ol0, 1);
    ol0 += __shfl_xor_sync(0xffffffffu, ol0, 2);
    ol1 += __shfl_xor_sync(0xffffffffu, ol1, 1);
    ol1 += __shfl_xor_sync(0xffffffffu, ol1, 2);

    if (dout) {
        // S == 1: write normalized fp16 output directly
        float inv0 = 1.f / ol0, inv1 = 1.f / ol1;
        if (qg < QQ) {
            __half* op = dout + ((size_t)(b * QQ + qg)) * DD + h * HD;
            #pragma unroll
            for (int nd = 0; nd < 4; nd++) {
                __half2 hv = __floats2half2_rn(oacc[nd][0] * inv0, oacc[nd][1] * inv0);
                *reinterpret_cast<uint32_t*>(op + nd * 8 + 2 * t) =
                    *reinterpret_cast<uint32_t*>(&hv);
            }
        }
        if (qg8 < QQ) {
            __half* op = dout + ((size_t)(b * QQ + qg8)) * DD + h * HD;
            #pragma unroll
            for (int nd = 0; nd < 4; nd++) {
                __half2 hv = __floats2half2_rn(oacc[nd][2] * inv1, oacc[nd][3] * inv1);
                *reinterpret_cast<uint32_t*>(op + nd * 8 + 2 * t) =
                    *reinterpret_cast<uint32_t*>(&hv);
            }
        }
        return;
    }

    size_t pbase = ((size_t)((b * HH + h) * S + sp)) * QQ;
    if (qg < QQ) {
        if (t == 0) { pm[pbase + qg] = om0; pl[pbase + qg] = ol0; }
        float* ap = pacc + (pbase + qg) * HD;
        #pragma unroll
        for (int nd = 0; nd < 4; nd++)
            *reinterpret_cast<float2*>(ap + nd * 8 + 2 * t) =
                make_float2(oacc[nd][0], oacc[nd][1]);
    }
    if (qg8 < QQ) {
        if (t == 0) { pm[pbase + qg8] = om1; pl[pbase + qg8] = ol1; }
        float* ap = pacc + (pbase + qg8) * HD;
        #pragma unroll
        for (int nd = 0; nd < 4; nd++)
            *reinterpret_cast<float2*>(ap + nd * 8 + 2 * t) =
                make_float2(oacc[nd][2], oacc[nd][3]);
    }
}

// ---------------- split combine (writes fp16 for GEMM consumption) --------
__global__ __launch_bounds__(256) void attn_combine_kernel(
    const float* __restrict__ pm, const float* __restrict__ pl,
    const float* __restrict__ pacc, int S, __half* __restrict__ out)
{
    int tt = blockIdx.x * 256 + threadIdx.x;
    if (tt >= BB * HH * QQ * (HD / 2)) return;
    int dp = tt & (HD / 2 - 1);
    int idx = tt >> 4;
    int q = idx % QQ;
    int bh = idx / QQ;
    int b = bh / HH, h = bh % HH;

    float mg = -INFINITY;
    for (int s = 0; s < S; s++)
        mg = fmaxf(mg, pm[((size_t)bh * S + s) * QQ + q]);
    float Lsum = 0.f;
    float olo = 0.f, ohi = 0.f;
    for (int s = 0; s < S; s++) {
        size_t pidx = ((size_t)bh * S + s) * QQ + q;
        float w = __expf(pm[pidx] - mg);
        Lsum += pl[pidx] * w;
        float2 a = *reinterpret_cast<const float2*>(pacc + pidx * HD + 2 * dp);
        olo += w * a.x; ohi += w * a.y;
    }
    float inv = 1.f / Lsum;
    __half2 hv = __floats2half2_rn(olo * inv, ohi * inv);
    *reinterpret_cast<uint32_t*>(
        out + ((size_t)(b * QQ + q)) * DD + h * HD + 2 * dp) =
        *reinterpret_cast<uint32_t*>(&hv);
}

// ---------------- host launcher ----------------
static inline int cdiv(int a, int b) { return (a + b - 1) / b; }

extern "C" void kernel_launch(void* const* d_in, const int* in_sizes, int n_in,
                              void* d_out, int out_size)
{
    const float* queries   = (const float*)d_in[0];
    const float* memory    = (const float*)d_in[1];
    const float* memory_pos= (const float*)d_in[2];
    const float* query_pos = (const float*)d_in[3];
    const float* sa_in_w   = (const float*)d_in[4];
    const float* sa_in_b   = (const float*)d_in[5];
    const float* sa_out_w  = (const float*)d_in[6];
    const float* sa_out_b  = (const float*)d_in[7];
    const float* norm1_g   = (const float*)d_in[8];
    const float* norm1_b   = (const float*)d_in[9];
    const float* q_w       = (const float*)d_in[10];
    const float* q_b       = (const float*)d_in[11];
    const float* k_w       = (const float*)d_in[12];
    const float* k_b       = (const float*)d_in[13];
    const float* v_w       = (const float*)d_in[14];
    const float* v_b       = (const float*)d_in[15];
    const float* o_w       = (const float*)d_in[16];
    const float* o_b       = (const float*)d_in[17];
    const float* norm2_g   = (const float*)d_in[18];
    const float* norm2_b   = (const float*)d_in[19];
    const float* beta      = (const float*)d_in[20];
    const float* dk_w1     = (const float*)d_in[21];
    const float* dk_b1     = (const float*)d_in[22];
    const float* dk_w2     = (const float*)d_in[23];
    const float* dk_b2     = (const float*)d_in[24];
    const float* ffn_w1    = (const float*)d_in[25];
    const float* ffn_b1    = (const float*)d_in[26];
    const float* ffn_w2    = (const float*)d_in[27];
    const float* ffn_b2    = (const float*)d_in[28];
    const float* norm3_g   = (const float*)d_in[29];
    const float* norm3_b   = (const float*)d_in[30];

    float *g_qkv, *g_x1, *g_x2, *g_q, *g_k, *g_v, *g_bias,
          *g_part, *g_pm, *g_pl, *g_pacc;
    cudaGetSymbolAddress((void**)&g_qkv,  s_qkv);
    cudaGetSymbolAddress((void**)&g_x1,   s_x1);
    cudaGetSymbolAddress((void**)&g_x2,   s_x2);
    cudaGetSymbolAddress((void**)&g_q,    s_q);
    cudaGetSymbolAddress((void**)&g_k,    s_k);
    cudaGetSymbolAddress((void**)&g_v,    s_v);
    cudaGetSymbolAddress((void**)&g_bias, s_bias);
    cudaGetSymbolAddress((void**)&g_part, s_part);
    cudaGetSymbolAddress((void**)&g_pm,   s_pm);
    cudaGetSymbolAddress((void**)&g_pl,   s_pl);
    cudaGetSymbolAddress((void**)&g_pacc, s_pacc);

    __half *hq, *hm, *h_siw, *h_sow, *h_qw, *h_kw, *h_vw, *h_ow,
           *h_fw1, *h_fw2, *hsa, *hca, *hx1, *hx2, *hffn;
    cudaGetSymbolAddress((void**)&hq,    h_queries);
    cudaGetSymbolAddress((void**)&hm,    h_memory);
    cudaGetSymbolAddress((void**)&h_siw, h_sa_in_w);
    cudaGetSymbolAddress((void**)&h_sow, h_sa_out_w);
    cudaGetSymbolAddress((void**)&h_qw,  h_q_w);
    cudaGetSymbolAddress((void**)&h_kw,  h_k_w);
    cudaGetSymbolAddress((void**)&h_vw,  h_v_w);
    cudaGetSymbolAddress((void**)&h_ow,  h_o_w);
    cudaGetSymbolAddress((void**)&h_fw1, h_ffn_w1);
    cudaGetSymbolAddress((void**)&h_fw2, h_ffn_w2);
    cudaGetSymbolAddress((void**)&hsa,   h_sa);
    cudaGetSymbolAddress((void**)&hca,   h_ca);
    cudaGetSymbolAddress((void**)&hx1,   h_x1);
    cudaGetSymbolAddress((void**)&hx2,   h_x2);
    cudaGetSymbolAddress((void**)&hffn,  h_ffn);

    static cudaStream_t st2 = nullptr, st3 = nullptr, st4 = nullptr;
    static cudaEvent_t ev0 = nullptr, ev2 = nullptr, ev3 = nullptr,
                       ev4 = nullptr, ev5 = nullptr;
    if (st2 == nullptr) {
        cudaStreamCreateWithFlags(&st2, cudaStreamNonBlocking);
        cudaStreamCreateWithFlags(&st3, cudaStreamNonBlocking);
        cudaStreamCreateWithFlags(&st4, cudaStreamNonBlocking);
        cudaEventCreateWithFlags(&ev0, cudaEventDisableTiming);
        cudaEventCreateWithFlags(&ev2, cudaEventDisableTiming);
        cudaEventCreateWithFlags(&ev3, cudaEventDisableTiming);
        cudaEventCreateWithFlags(&ev4, cudaEventDisableTiming);
        cudaEventCreateWithFlags(&ev5, cudaEventDisableTiming);
    }

    const int Mq = BB * QQ;   // 2400
    const int Mm = BB * LL;   // 8192
    const int NCOMB = BB * HH * QQ * (HD / 2);

    auto conv = [](const float* s, __half* d, int n, cudaStream_t st) {
        f2h_kernel<<<cdiv(n / 8, 256), 256, 0, st>>>(s, d, n);
    };

    // ---- fork ----
    cudaEventRecord(ev0, 0);
    cudaStreamWaitEvent(st2, ev0, 0);
    cudaStreamWaitEvent(st3, ev0, 0);
    cudaStreamWaitEvent(st4, ev0, 0);

    // st2: memory + KV weights conversion, then fused KV GEMM
    conv(memory, hm, Mm * DD, st2);
    conv(k_w, h_kw, DD * DD, st2);
    conv(v_w, h_vw, DD * DD, st2);
    gemm_f16_kernel<2><<<dim3(2 * DD / 64, cdiv(Mm, 128), 1), 256, 0, st2>>>(
        hm, h_kw, k_b, g_k, nullptr, Mm, DD, DD, 0, h_vw, v_b, g_v, nullptr);
    cudaEventRecord(ev2, st2);

    // st3: GASA bias
    gasa_bias_kernel<<<dim3(LL, BB), 128, 0, st3>>>(
        query_pos, memory_pos, dk_w1, dk_b1, dk_w2, dk_b2, beta, g_bias);
    cudaEventRecord(ev3, st3);

    // st4: sa_in_w first (critical for GEMM1), then remaining weights
    conv(sa_in_w, h_siw, 3 * DD * DD, st4);
    cudaEventRecord(ev5, st4);
    conv(sa_out_w, h_sow, DD * DD, st4);
    conv(q_w, h_qw, DD * DD, st4);
    conv(o_w, h_ow, DD * DD, st4);
    conv(ffn_w1, h_fw1, DFF * DD, st4);
    conv(ffn_w2, h_fw2, DD * DFF, st4);
    cudaEventRecord(ev4, st4);

    // ---- main chain ----
    conv(queries, hq, Mq * DD, 0);
    cudaStreamWaitEvent(0, ev5, 0);

    // 1) self-attn packed in-proj (fp32 out for attention)
    gemm_f16_kernel<2><<<dim3(3 * DD / 64, cdiv(Mq, 128), 1), 256>>>(
        hq, h_siw, sa_in_b, g_qkv, nullptr, Mq, 3 * DD, DD, 0);

    // 2) self-attention, S=1, direct fp16 output (no combine)
    {
        int step = cdiv(QQ, 16) * 16;   // 608
        attn_mma_kernel<<<dim3(NQT, HH, BB), 128>>>(
            g_qkv, 3 * DD, g_qkv + DD, g_qkv + 2 * DD, 3 * DD,
            nullptr, QQ, 1, step, g_pm, g_pl, g_pacc, 0, hsa);
    }

    cudaStreamWaitEvent(0, ev4, 0);

    // 3) SA out-proj split-K=2 + LN1 (x1 fp32 + fp16)
    gemm_f16_kernel<1><<<dim3(DD / 64, cdiv(Mq, 64), 2), 256>>>(
        hsa, h_sow, sa_out_b, g_part, nullptr, Mq, DD, DD, 0);
    ln_split_kernel<<<Mq / 8, 256>>>(queries, g_part, sa_out_b,
                                     norm1_g, norm1_b, g_x1, hx1, 2);

    // 4) Q projection (fp32 out for attention)
    gemm_f16_kernel<1><<<dim3(DD / 64, cdiv(Mq, 64), 1), 256>>>(
        hx1, h_qw, q_b, g_q, nullptr, Mq, DD, DD, 0);

    cudaStreamWaitEvent(0, ev2, 0);
    cudaStreamWaitEvent(0, ev3, 0);

    // 5) cross-attention, split S=4 -> combine -> h_ca (fp16)
    {
        int S = 4, step = cdiv(LL, S * 16) * 16;
        attn_mma_kernel<<<dim3(NQT * S, HH, BB), 128>>>(
            g_q, DD, g_k, g_v, DD, g_bias, LL, S, step,
            g_pm, g_pl, g_pacc, 1, nullptr);
        attn_combine_kernel<<<cdiv(NCOMB, 256), 256>>>(g_pm, g_pl, g_pacc, S, hca);
    }

    // 6) O proj split-K=2 + LN2 (x2 fp32 + fp16)
    gemm_f16_kernel<1><<<dim3(DD / 64, cdiv(Mq, 64), 2), 256>>>(
        hca, h_ow, o_b, g_part, nullptr, Mq, DD, DD, 0);
    ln_split_kernel<<<Mq / 8, 256>>>(g_x1, g_part, o_b,
                                     norm2_g, norm2_b, g_x2, hx2, 2);

    // 7) FFN1 (relu) -> fp16 only
    gemm_f16_kernel<2><<<dim3(DFF / 64, cdiv(Mq, 128), 1), 256>>>(
        hx2, h_fw1, ffn_b1, nullptr, hffn, Mq, DFF, DD, 1);

    // 8) FFN2 split-K=4 partials + fused combine in LN3 -> output
    gemm_f16_kernel<1><<<dim3(DD / 64, cdiv(Mq, 64), 4), 256>>>(
        hffn, h_fw2, ffn_b2, g_part, nullptr, Mq, DD, DFF, 0);
    ln_split_kernel<<<Mq / 8, 256>>>(g_x2, g_part, ffn_b2,
                                     norm3_g, norm3_b, (float*)d_out, nullptr, 4);
}

// round 11
// speedup vs baseline: 1.0876x; 1.0876x over previous
#include <cuda_runtime.h>
#include <cuda_fp16.h>
#include <math.h>
#include <stdint.h>

// ---------------- problem constants ----------------
#define BB 4
#define QQ 600
#define LL 2048
#define DD 256
#define HH 8
#define HD 32
#define DFF 2048
#define KD 32
#define SCALE 0.17677669529663687f   // 32^-0.5
#define NQT 10                       // ceil(600/64) 64-query tiles

typedef unsigned long long u64;

// ---------------- helpers ----------------
__device__ __forceinline__ uint32_t f2tf32(float x) {
    uint32_t u; asm("cvt.rna.tf32.f32 %0, %1;" : "=r"(u) : "f"(x)); return u;
}
__device__ __forceinline__ void mma8(float c[4], uint32_t a0, uint32_t a1,
                                     uint32_t a2, uint32_t a3,
                                     uint32_t b0, uint32_t b1) {
    asm("mma.sync.aligned.m16n8k8.row.col.f32.tf32.tf32.f32 "
        "{%0,%1,%2,%3},{%4,%5,%6,%7},{%8,%9},{%0,%1,%2,%3};"
        : "+f"(c[0]), "+f"(c[1]), "+f"(c[2]), "+f"(c[3])
        : "r"(a0), "r"(a1), "r"(a2), "r"(a3), "r"(b0), "r"(b1));
}
__device__ __forceinline__ void mma16h(float c[4], uint32_t a0, uint32_t a1,
                                       uint32_t a2, uint32_t a3,
                                       uint32_t b0, uint32_t b1) {
    asm("mma.sync.aligned.m16n8k16.row.col.f32.f16.f16.f32 "
        "{%0,%1,%2,%3},{%4,%5,%6,%7},{%8,%9},{%0,%1,%2,%3};"
        : "+f"(c[0]), "+f"(c[1]), "+f"(c[2]), "+f"(c[3])
        : "r"(a0), "r"(a1), "r"(a2), "r"(a3), "r"(b0), "r"(b1));
}
__device__ __forceinline__ void ldsm4(uint32_t& r0, uint32_t& r1,
                                      uint32_t& r2, uint32_t& r3, uint32_t addr) {
    asm volatile("ldmatrix.sync.aligned.m8n8.x4.shared.b16 {%0,%1,%2,%3}, [%4];"
                 : "=r"(r0), "=r"(r1), "=r"(r2), "=r"(r3) : "r"(addr));
}
__device__ __forceinline__ void cp16(uint32_t dst, const void* src, int srcsize) {
    asm volatile("cp.async.ca.shared.global [%0], [%1], 16, %2;"
                 :: "r"(dst), "l"(src), "r"(srcsize));
}
__device__ __forceinline__ void cp_commit() {
    asm volatile("cp.async.commit_group;");
}
template<int N>
__device__ __forceinline__ void cp_wait() {
    asm volatile("cp.async.wait_group %0;" :: "n"(N));
}

// ---------------- scratch (device globals) ----------------
__device__ float s_qkv [BB*QQ*3*DD];
__device__ float s_x1  [BB*QQ*DD];
__device__ float s_x2  [BB*QQ*DD];
__device__ float s_q   [BB*QQ*DD];
__device__ float s_k   [BB*LL*DD];
__device__ float s_v   [BB*LL*DD];
__device__ float s_bias[BB*LL*QQ];
__device__ float s_part[4*BB*QQ*DD];
__device__ float s_pm  [BB*HH*8*QQ];
__device__ float s_pl  [BB*HH*8*QQ];
__device__ float s_pacc[BB*HH*8*QQ*HD];
// fp16 copies
__device__ __half h_queries[BB*QQ*DD];
__device__ __half h_memory [BB*LL*DD];
__device__ __half h_sa_in_w[3*DD*DD];
__device__ __half h_sa_out_w[DD*DD];
__device__ __half h_q_w[DD*DD];
__device__ __half h_k_w[DD*DD];
__device__ __half h_v_w[DD*DD];
__device__ __half h_o_w[DD*DD];
__device__ __half h_ffn_w1[DFF*DD];
__device__ __half h_ffn_w2[DD*DFF];
__device__ __half h_sa [BB*QQ*DD];
__device__ __half h_ca [BB*QQ*DD];
__device__ __half h_x1 [BB*QQ*DD];
__device__ __half h_x2 [BB*QQ*DD];
__device__ __half h_ffn[BB*QQ*DFF];

// ---------------- fp32 -> fp16 convert (8 elts/thread) ----------------
__device__ __forceinline__ void conv8(const float* src, __half* dst, int i) {
    float4 x0 = *reinterpret_cast<const float4*>(src + i);
    float4 x1 = *reinterpret_cast<const float4*>(src + i + 4);
    __half2 h0 = __floats2half2_rn(x0.x, x0.y);
    __half2 h1 = __floats2half2_rn(x0.z, x0.w);
    __half2 h2 = __floats2half2_rn(x1.x, x1.y);
    __half2 h3 = __floats2half2_rn(x1.z, x1.w);
    uint4 u;
    u.x = *reinterpret_cast<uint32_t*>(&h0);
    u.y = *reinterpret_cast<uint32_t*>(&h1);
    u.z = *reinterpret_cast<uint32_t*>(&h2);
    u.w = *reinterpret_cast<uint32_t*>(&h3);
    *reinterpret_cast<uint4*>(dst + i) = u;
}

__global__ __launch_bounds__(256) void f2h_kernel(
    const float* __restrict__ src, __half* __restrict__ dst, int n)
{
    int i = (blockIdx.x * 256 + threadIdx.x) * 8;
    if (i >= n) return;
    conv8(src, dst, i);
}

// fused 5-way weight conversion: [sa_out_w|q_w|o_w][ffn_w1][ffn_w2]
#define WSEG (DD * DD)          // 65536
#define WF   (DFF * DD)         // 524288
__global__ __launch_bounds__(256) void f2h_weights_kernel(
    const float* __restrict__ sow, const float* __restrict__ qw,
    const float* __restrict__ ow, const float* __restrict__ fw1,
    const float* __restrict__ fw2,
    __half* __restrict__ hsow, __half* __restrict__ hqw,
    __half* __restrict__ how, __half* __restrict__ hfw1,
    __half* __restrict__ hfw2)
{
    int i = (blockIdx.x * 256 + threadIdx.x) * 8;
    if (i < WSEG) { conv8(sow, hsow, i); return; }
    i -= WSEG;
    if (i < WSEG) { conv8(qw, hqw, i); return; }
    i -= WSEG;
    if (i < WSEG) { conv8(ow, how, i); return; }
    i -= WSEG;
    if (i < WF) { conv8(fw1, hfw1, i); return; }
    i -= WF;
    if (i < WF) conv8(fw2, hfw2, i);
}

// ---------------- FP16 tensor-core GEMM (cp.async + ldmatrix, 32k stages) --
#define KP 40
#define NST 3

template<int MF>
__global__ __launch_bounds__(256) void gemm_f16_kernel(
    const __half* __restrict__ A, const __half* __restrict__ W,
    const float* __restrict__ bias, float* C, __half* Ch,
    int M, int N, int K, int relu,
    const __half* __restrict__ W2 = nullptr,
    const float* __restrict__ bias2 = nullptr,
    float* C2 = nullptr, __half* C2h = nullptr)
{
    __shared__ __align__(16) __half As[NST][64 * MF][KP];
    __shared__ __align__(16) __half Ws[NST][64][KP];

    const int tid = threadIdx.x;
    const int lane = tid & 31;
    const int w = tid >> 5;
    const int wm = w & 3;
    const int wn = w >> 2;
    const int g = lane >> 2;
    const int t = lane & 3;

    int bx = blockIdx.x;
    const int nblk = N / 64;
    if (W2 != nullptr && bx >= nblk) {
        bx -= nblk;
        W = W2; bias = bias2; C = C2; Ch = C2h;
    }

    const int m0 = blockIdx.y * (64 * MF);
    const int n0 = bx * 64;

    const int nsplit = gridDim.z;
    const int Klen = K / nsplit;
    const int kstart = blockIdx.z * Klen;
    float* Cout = (C && nsplit > 1) ? (C + (size_t)blockIdx.z * M * N) : C;

    const uint32_t as_base = (uint32_t)__cvta_generic_to_shared(&As[0][0][0]);
    const uint32_t ws_base = (uint32_t)__cvta_generic_to_shared(&Ws[0][0][0]);

    float acc[MF][4][4];
    #pragma unroll
    for (int i = 0; i < MF; i++)
        #pragma unroll
        for (int j = 0; j < 4; j++)
            #pragma unroll
            for (int e = 0; e < 4; e++) acc[i][j][e] = 0.f;

    const int m_warp = wm * (16 * MF);
    const int n_warp = wn * 32;
    const int nIter = Klen / 32;

    const int lr8 = lane & 7;
    const int lb1 = (lane >> 3) & 1;
    const int lb2 = (lane >> 4) & 1;
    uint32_t aAddr[MF];
    #pragma unroll
    for (int mi = 0; mi < MF; mi++) {
        int row = m_warp + mi * 16 + lr8 + lb1 * 8;
        aAddr[mi] = as_base + (row * KP + lb2 * 8) * 2;
    }
    uint32_t bAddr[2];
    #pragma unroll
    for (int p = 0; p < 2; p++) {
        int row = n_warp + p * 16 + lb2 * 8 + lr8;
        bAddr[p] = ws_base + (row * KP + lb1 * 8) * 2;
    }
    const uint32_t aStride = (64 * MF) * KP * 2;
    const uint32_t bStride = 64 * KP * 2;

    auto load_stage = [&](int st, int it) {
        const int kg = kstart + it * 32;
        if (MF == 2) {
            #pragma unroll
            for (int s = 0; s < 2; s++) {
                int idx = tid + s * 256;
                int r = idx >> 2, kc = (idx & 3) * 8;
                int arow = m0 + r;
                uint32_t dst = as_base + ((st * 128 + r) * KP + kc) * 2;
                cp16(dst, A + (size_t)arow * K + kg + kc, (arow < M) ? 16 : 0);
            }
            {
                int r = tid >> 2, kc = (tid & 3) * 8;
                uint32_t dst = ws_base + ((st * 64 + r) * KP + kc) * 2;
                cp16(dst, W + (size_t)(n0 + r) * K + kg + kc, 16);
            }
        } else {
            int r = tid >> 2, kc = (tid & 3) * 8;
            int arow = m0 + r;
            uint32_t dst = as_base + ((st * 64 + r) * KP + kc) * 2;
            cp16(dst, A + (size_t)arow * K + kg + kc, (arow < M) ? 16 : 0);
            uint32_t dst2 = ws_base + ((st * 64 + r) * KP + kc) * 2;
            cp16(dst2, W + (size_t)(n0 + r) * K + kg + kc, 16);
        }
        cp_commit();
    };

    load_stage(0, 0);
    load_stage(1, 1);

    for (int it = 0; it < nIter; it++) {
        cp_wait<NST - 2>();
        __syncthreads();
        if (it + NST - 1 < nIter) load_stage((it + NST - 1) % NST, it + NST - 1);
        else cp_commit();

        const int st = it % NST;
        #pragma unroll
        for (int kk = 0; kk < 32; kk += 16) {
            uint32_t b0[4], b1[4];
            ldsm4(b0[0], b1[0], b0[1], b1[1], bAddr[0] + st * bStride + kk * 2);
            ldsm4(b0[2], b1[2], b0[3], b1[3], bAddr[1] + st * bStride + kk * 2);
            #pragma unroll
            for (int mi = 0; mi < MF; mi++) {
                uint32_t a0, a1, a2, a3;
                ldsm4(a0, a1, a2, a3, aAddr[mi] + st * aStride + kk * 2);
                #pragma unroll
                for (int ni = 0; ni < 4; ni++)
                    mma16h(acc[mi][ni], a0, a1, a2, a3, b0[ni], b1[ni]);
            }
        }
    }

    #pragma unroll
    for (int mi = 0; mi < MF; mi++) {
        #pragma unroll
        for (int ni = 0; ni < 4; ni++) {
            int col = n0 + n_warp + ni * 8 + 2 * t;
            float bz0 = 0.f, bz1 = 0.f;
            if (nsplit == 1) { bz0 = bias[col]; bz1 = bias[col + 1]; }
            int r0 = m0 + m_warp + mi * 16 + g;
            int r1 = r0 + 8;
            float v0 = acc[mi][ni][0] + bz0, v1 = acc[mi][ni][1] + bz1;
            float v2 = acc[mi][ni][2] + bz0, v3 = acc[mi][ni][3] + bz1;
            if (relu) {
                v0 = fmaxf(v0, 0.f); v1 = fmaxf(v1, 0.f);
                v2 = fmaxf(v2, 0.f); v3 = fmaxf(v3, 0.f);
            }
            if (Cout) {
                if (r0 < M) *reinterpret_cast<float2*>(Cout + (size_t)r0 * N + col) = make_float2(v0, v1);
                if (r1 < M) *reinterpret_cast<float2*>(Cout + (size_t)r1 * N + col) = make_float2(v2, v3);
            }
            if (Ch) {
                if (r0 < M) {
                    __half2 hv = __floats2half2_rn(v0, v1);
                    *reinterpret_cast<uint32_t*>(Ch + (size_t)r0 * N + col) =
                        *reinterpret_cast<uint32_t*>(&hv);
                }
                if (r1 < M) {
                    __half2 hv = __floats2half2_rn(v2, v3);
                    *reinterpret_cast<uint32_t*>(Ch + (size_t)r1 * N + col) =
                        *reinterpret_cast<uint32_t*>(&hv);
                }
            }
        }
    }
}

// ---------------- warp-per-row LayerNorm core ----------------
__device__ __forceinline__ void lnw_finish(
    float v[8], int lane, const float* g, const float* bt,
    float* out, __half* outh, size_t row)
{
    float s1 = 0.f, s2 = 0.f;
    #pragma unroll
    for (int i = 0; i < 8; i++) { s1 += v[i]; s2 += v[i] * v[i]; }
    #pragma unroll
    for (int o = 16; o > 0; o >>= 1) {
        s1 += __shfl_xor_sync(0xffffffffu, s1, o);
        s2 += __shfl_xor_sync(0xffffffffu, s2, o);
    }
    float mean = s1 * (1.f / DD);
    float var = s2 * (1.f / DD) - mean * mean;
    float rstd = rsqrtf(var + 1e-5f);
    int c0 = lane * 8;
    float r[8];
    #pragma unroll
    for (int i = 0; i < 8; i++)
        r[i] = (v[i] - mean) * rstd * g[c0 + i] + bt[c0 + i];
    if (out) {
        *reinterpret_cast<float4*>(out + row * DD + c0) = make_float4(r[0], r[1], r[2], r[3]);
        *reinterpret_cast<float4*>(out + row * DD + c0 + 4) = make_float4(r[4], r[5], r[6], r[7]);
    }
    if (outh) {
        __half2 h0 = __floats2half2_rn(r[0], r[1]);
        __half2 h1 = __floats2half2_rn(r[2], r[3]);
        __half2 h2 = __floats2half2_rn(r[4], r[5]);
        __half2 h3 = __floats2half2_rn(r[6], r[7]);
        uint4 u;
        u.x = *reinterpret_cast<uint32_t*>(&h0);
        u.y = *reinterpret_cast<uint32_t*>(&h1);
        u.z = *reinterpret_cast<uint32_t*>(&h2);
        u.w = *reinterpret_cast<uint32_t*>(&h3);
        *reinterpret_cast<uint4*>(outh + row * DD + c0) = u;
    }
}

__global__ __launch_bounds__(256) void ln_split_kernel(
    const float* __restrict__ X, const float* __restrict__ parts,
    const float* __restrict__ fbias,
    const float* __restrict__ g, const float* __restrict__ bt,
    float* out, __half* outh, int nsplit)
{
    const int lane = threadIdx.x & 31;
    const size_t row = blockIdx.x * 8 + (threadIdx.x >> 5);
    const size_t stride = (size_t)BB * QQ * DD;
    int c0 = lane * 8;
    float v[8];
    float4 x0 = *reinterpret_cast<const float4*>(X + row * DD + c0);
    float4 x1 = *reinterpret_cast<const float4*>(X + row * DD + c0 + 4);
    float4 f0 = *reinterpret_cast<const float4*>(fbias + c0);
    float4 f1 = *reinterpret_cast<const float4*>(fbias + c0 + 4);
    v[0] = x0.x + f0.x; v[1] = x0.y + f0.y; v[2] = x0.z + f0.z; v[3] = x0.w + f0.w;
    v[4] = x1.x + f1.x; v[5] = x1.y + f1.y; v[6] = x1.z + f1.z; v[7] = x1.w + f1.w;
    for (int s = 0; s < nsplit; s++) {
        float4 p0 = *reinterpret_cast<const float4*>(parts + s * stride + row * DD + c0);
        float4 p1 = *reinterpret_cast<const float4*>(parts + s * stride + row * DD + c0 + 4);
        v[0] += p0.x; v[1] += p0.y; v[2] += p0.z; v[3] += p0.w;
        v[4] += p1.x; v[5] += p1.y; v[6] += p1.z; v[7] += p1.w;
    }
    lnw_finish(v, lane, g, bt, out, outh, row);
}

// ---------------- GASA geometric bias: block per (b,l) ----------------
__global__ __launch_bounds__(128) void gasa_bias_kernel(
    const float* __restrict__ qpos, const float* __restrict__ mpos,
    const float* __restrict__ w1, const float* __restrict__ b1,
    const float* __restrict__ w2, const float* __restrict__ b2,
    const float* __restrict__ betap, float* __restrict__ biasT)
{
    const int l = blockIdx.x;
    const int b = blockIdx.y;
    const int tid = threadIdx.x;

    __shared__ float sw1[KD], sb1[KD], sw2[KD], smp[3], sb2, sbeta;
    if (tid < KD) {
        sw1[tid] = w1[tid];
        sb1[tid] = b1[tid];
        sw2[tid] = w2[tid];
    }
    if (tid < 3) smp[tid] = mpos[((size_t)b * LL + l) * 3 + tid];
    if (tid == 3) sb2 = b2[0];
    if (tid == 4) sbeta = betap[0];
    __syncthreads();

    const float mx = smp[0], my = smp[1], mz = smp[2];
    const float bb2 = sb2, bet = sbeta;
    float* orow = biasT + ((size_t)b * LL + l) * QQ;

    for (int q = tid; q < QQ; q += 128) {
        const float* qp = qpos + ((size_t)b * QQ + q) * 3;
        float dx = qp[0] - mx, dy = qp[1] - my, dz = qp[2] - mz;
        float dist = sqrtf(fmaxf(dx * dx + dy * dy + dz * dz, 0.f));
        float s = 0.f;
        #pragma unroll
        for (int k = 0; k < KD; k++) {
            float h = fmaxf(dist * sw1[k] + sb1[k], 0.f);
            s += h * sw2[k];
        }
        s += bb2;
        s = fminf(fmaxf(s, -10.f), 0.f);
        orow[q] = s * bet;
    }
}

// ---------------- tensor-core flash attention partials ----------------
__global__ __launch_bounds__(128) void attn_mma_kernel(
    const float* __restrict__ Qp, int qstride,
    const float* __restrict__ Kp, const float* __restrict__ Vp, int kvstride,
    const float* __restrict__ biasT, int Lk, int S, int step,
    float* __restrict__ pm, float* __restrict__ pl, float* __restrict__ pacc,
    int useBias)
{
    const int b = blockIdx.z, h = blockIdx.y;
    const int sp = blockIdx.x / NQT;
    const int qt = blockIdx.x % NQT;
    const int tid = threadIdx.x;
    const int lane = tid & 31;
    const int warp = tid >> 5;
    const int g = lane >> 2;
    const int t = lane & 3;

    const int q0 = qt * 64 + warp * 16;
    const int qg  = q0 + g;
    const int qg8 = q0 + g + 8;
    const int qgc  = min(qg, QQ - 1);
    const int qg8c = min(qg8, QQ - 1);

    const int ls = sp * step;
    const int le = min(ls + step, Lk);

    uint32_t qa[4][4];
    {
        const float* q0p = Qp + ((size_t)(b * QQ + qgc)) * qstride + h * HD;
        const float* q1p = Qp + ((size_t)(b * QQ + qg8c)) * qstride + h * HD;
        #pragma unroll
        for (int ks = 0; ks < 4; ks++) {
            qa[ks][0] = f2tf32(q0p[ks * 8 + t] * SCALE);
            qa[ks][1] = f2tf32(q1p[ks * 8 + t] * SCALE);
            qa[ks][2] = f2tf32(q0p[ks * 8 + t + 4] * SCALE);
            qa[ks][3] = f2tf32(q1p[ks * 8 + t + 4] * SCALE);
        }
    }

    __shared__ uint32_t Ks[16][36];
    __shared__ uint32_t Vt[HD][17];
    __shared__ float    Bsm[16][68];

    float oacc[4][4];
    #pragma unroll
    for (int i = 0; i < 4; i++)
        #pragma unroll
        for (int j = 0; j < 4; j++) oacc[i][j] = 0.f;
    float om0 = -INFINITY, om1 = -INFINITY;
    float ol0 = 0.f, ol1 = 0.f;

    const int key_l = tid >> 3;
    const int d0 = (tid & 7) * 4;
    const int bq0 = (tid & 7) * 8;
    const bool qtail = (qt == NQT - 1);

    float4 kreg, vreg, breg0, breg1;

    auto prefetch = [&](int l0) {
        int grow = b * Lk + min(l0 + key_l, Lk - 1);
        kreg = *reinterpret_cast<const float4*>(
            Kp + (size_t)grow * kvstride + h * HD + d0);
        vreg = *reinterpret_cast<const float4*>(
            Vp + (size_t)grow * kvstride + h * HD + d0);
        if (useBias) {
            const float* brow = biasT + ((size_t)(b * Lk + l0 + key_l)) * QQ
                                + qt * 64 + bq0;
            if (!qtail) {
                breg0 = *reinterpret_cast<const float4*>(brow);
                breg1 = *reinterpret_cast<const float4*>(brow + 4);
            } else {
                int qb = qt * 64 + bq0;
                float e[8];
                #pragma unroll
                for (int i = 0; i < 8; i++)
                    e[i] = (qb + i < QQ) ? brow[i] : 0.f;
                breg0 = make_float4(e[0], e[1], e[2], e[3]);
                breg1 = make_float4(e[4], e[5], e[6], e[7]);
            }
        }
    };

    prefetch(ls);

    for (int l0 = ls; l0 < le; l0 += 16) {
        __syncthreads();
        {
            uint4 ku = make_uint4(f2tf32(kreg.x), f2tf32(kreg.y),
                                  f2tf32(kreg.z), f2tf32(kreg.w));
            *reinterpret_cast<uint4*>(&Ks[key_l][d0]) = ku;
            Vt[d0 + 0][key_l] = f2tf32(vreg.x);
            Vt[d0 + 1][key_l] = f2tf32(vreg.y);
            Vt[d0 + 2][key_l] = f2tf32(vreg.z);
            Vt[d0 + 3][key_l] = f2tf32(vreg.w);
            if (useBias) {
                *reinterpret_cast<float4*>(&Bsm[key_l][bq0]) = breg0;
                *reinterpret_cast<float4*>(&Bsm[key_l][bq0 + 4]) = breg1;
            }
        }
        if (l0 + 16 < le) prefetch(l0 + 16);
        __syncthreads();

        float sc[2][4];
        #pragma unroll
        for (int nf = 0; nf < 2; nf++) {
            sc[nf][0] = sc[nf][1] = sc[nf][2] = sc[nf][3] = 0.f;
            #pragma unroll
            for (int ks = 0; ks < 4; ks++) {
                uint32_t b0 = Ks[nf * 8 + g][ks * 8 + t];
                uint32_t b1 = Ks[nf * 8 + g][ks * 8 + t + 4];
                mma8(sc[nf], qa[ks][0], qa[ks][1], qa[ks][2], qa[ks][3], b0, b1);
            }
        }

        #pragma unroll
        for (int nf = 0; nf < 2; nf++) {
            if (useBias) {
                int brow = nf * 8 + 2 * t;
                int c0 = warp * 16 + g;
                sc[nf][0] += Bsm[brow][c0];
                sc[nf][1] += Bsm[brow + 1][c0];
                sc[nf][2] += Bsm[brow][c0 + 8];
                sc[nf][3] += Bsm[brow + 1][c0 + 8];
            }
            int kc = l0 + nf * 8 + 2 * t;
            if (kc >= le)     { sc[nf][0] = -1e30f; sc[nf][2] = -1e30f; }
            if (kc + 1 >= le) { sc[nf][1] = -1e30f; sc[nf][3] = -1e30f; }
        }

        float mx0 = fmaxf(fmaxf(sc[0][0], sc[0][1]), fmaxf(sc[1][0], sc[1][1]));
        float mx1 = fmaxf(fmaxf(sc[0][2], sc[0][3]), fmaxf(sc[1][2], sc[1][3]));
        mx0 = fmaxf(mx0, __shfl_xor_sync(0xffffffffu, mx0, 1));
        mx0 = fmaxf(mx0, __shfl_xor_sync(0xffffffffu, mx0, 2));
        mx1 = fmaxf(mx1, __shfl_xor_sync(0xffffffffu, mx1, 1));
        mx1 = fmaxf(mx1, __shfl_xor_sync(0xffffffffu, mx1, 2));

        float nm0 = fmaxf(om0, mx0), nm1 = fmaxf(om1, mx1);
        float cr0 = __expf(om0 - nm0), cr1 = __expf(om1 - nm1);
        om0 = nm0; om1 = nm1;
        ol0 *= cr0; ol1 *= cr1;
        #pragma unroll
        for (int nd = 0; nd < 4; nd++) {
            oacc[nd][0] *= cr0; oacc[nd][1] *= cr0;
            oacc[nd][2] *= cr1; oacc[nd][3] *= cr1;
        }

        #pragma unroll
        for (int nf = 0; nf < 2; nf++) {
            sc[nf][0] = __expf(sc[nf][0] - nm0);
            sc[nf][1] = __expf(sc[nf][1] - nm0);
            sc[nf][2] = __expf(sc[nf][2] - nm1);
            sc[nf][3] = __expf(sc[nf][3] - nm1);
            ol0 += sc[nf][0] + sc[nf][1];
            ol1 += sc[nf][2] + sc[nf][3];
        }

        #pragma unroll
        for (int ks = 0; ks < 2; ks++) {
            int src0 = t >> 1, src1 = (t >> 1) + 2;
            float v0 = __shfl_sync(0xffffffffu, sc[ks][0], src0, 4);
            float v1 = __shfl_sync(0xffffffffu, sc[ks][1], src0, 4);
            float v2 = __shfl_sync(0xffffffffu, sc[ks][2], src0, 4);
            float v3 = __shfl_sync(0xffffffffu, sc[ks][3], src0, 4);
            float w0 = __shfl_sync(0xffffffffu, sc[ks][0], src1, 4);
            float w1 = __shfl_sync(0xffffffffu, sc[ks][1], src1, 4);
            float w2 = __shfl_sync(0xffffffffu, sc[ks][2], src1, 4);
            float w3 = __shfl_sync(0xffffffffu, sc[ks][3], src1, 4);
            bool odd = (t & 1);
            uint32_t pa0 = f2tf32(odd ? v1 : v0);
            uint32_t pa1 = f2tf32(odd ? v3 : v2);
            uint32_t pa2 = f2tf32(odd ? w1 : w0);
            uint32_t pa3 = f2tf32(odd ? w3 : w2);
            #pragma unroll
            for (int nd = 0; nd < 4; nd++) {
                uint32_t b0 = Vt[nd * 8 + g][ks * 8 + t];
                uint32_t b1 = Vt[nd * 8 + g][ks * 8 + t + 4];
                mma8(oacc[nd], pa0, pa1, pa2, pa3, b0, b1);
            }
        }
    }

    ol0 += __shfl_xor_sync(0xffffffffu, ol0, 1);
    ol0 += __shfl_xor_sync(0xffffffffu, ol0, 2);
    ol1 += __shfl_xor_sync(0xffffffffu, ol1, 1);
    ol1 += __shfl_xor_sync(0xffffffffu, ol1, 2);

    size_t pbase = ((size_t)((b * HH + h) * S + sp)) * QQ;
    if (qg < QQ) {
        if (t == 0) { pm[pbase + qg] = om0; pl[pbase + qg] = ol0; }
        float* ap = pacc + (pbase + qg) * HD;
        #pragma unroll
        for (int nd = 0; nd < 4; nd++)
            *reinterpret_cast<float2*>(ap + nd * 8 + 2 * t) =
                make_float2(oacc[nd][0], oacc[nd][1]);
    }
    if (qg8 < QQ) {
        if (t == 0) { pm[pbase + qg8] = om1; pl[pbase + qg8] = ol1; }
        float* ap = pacc + (pbase + qg8) * HD;
        #pragma unroll
        for (int nd = 0; nd < 4; nd++)
            *reinterpret_cast<float2*>(ap + nd * 8 + 2 * t) =
                make_float2(oacc[nd][2], oacc[nd][3]);
    }
}

// ---------------- split combine (writes fp16 for GEMM consumption) --------
__global__ __launch_bounds__(256) void attn_combine_kernel(
    const float* __restrict__ pm, const float* __restrict__ pl,
    const float* __restrict__ pacc, int S, __half* __restrict__ out)
{
    int tt = blockIdx.x * 256 + threadIdx.x;
    if (tt >= BB * HH * QQ * (HD / 2)) return;
    int dp = tt & (HD / 2 - 1);
    int idx = tt >> 4;
    int q = idx % QQ;
    int bh = idx / QQ;
    int b = bh / HH, h = bh % HH;

    float mg = -INFINITY;
    for (int s = 0; s < S; s++)
        mg = fmaxf(mg, pm[((size_t)bh * S + s) * QQ + q]);
    float Lsum = 0.f;
    float olo = 0.f, ohi = 0.f;
    for (int s = 0; s < S; s++) {
        size_t pidx = ((size_t)bh * S + s) * QQ + q;
        float w = __expf(pm[pidx] - mg);
        Lsum += pl[pidx] * w;
        float2 a = *reinterpret_cast<const float2*>(pacc + pidx * HD + 2 * dp);
        olo += w * a.x; ohi += w * a.y;
    }
    float inv = 1.f / Lsum;
    __half2 hv = __floats2half2_rn(olo * inv, ohi * inv);
    *reinterpret_cast<uint32_t*>(
        out + ((size_t)(b * QQ + q)) * DD + h * HD + 2 * dp) =
        *reinterpret_cast<uint32_t*>(&hv);
}

// ---------------- host launcher ----------------
static inline int cdiv(int a, int b) { return (a + b - 1) / b; }

extern "C" void kernel_launch(void* const* d_in, const int* in_sizes, int n_in,
                              void* d_out, int out_size)
{
    const float* queries   = (const float*)d_in[0];
    const float* memory    = (const float*)d_in[1];
    const float* memory_pos= (const float*)d_in[2];
    const float* query_pos = (const float*)d_in[3];
    const float* sa_in_w   = (const float*)d_in[4];
    const float* sa_in_b   = (const float*)d_in[5];
    const float* sa_out_w  = (const float*)d_in[6];
    const float* sa_out_b  = (const float*)d_in[7];
    const float* norm1_g   = (const float*)d_in[8];
    const float* norm1_b   = (const float*)d_in[9];
    const float* q_w       = (const float*)d_in[10];
    const float* q_b       = (const float*)d_in[11];
    const float* k_w       = (const float*)d_in[12];
    const float* k_b       = (const float*)d_in[13];
    const float* v_w       = (const float*)d_in[14];
    const float* v_b       = (const float*)d_in[15];
    const float* o_w       = (const float*)d_in[16];
    const float* o_b       = (const float*)d_in[17];
    const float* norm2_g   = (const float*)d_in[18];
    const float* norm2_b   = (const float*)d_in[19];
    const float* beta      = (const float*)d_in[20];
    const float* dk_w1     = (const float*)d_in[21];
    const float* dk_b1     = (const float*)d_in[22];
    const float* dk_w2     = (const float*)d_in[23];
    const float* dk_b2     = (const float*)d_in[24];
    const float* ffn_w1    = (const float*)d_in[25];
    const float* ffn_b1    = (const float*)d_in[26];
    const float* ffn_w2    = (const float*)d_in[27];
    const float* ffn_b2    = (const float*)d_in[28];
    const float* norm3_g   = (const float*)d_in[29];
    const float* norm3_b   = (const float*)d_in[30];

    float *g_qkv, *g_x1, *g_x2, *g_q, *g_k, *g_v, *g_bias,
          *g_part, *g_pm, *g_pl, *g_pacc;
    cudaGetSymbolAddress((void**)&g_qkv,  s_qkv);
    cudaGetSymbolAddress((void**)&g_x1,   s_x1);
    cudaGetSymbolAddress((void**)&g_x2,   s_x2);
    cudaGetSymbolAddress((void**)&g_q,    s_q);
    cudaGetSymbolAddress((void**)&g_k,    s_k);
    cudaGetSymbolAddress((void**)&g_v,    s_v);
    cudaGetSymbolAddress((void**)&g_bias, s_bias);
    cudaGetSymbolAddress((void**)&g_part, s_part);
    cudaGetSymbolAddress((void**)&g_pm,   s_pm);
    cudaGetSymbolAddress((void**)&g_pl,   s_pl);
    cudaGetSymbolAddress((void**)&g_pacc, s_pacc);

    __half *hq, *hm, *h_siw, *h_sow, *h_qw, *h_kw, *h_vw, *h_ow,
           *h_fw1, *h_fw2, *hsa, *hca, *hx1, *hx2, *hffn;
    cudaGetSymbolAddress((void**)&hq,    h_queries);
    cudaGetSymbolAddress((void**)&hm,    h_memory);
    cudaGetSymbolAddress((void**)&h_siw, h_sa_in_w);
    cudaGetSymbolAddress((void**)&h_sow, h_sa_out_w);
    cudaGetSymbolAddress((void**)&h_qw,  h_q_w);
    cudaGetSymbolAddress((void**)&h_kw,  h_k_w);
    cudaGetSymbolAddress((void**)&h_vw,  h_v_w);
    cudaGetSymbolAddress((void**)&h_ow,  h_o_w);
    cudaGetSymbolAddress((void**)&h_fw1, h_ffn_w1);
    cudaGetSymbolAddress((void**)&h_fw2, h_ffn_w2);
    cudaGetSymbolAddress((void**)&hsa,   h_sa);
    cudaGetSymbolAddress((void**)&hca,   h_ca);
    cudaGetSymbolAddress((void**)&hx1,   h_x1);
    cudaGetSymbolAddress((void**)&hx2,   h_x2);
    cudaGetSymbolAddress((void**)&hffn,  h_ffn);

    static cudaStream_t st2 = nullptr, st3 = nullptr, st4 = nullptr;
    static cudaEvent_t ev0 = nullptr, ev2 = nullptr, ev3 = nullptr,
                       ev4 = nullptr, ev5 = nullptr;
    if (st2 == nullptr) {
        cudaStreamCreateWithFlags(&st2, cudaStreamNonBlocking);
        cudaStreamCreateWithFlags(&st3, cudaStreamNonBlocking);
        cudaStreamCreateWithFlags(&st4, cudaStreamNonBlocking);
        cudaEventCreateWithFlags(&ev0, cudaEventDisableTiming);
        cudaEventCreateWithFlags(&ev2, cudaEventDisableTiming);
        cudaEventCreateWithFlags(&ev3, cudaEventDisableTiming);
        cudaEventCreateWithFlags(&ev4, cudaEventDisableTiming);
        cudaEventCreateWithFlags(&ev5, cudaEventDisableTiming);
    }

    const int Mq = BB * QQ;   // 2400
    const int Mm = BB * LL;   // 8192
    const int NCOMB = BB * HH * QQ * (HD / 2);

    auto conv = [](const float* s, __half* d, int n, cudaStream_t st) {
        f2h_kernel<<<cdiv(n / 8, 256), 256, 0, st>>>(s, d, n);
    };

    // ---- fork ----
    cudaEventRecord(ev0, 0);
    cudaStreamWaitEvent(st2, ev0, 0);
    cudaStreamWaitEvent(st3, ev0, 0);
    cudaStreamWaitEvent(st4, ev0, 0);

    // st2: memory + KV weights conversion, then fused KV GEMM
    conv(memory, hm, Mm * DD, st2);
    conv(k_w, h_kw, DD * DD, st2);
    conv(v_w, h_vw, DD * DD, st2);
    gemm_f16_kernel<2><<<dim3(2 * DD / 64, cdiv(Mm, 128), 1), 256, 0, st2>>>(
        hm, h_kw, k_b, g_k, nullptr, Mm, DD, DD, 0, h_vw, v_b, g_v, nullptr);
    cudaEventRecord(ev2, st2);

    // st3: GASA bias
    gasa_bias_kernel<<<dim3(LL, BB), 128, 0, st3>>>(
        query_pos, memory_pos, dk_w1, dk_b1, dk_w2, dk_b2, beta, g_bias);
    cudaEventRecord(ev3, st3);

    // st4: sa_in_w first (critical for GEMM1), then fused remaining weights
    conv(sa_in_w, h_siw, 3 * DD * DD, st4);
    cudaEventRecord(ev5, st4);
    {
        int total = 3 * WSEG + 2 * WF;
        f2h_weights_kernel<<<cdiv(total / 8, 256), 256, 0, st4>>>(
            sa_out_w, q_w, o_w, ffn_w1, ffn_w2,
            h_sow, h_qw, h_ow, h_fw1, h_fw2);
    }
    cudaEventRecord(ev4, st4);

    // ---- main chain ----
    conv(queries, hq, Mq * DD, 0);
    cudaStreamWaitEvent(0, ev5, 0);

    // 1) self-attn packed in-proj (fp32 out for attention)
    gemm_f16_kernel<2><<<dim3(3 * DD / 64, cdiv(Mq, 128), 1), 256>>>(
        hq, h_siw, sa_in_b, g_qkv, nullptr, Mq, 3 * DD, DD, 0);

    // 2) self-attention, split S=2 -> combine -> h_sa (fp16)
    {
        int S = 2, step = cdiv(QQ, S * 16) * 16;   // 304
        attn_mma_kernel<<<dim3(NQT * S, HH, BB), 128>>>(
            g_qkv, 3 * DD, g_qkv + DD, g_qkv + 2 * DD, 3 * DD,
            nullptr, QQ, S, step, g_pm, g_pl, g_pacc, 0);
        attn_combine_kernel<<<cdiv(NCOMB, 256), 256>>>(g_pm, g_pl, g_pacc, S, hsa);
    }

    cudaStreamWaitEvent(0, ev4, 0);

    // 3) SA out-proj split-K=2 + LN1 (x1 fp32 + fp16)
    gemm_f16_kernel<1><<<dim3(DD / 64, cdiv(Mq, 64), 2), 256>>>(
        hsa, h_sow, sa_out_b, g_part, nullptr, Mq, DD, DD, 0);
    ln_split_kernel<<<Mq / 8, 256>>>(queries, g_part, sa_out_b,
                                     norm1_g, norm1_b, g_x1, hx1, 2);

    // 4) Q projection (fp32 out for attention)
    gemm_f16_kernel<1><<<dim3(DD / 64, cdiv(Mq, 64), 1), 256>>>(
        hx1, h_qw, q_b, g_q, nullptr, Mq, DD, DD, 0);

    cudaStreamWaitEvent(0, ev2, 0);
    cudaStreamWaitEvent(0, ev3, 0);

    // 5) cross-attention, split S=4 -> combine -> h_ca (fp16)
    {
        int S = 4, step = cdiv(LL, S * 16) * 16;
        attn_mma_kernel<<<dim3(NQT * S, HH, BB), 128>>>(
            g_q, DD, g_k, g_v, DD, g_bias, LL, S, step,
            g_pm, g_pl, g_pacc, 1);
        attn_combine_kernel<<<cdiv(NCOMB, 256), 256>>>(g_pm, g_pl, g_pacc, S, hca);
    }

    // 6) O proj split-K=2 + LN2 (x2 fp32 + fp16)
    gemm_f16_kernel<1><<<dim3(DD / 64, cdiv(Mq, 64), 2), 256>>>(
        hca, h_ow, o_b, g_part, nullptr, Mq, DD, DD, 0);
    ln_split_kernel<<<Mq / 8, 256>>>(g_x1, g_part, o_b,
                                     norm2_g, norm2_b, g_x2, hx2, 2);

    // 7) FFN1 (relu) -> fp16 only
    gemm_f16_kernel<2><<<dim3(DFF / 64, cdiv(Mq, 128), 1), 256>>>(
        hx2, h_fw1, ffn_b1, nullptr, hffn, Mq, DFF, DD, 1);

    // 8) FFN2 split-K=4 partials + fused combine in LN3 -> output
    gemm_f16_kernel<1><<<dim3(DD / 64, cdiv(Mq, 64), 4), 256>>>(
        hffn, h_fw2, ffn_b2, g_part, nullptr, Mq, DD, DFF, 0);
    ln_split_kernel<<<Mq / 8, 256>>>(g_x2, g_part, ffn_b2,
                                     norm3_g, norm3_b, (float*)d_out, nullptr, 4);
}

// round 12
// speedup vs baseline: 1.2116x; 1.1140x over previous
#include <cuda_runtime.h>
#include <cuda_fp16.h>
#include <math.h>
#include <stdint.h>

// ---------------- problem constants ----------------
#define BB 4
#define QQ 600
#define LL 2048
#define DD 256
#define HH 8
#define HD 32
#define DFF 2048
#define KD 32
#define SCALE 0.17677669529663687f   // 32^-0.5
#define NQT 10                       // ceil(600/64) 64-query tiles

typedef unsigned long long u64;

// ---------------- helpers ----------------
__device__ __forceinline__ void mma16h(float c[4], uint32_t a0, uint32_t a1,
                                       uint32_t a2, uint32_t a3,
                                       uint32_t b0, uint32_t b1) {
    asm("mma.sync.aligned.m16n8k16.row.col.f32.f16.f16.f32 "
        "{%0,%1,%2,%3},{%4,%5,%6,%7},{%8,%9},{%0,%1,%2,%3};"
        : "+f"(c[0]), "+f"(c[1]), "+f"(c[2]), "+f"(c[3])
        : "r"(a0), "r"(a1), "r"(a2), "r"(a3), "r"(b0), "r"(b1));
}
__device__ __forceinline__ void ldsm4(uint32_t& r0, uint32_t& r1,
                                      uint32_t& r2, uint32_t& r3, uint32_t addr) {
    asm volatile("ldmatrix.sync.aligned.m8n8.x4.shared.b16 {%0,%1,%2,%3}, [%4];"
                 : "=r"(r0), "=r"(r1), "=r"(r2), "=r"(r3) : "r"(addr));
}
__device__ __forceinline__ void cp16(uint32_t dst, const void* src, int srcsize) {
    asm volatile("cp.async.ca.shared.global [%0], [%1], 16, %2;"
                 :: "r"(dst), "l"(src), "r"(srcsize));
}
__device__ __forceinline__ void cp_commit() {
    asm volatile("cp.async.commit_group;");
}
template<int N>
__device__ __forceinline__ void cp_wait() {
    asm volatile("cp.async.wait_group %0;" :: "n"(N));
}
__device__ __forceinline__ uint32_t h2bits(float lo, float hi) {
    __half2 h = __floats2half2_rn(lo, hi);
    return *reinterpret_cast<uint32_t*>(&h);
}

// ---------------- scratch (device globals) ----------------
__device__ float s_qkv [BB*QQ*3*DD];
__device__ float s_x1  [BB*QQ*DD];
__device__ float s_x2  [BB*QQ*DD];
__device__ float s_q   [BB*QQ*DD];
__device__ float s_k   [BB*LL*DD];
__device__ float s_v   [BB*LL*DD];
__device__ float s_bias[BB*LL*QQ];
__device__ float s_part[4*BB*QQ*DD];
__device__ float s_pm  [BB*HH*8*QQ];
__device__ float s_pl  [BB*HH*8*QQ];
__device__ float s_pacc[BB*HH*8*QQ*HD];
// fp16 copies
__device__ __half h_queries[BB*QQ*DD];
__device__ __half h_memory [BB*LL*DD];
__device__ __half h_sa_in_w[3*DD*DD];
__device__ __half h_sa_out_w[DD*DD];
__device__ __half h_q_w[DD*DD];
__device__ __half h_k_w[DD*DD];
__device__ __half h_v_w[DD*DD];
__device__ __half h_o_w[DD*DD];
__device__ __half h_ffn_w1[DFF*DD];
__device__ __half h_ffn_w2[DD*DFF];
__device__ __half h_sa [BB*QQ*DD];
__device__ __half h_ca [BB*QQ*DD];
__device__ __half h_x1 [BB*QQ*DD];
__device__ __half h_x2 [BB*QQ*DD];
__device__ __half h_ffn[BB*QQ*DFF];

// ---------------- fp32 -> fp16 convert (8 elts/thread) ----------------
__device__ __forceinline__ void conv8(const float* src, __half* dst, int i) {
    float4 x0 = *reinterpret_cast<const float4*>(src + i);
    float4 x1 = *reinterpret_cast<const float4*>(src + i + 4);
    uint4 u;
    u.x = h2bits(x0.x, x0.y);
    u.y = h2bits(x0.z, x0.w);
    u.z = h2bits(x1.x, x1.y);
    u.w = h2bits(x1.z, x1.w);
    *reinterpret_cast<uint4*>(dst + i) = u;
}

__global__ __launch_bounds__(256) void f2h_kernel(
    const float* __restrict__ src, __half* __restrict__ dst, int n)
{
    int i = (blockIdx.x * 256 + threadIdx.x) * 8;
    if (i >= n) return;
    conv8(src, dst, i);
}

// fused 5-way weight conversion
#define WSEG (DD * DD)
#define WF   (DFF * DD)
__global__ __launch_bounds__(256) void f2h_weights_kernel(
    const float* __restrict__ sow, const float* __restrict__ qw,
    const float* __restrict__ ow, const float* __restrict__ fw1,
    const float* __restrict__ fw2,
    __half* __restrict__ hsow, __half* __restrict__ hqw,
    __half* __restrict__ how, __half* __restrict__ hfw1,
    __half* __restrict__ hfw2)
{
    int i = (blockIdx.x * 256 + threadIdx.x) * 8;
    if (i < WSEG) { conv8(sow, hsow, i); return; }
    i -= WSEG;
    if (i < WSEG) { conv8(qw, hqw, i); return; }
    i -= WSEG;
    if (i < WSEG) { conv8(ow, how, i); return; }
    i -= WSEG;
    if (i < WF) { conv8(fw1, hfw1, i); return; }
    i -= WF;
    if (i < WF) conv8(fw2, hfw2, i);
}

// ---------------- FP16 tensor-core GEMM (cp.async + ldmatrix, 32k stages) --
#define KP 40
#define NST 3

template<int MF>
__global__ __launch_bounds__(256) void gemm_f16_kernel(
    const __half* __restrict__ A, const __half* __restrict__ W,
    const float* __restrict__ bias, float* C, __half* Ch,
    int M, int N, int K, int relu,
    const __half* __restrict__ W2 = nullptr,
    const float* __restrict__ bias2 = nullptr,
    float* C2 = nullptr, __half* C2h = nullptr)
{
    __shared__ __align__(16) __half As[NST][64 * MF][KP];
    __shared__ __align__(16) __half Ws[NST][64][KP];

    const int tid = threadIdx.x;
    const int lane = tid & 31;
    const int w = tid >> 5;
    const int wm = w & 3;
    const int wn = w >> 2;
    const int g = lane >> 2;
    const int t = lane & 3;

    int bx = blockIdx.x;
    const int nblk = N / 64;
    if (W2 != nullptr && bx >= nblk) {
        bx -= nblk;
        W = W2; bias = bias2; C = C2; Ch = C2h;
    }

    const int m0 = blockIdx.y * (64 * MF);
    const int n0 = bx * 64;

    const int nsplit = gridDim.z;
    const int Klen = K / nsplit;
    const int kstart = blockIdx.z * Klen;
    float* Cout = (C && nsplit > 1) ? (C + (size_t)blockIdx.z * M * N) : C;

    const uint32_t as_base = (uint32_t)__cvta_generic_to_shared(&As[0][0][0]);
    const uint32_t ws_base = (uint32_t)__cvta_generic_to_shared(&Ws[0][0][0]);

    float acc[MF][4][4];
    #pragma unroll
    for (int i = 0; i < MF; i++)
        #pragma unroll
        for (int j = 0; j < 4; j++)
            #pragma unroll
            for (int e = 0; e < 4; e++) acc[i][j][e] = 0.f;

    const int m_warp = wm * (16 * MF);
    const int n_warp = wn * 32;
    const int nIter = Klen / 32;

    const int lr8 = lane & 7;
    const int lb1 = (lane >> 3) & 1;
    const int lb2 = (lane >> 4) & 1;
    uint32_t aAddr[MF];
    #pragma unroll
    for (int mi = 0; mi < MF; mi++) {
        int row = m_warp + mi * 16 + lr8 + lb1 * 8;
        aAddr[mi] = as_base + (row * KP + lb2 * 8) * 2;
    }
    uint32_t bAddr[2];
    #pragma unroll
    for (int p = 0; p < 2; p++) {
        int row = n_warp + p * 16 + lb2 * 8 + lr8;
        bAddr[p] = ws_base + (row * KP + lb1 * 8) * 2;
    }
    const uint32_t aStride = (64 * MF) * KP * 2;
    const uint32_t bStride = 64 * KP * 2;

    auto load_stage = [&](int st, int it) {
        const int kg = kstart + it * 32;
        if (MF == 2) {
            #pragma unroll
            for (int s = 0; s < 2; s++) {
                int idx = tid + s * 256;
                int r = idx >> 2, kc = (idx & 3) * 8;
                int arow = m0 + r;
                uint32_t dst = as_base + ((st * 128 + r) * KP + kc) * 2;
                cp16(dst, A + (size_t)arow * K + kg + kc, (arow < M) ? 16 : 0);
            }
            {
                int r = tid >> 2, kc = (tid & 3) * 8;
                uint32_t dst = ws_base + ((st * 64 + r) * KP + kc) * 2;
                cp16(dst, W + (size_t)(n0 + r) * K + kg + kc, 16);
            }
        } else {
            int r = tid >> 2, kc = (tid & 3) * 8;
            int arow = m0 + r;
            uint32_t dst = as_base + ((st * 64 + r) * KP + kc) * 2;
            cp16(dst, A + (size_t)arow * K + kg + kc, (arow < M) ? 16 : 0);
            uint32_t dst2 = ws_base + ((st * 64 + r) * KP + kc) * 2;
            cp16(dst2, W + (size_t)(n0 + r) * K + kg + kc, 16);
        }
        cp_commit();
    };

    load_stage(0, 0);
    load_stage(1, 1);

    for (int it = 0; it < nIter; it++) {
        cp_wait<NST - 2>();
        __syncthreads();
        if (it + NST - 1 < nIter) load_stage((it + NST - 1) % NST, it + NST - 1);
        else cp_commit();

        const int st = it % NST;
        #pragma unroll
        for (int kk = 0; kk < 32; kk += 16) {
            uint32_t b0[4], b1[4];
            ldsm4(b0[0], b1[0], b0[1], b1[1], bAddr[0] + st * bStride + kk * 2);
            ldsm4(b0[2], b1[2], b0[3], b1[3], bAddr[1] + st * bStride + kk * 2);
            #pragma unroll
            for (int mi = 0; mi < MF; mi++) {
                uint32_t a0, a1, a2, a3;
                ldsm4(a0, a1, a2, a3, aAddr[mi] + st * aStride + kk * 2);
                #pragma unroll
                for (int ni = 0; ni < 4; ni++)
                    mma16h(acc[mi][ni], a0, a1, a2, a3, b0[ni], b1[ni]);
            }
        }
    }

    #pragma unroll
    for (int mi = 0; mi < MF; mi++) {
        #pragma unroll
        for (int ni = 0; ni < 4; ni++) {
            int col = n0 + n_warp + ni * 8 + 2 * t;
            float bz0 = 0.f, bz1 = 0.f;
            if (nsplit == 1) { bz0 = bias[col]; bz1 = bias[col + 1]; }
            int r0 = m0 + m_warp + mi * 16 + g;
            int r1 = r0 + 8;
            float v0 = acc[mi][ni][0] + bz0, v1 = acc[mi][ni][1] + bz1;
            float v2 = acc[mi][ni][2] + bz0, v3 = acc[mi][ni][3] + bz1;
            if (relu) {
                v0 = fmaxf(v0, 0.f); v1 = fmaxf(v1, 0.f);
                v2 = fmaxf(v2, 0.f); v3 = fmaxf(v3, 0.f);
            }
            if (Cout) {
                if (r0 < M) *reinterpret_cast<float2*>(Cout + (size_t)r0 * N + col) = make_float2(v0, v1);
                if (r1 < M) *reinterpret_cast<float2*>(Cout + (size_t)r1 * N + col) = make_float2(v2, v3);
            }
            if (Ch) {
                if (r0 < M) {
                    uint32_t hv = h2bits(v0, v1);
                    *reinterpret_cast<uint32_t*>(Ch + (size_t)r0 * N + col) = hv;
                }
                if (r1 < M) {
                    uint32_t hv = h2bits(v2, v3);
                    *reinterpret_cast<uint32_t*>(Ch + (size_t)r1 * N + col) = hv;
                }
            }
        }
    }
}

// ---------------- warp-per-row LayerNorm core ----------------
__device__ __forceinline__ void lnw_finish(
    float v[8], int lane, const float* g, const float* bt,
    float* out, __half* outh, size_t row)
{
    float s1 = 0.f, s2 = 0.f;
    #pragma unroll
    for (int i = 0; i < 8; i++) { s1 += v[i]; s2 += v[i] * v[i]; }
    #pragma unroll
    for (int o = 16; o > 0; o >>= 1) {
        s1 += __shfl_xor_sync(0xffffffffu, s1, o);
        s2 += __shfl_xor_sync(0xffffffffu, s2, o);
    }
    float mean = s1 * (1.f / DD);
    float var = s2 * (1.f / DD) - mean * mean;
    float rstd = rsqrtf(var + 1e-5f);
    int c0 = lane * 8;
    float r[8];
    #pragma unroll
    for (int i = 0; i < 8; i++)
        r[i] = (v[i] - mean) * rstd * g[c0 + i] + bt[c0 + i];
    if (out) {
        *reinterpret_cast<float4*>(out + row * DD + c0) = make_float4(r[0], r[1], r[2], r[3]);
        *reinterpret_cast<float4*>(out + row * DD + c0 + 4) = make_float4(r[4], r[5], r[6], r[7]);
    }
    if (outh) {
        uint4 u;
        u.x = h2bits(r[0], r[1]);
        u.y = h2bits(r[2], r[3]);
        u.z = h2bits(r[4], r[5]);
        u.w = h2bits(r[6], r[7]);
        *reinterpret_cast<uint4*>(outh + row * DD + c0) = u;
    }
}

__global__ __launch_bounds__(256) void ln_split_kernel(
    const float* __restrict__ X, const float* __restrict__ parts,
    const float* __restrict__ fbias,
    const float* __restrict__ g, const float* __restrict__ bt,
    float* out, __half* outh, int nsplit)
{
    const int lane = threadIdx.x & 31;
    const size_t row = blockIdx.x * 8 + (threadIdx.x >> 5);
    const size_t stride = (size_t)BB * QQ * DD;
    int c0 = lane * 8;
    float v[8];
    float4 x0 = *reinterpret_cast<const float4*>(X + row * DD + c0);
    float4 x1 = *reinterpret_cast<const float4*>(X + row * DD + c0 + 4);
    float4 f0 = *reinterpret_cast<const float4*>(fbias + c0);
    float4 f1 = *reinterpret_cast<const float4*>(fbias + c0 + 4);
    v[0] = x0.x + f0.x; v[1] = x0.y + f0.y; v[2] = x0.z + f0.z; v[3] = x0.w + f0.w;
    v[4] = x1.x + f1.x; v[5] = x1.y + f1.y; v[6] = x1.z + f1.z; v[7] = x1.w + f1.w;
    for (int s = 0; s < nsplit; s++) {
        float4 p0 = *reinterpret_cast<const float4*>(parts + s * stride + row * DD + c0);
        float4 p1 = *reinterpret_cast<const float4*>(parts + s * stride + row * DD + c0 + 4);
        v[0] += p0.x; v[1] += p0.y; v[2] += p0.z; v[3] += p0.w;
        v[4] += p1.x; v[5] += p1.y; v[6] += p1.z; v[7] += p1.w;
    }
    lnw_finish(v, lane, g, bt, out, outh, row);
}

// ---------------- GASA geometric bias: block per (b,l) ----------------
__global__ __launch_bounds__(128) void gasa_bias_kernel(
    const float* __restrict__ qpos, const float* __restrict__ mpos,
    const float* __restrict__ w1, const float* __restrict__ b1,
    const float* __restrict__ w2, const float* __restrict__ b2,
    const float* __restrict__ betap, float* __restrict__ biasT)
{
    const int l = blockIdx.x;
    const int b = blockIdx.y;
    const int tid = threadIdx.x;

    __shared__ float sw1[KD], sb1[KD], sw2[KD], smp[3], sb2, sbeta;
    if (tid < KD) {
        sw1[tid] = w1[tid];
        sb1[tid] = b1[tid];
        sw2[tid] = w2[tid];
    }
    if (tid < 3) smp[tid] = mpos[((size_t)b * LL + l) * 3 + tid];
    if (tid == 3) sb2 = b2[0];
    if (tid == 4) sbeta = betap[0];
    __syncthreads();

    const float mx = smp[0], my = smp[1], mz = smp[2];
    const float bb2 = sb2, bet = sbeta;
    float* orow = biasT + ((size_t)b * LL + l) * QQ;

    for (int q = tid; q < QQ; q += 128) {
        const float* qp = qpos + ((size_t)b * QQ + q) * 3;
        float dx = qp[0] - mx, dy = qp[1] - my, dz = qp[2] - mz;
        float dist = sqrtf(fmaxf(dx * dx + dy * dy + dz * dz, 0.f));
        float s = 0.f;
        #pragma unroll
        for (int k = 0; k < KD; k++) {
            float h = fmaxf(dist * sw1[k] + sb1[k], 0.f);
            s += h * sw2[k];
        }
        s += bb2;
        s = fminf(fmaxf(s, -10.f), 0.f);
        orow[q] = s * bet;
    }
}

// ---------------- fp16 tensor-core flash attention partials ----------------
// Warp owns 16 queries; chunk = 16 keys. QK and PV via mma.m16n8k16.f16.
// P's score C-fragment layout IS its A-fragment layout -> no transpose.
__global__ __launch_bounds__(128) void attn_mma_kernel(
    const float* __restrict__ Qp, int qstride,
    const float* __restrict__ Kp, const float* __restrict__ Vp, int kvstride,
    const float* __restrict__ biasT, int Lk, int S, int step,
    float* __restrict__ pm, float* __restrict__ pl, float* __restrict__ pacc,
    int useBias)
{
    const int b = blockIdx.z, h = blockIdx.y;
    const int sp = blockIdx.x / NQT;
    const int qt = blockIdx.x % NQT;
    const int tid = threadIdx.x;
    const int lane = tid & 31;
    const int warp = tid >> 5;
    const int g = lane >> 2;
    const int t = lane & 3;

    const int q0 = qt * 64 + warp * 16;
    const int qg  = q0 + g;
    const int qg8 = q0 + g + 8;
    const int qgc  = min(qg, QQ - 1);
    const int qg8c = min(qg8, QQ - 1);

    const int ls = sp * step;
    const int le = min(ls + step, Lk);

    // Q a-fragments (fp16, pre-scaled): qa[ks] covers d [ks*16, ks*16+16)
    uint32_t qa[2][4];
    {
        const float* q0p = Qp + ((size_t)(b * QQ + qgc)) * qstride + h * HD;
        const float* q1p = Qp + ((size_t)(b * QQ + qg8c)) * qstride + h * HD;
        #pragma unroll
        for (int ks = 0; ks < 2; ks++) {
            int d = ks * 16 + 2 * t;
            qa[ks][0] = h2bits(q0p[d] * SCALE,     q0p[d + 1] * SCALE);
            qa[ks][1] = h2bits(q1p[d] * SCALE,     q1p[d + 1] * SCALE);
            qa[ks][2] = h2bits(q0p[d + 8] * SCALE, q0p[d + 9] * SCALE);
            qa[ks][3] = h2bits(q1p[d + 8] * SCALE, q1p[d + 9] * SCALE);
        }
    }

    __shared__ __align__(16) __half Kh[16][40];   // [key][d], 80B pitch
    __shared__ __align__(16) __half Vh[HD][24];   // [d][key], 48B pitch
    __shared__ float Bsm[16][68];

    float oacc[4][4];
    #pragma unroll
    for (int i = 0; i < 4; i++)
        #pragma unroll
        for (int j = 0; j < 4; j++) oacc[i][j] = 0.f;
    float om0 = -INFINITY, om1 = -INFINITY;
    float ol0 = 0.f, ol1 = 0.f;

    const int key_l = tid >> 3;
    const int d0 = (tid & 7) * 4;
    const int bq0 = (tid & 7) * 8;
    const bool qtail = (qt == NQT - 1);

    const uint32_t kh_base = (uint32_t)__cvta_generic_to_shared(&Kh[0][0]);
    const uint32_t vh_base = (uint32_t)__cvta_generic_to_shared(&Vh[0][0]);
    const int lr8 = lane & 7;
    const int lb1 = (lane >> 3) & 1;
    const int lb2 = (lane >> 4) & 1;
    // K ldsm: rows = keys (lb2 picks key group), cols d (lb1 picks k8 block)
    const uint32_t kAddr = kh_base + ((lb2 * 8 + lr8) * 40 + lb1 * 8) * 2;
    // V ldsm: rows = d (2 pairs of 16), cols keys
    uint32_t vAddr[2];
    #pragma unroll
    for (int p = 0; p < 2; p++)
        vAddr[p] = vh_base + ((p * 16 + lb2 * 8 + lr8) * 24 + lb1 * 8) * 2;

    float4 kreg, vreg, breg0, breg1;

    auto prefetch = [&](int l0) {
        int grow = b * Lk + min(l0 + key_l, Lk - 1);
        kreg = *reinterpret_cast<const float4*>(
            Kp + (size_t)grow * kvstride + h * HD + d0);
        vreg = *reinterpret_cast<const float4*>(
            Vp + (size_t)grow * kvstride + h * HD + d0);
        if (useBias) {
            const float* brow = biasT + ((size_t)(b * Lk + l0 + key_l)) * QQ
                                + qt * 64 + bq0;
            if (!qtail) {
                breg0 = *reinterpret_cast<const float4*>(brow);
                breg1 = *reinterpret_cast<const float4*>(brow + 4);
            } else {
                int qb = qt * 64 + bq0;
                float e[8];
                #pragma unroll
                for (int i = 0; i < 8; i++)
                    e[i] = (qb + i < QQ) ? brow[i] : 0.f;
                breg0 = make_float4(e[0], e[1], e[2], e[3]);
                breg1 = make_float4(e[4], e[5], e[6], e[7]);
            }
        }
    };

    prefetch(ls);

    for (int l0 = ls; l0 < le; l0 += 16) {
        __syncthreads();
        {
            // K: fp16 [key][d]
            uint32_t k01 = h2bits(kreg.x, kreg.y);
            uint32_t k23 = h2bits(kreg.z, kreg.w);
            *reinterpret_cast<uint32_t*>(&Kh[key_l][d0])     = k01;
            *reinterpret_cast<uint32_t*>(&Kh[key_l][d0 + 2]) = k23;
            // V: fp16 transposed [d][key]
            Vh[d0 + 0][key_l] = __float2half_rn(vreg.x);
            Vh[d0 + 1][key_l] = __float2half_rn(vreg.y);
            Vh[d0 + 2][key_l] = __float2half_rn(vreg.z);
            Vh[d0 + 3][key_l] = __float2half_rn(vreg.w);
            if (useBias) {
                *reinterpret_cast<float4*>(&Bsm[key_l][bq0]) = breg0;
                *reinterpret_cast<float4*>(&Bsm[key_l][bq0 + 4]) = breg1;
            }
        }
        if (l0 + 16 < le) prefetch(l0 + 16);
        __syncthreads();

        // --- scores: S = Qs @ K^T (2 ldsm4 + 4 mma16h) ---
        float sc[2][4];
        sc[0][0] = sc[0][1] = sc[0][2] = sc[0][3] = 0.f;
        sc[1][0] = sc[1][1] = sc[1][2] = sc[1][3] = 0.f;
        #pragma unroll
        for (int ks = 0; ks < 2; ks++) {
            uint32_t r0, r1, r2, r3;
            ldsm4(r0, r1, r2, r3, kAddr + ks * 32);   // +16 halves
            mma16h(sc[0], qa[ks][0], qa[ks][1], qa[ks][2], qa[ks][3], r0, r1);
            mma16h(sc[1], qa[ks][0], qa[ks][1], qa[ks][2], qa[ks][3], r2, r3);
        }

        // --- bias (smem) + key-bound mask ---
        #pragma unroll
        for (int nf = 0; nf < 2; nf++) {
            if (useBias) {
                int brow = nf * 8 + 2 * t;
                int c0 = warp * 16 + g;
                sc[nf][0] += Bsm[brow][c0];
                sc[nf][1] += Bsm[brow + 1][c0];
                sc[nf][2] += Bsm[brow][c0 + 8];
                sc[nf][3] += Bsm[brow + 1][c0 + 8];
            }
            int kc = l0 + nf * 8 + 2 * t;
            if (kc >= le)     { sc[nf][0] = -1e30f; sc[nf][2] = -1e30f; }
            if (kc + 1 >= le) { sc[nf][1] = -1e30f; sc[nf][3] = -1e30f; }
        }

        // --- row max + online rescale ---
        float mx0 = fmaxf(fmaxf(sc[0][0], sc[0][1]), fmaxf(sc[1][0], sc[1][1]));
        float mx1 = fmaxf(fmaxf(sc[0][2], sc[0][3]), fmaxf(sc[1][2], sc[1][3]));
        mx0 = fmaxf(mx0, __shfl_xor_sync(0xffffffffu, mx0, 1));
        mx0 = fmaxf(mx0, __shfl_xor_sync(0xffffffffu, mx0, 2));
        mx1 = fmaxf(mx1, __shfl_xor_sync(0xffffffffu, mx1, 1));
        mx1 = fmaxf(mx1, __shfl_xor_sync(0xffffffffu, mx1, 2));

        float nm0 = fmaxf(om0, mx0), nm1 = fmaxf(om1, mx1);
        float cr0 = __expf(om0 - nm0), cr1 = __expf(om1 - nm1);
        om0 = nm0; om1 = nm1;
        ol0 *= cr0; ol1 *= cr1;
        #pragma unroll
        for (int nd = 0; nd < 4; nd++) {
            oacc[nd][0] *= cr0; oacc[nd][1] *= cr0;
            oacc[nd][2] *= cr1; oacc[nd][3] *= cr1;
        }

        // --- P = exp(S - m) ---
        #pragma unroll
        for (int nf = 0; nf < 2; nf++) {
            sc[nf][0] = __expf(sc[nf][0] - nm0);
            sc[nf][1] = __expf(sc[nf][1] - nm0);
            sc[nf][2] = __expf(sc[nf][2] - nm1);
            sc[nf][3] = __expf(sc[nf][3] - nm1);
            ol0 += sc[nf][0] + sc[nf][1];
            ol1 += sc[nf][2] + sc[nf][3];
        }

        // --- PV: P c-frag layout == A-frag layout (no transpose!) ---
        uint32_t pa0 = h2bits(sc[0][0], sc[0][1]);   // row g,  keys 2t,2t+1
        uint32_t pa1 = h2bits(sc[0][2], sc[0][3]);   // row g8, keys 2t,2t+1
        uint32_t pa2 = h2bits(sc[1][0], sc[1][1]);   // row g,  keys 2t+8,2t+9
        uint32_t pa3 = h2bits(sc[1][2], sc[1][3]);   // row g8, keys 2t+8,2t+9
        uint32_t b0[4], b1[4];
        ldsm4(b0[0], b1[0], b0[1], b1[1], vAddr[0]);
        ldsm4(b0[2], b1[2], b0[3], b1[3], vAddr[1]);
        #pragma unroll
        for (int nd = 0; nd < 4; nd++)
            mma16h(oacc[nd], pa0, pa1, pa2, pa3, b0[nd], b1[nd]);
    }

    ol0 += __shfl_xor_sync(0xffffffffu, ol0, 1);
    ol0 += __shfl_xor_sync(0xffffffffu, ol0, 2);
    ol1 += __shfl_xor_sync(0xffffffffu, ol1, 1);
    ol1 += __shfl_xor_sync(0xffffffffu, ol1, 2);

    size_t pbase = ((size_t)((b * HH + h) * S + sp)) * QQ;
    if (qg < QQ) {
        if (t == 0) { pm[pbase + qg] = om0; pl[pbase + qg] = ol0; }
        float* ap = pacc + (pbase + qg) * HD;
        #pragma unroll
        for (int nd = 0; nd < 4; nd++)
            *reinterpret_cast<float2*>(ap + nd * 8 + 2 * t) =
                make_float2(oacc[nd][0], oacc[nd][1]);
    }
    if (qg8 < QQ) {
        if (t == 0) { pm[pbase + qg8] = om1; pl[pbase + qg8] = ol1; }
        float* ap = pacc + (pbase + qg8) * HD;
        #pragma unroll
        for (int nd = 0; nd < 4; nd++)
            *reinterpret_cast<float2*>(ap + nd * 8 + 2 * t) =
                make_float2(oacc[nd][2], oacc[nd][3]);
    }
}

// ---------------- split combine (writes fp16 for GEMM consumption) --------
__global__ __launch_bounds__(256) void attn_combine_kernel(
    const float* __restrict__ pm, const float* __restrict__ pl,
    const float* __restrict__ pacc, int S, __half* __restrict__ out)
{
    int tt = blockIdx.x * 256 + threadIdx.x;
    if (tt >= BB * HH * QQ * (HD / 2)) return;
    int dp = tt & (HD / 2 - 1);
    int idx = tt >> 4;
    int q = idx % QQ;
    int bh = idx / QQ;
    int b = bh / HH, h = bh % HH;

    float mg = -INFINITY;
    for (int s = 0; s < S; s++)
        mg = fmaxf(mg, pm[((size_t)bh * S + s) * QQ + q]);
    float Lsum = 0.f;
    float olo = 0.f, ohi = 0.f;
    for (int s = 0; s < S; s++) {
        size_t pidx = ((size_t)bh * S + s) * QQ + q;
        float w = __expf(pm[pidx] - mg);
        Lsum += pl[pidx] * w;
        float2 a = *reinterpret_cast<const float2*>(pacc + pidx * HD + 2 * dp);
        olo += w * a.x; ohi += w * a.y;
    }
    float inv = 1.f / Lsum;
    uint32_t hv = h2bits(olo * inv, ohi * inv);
    *reinterpret_cast<uint32_t*>(
        out + ((size_t)(b * QQ + q)) * DD + h * HD + 2 * dp) = hv;
}

// ---------------- host launcher ----------------
static inline int cdiv(int a, int b) { return (a + b - 1) / b; }

extern "C" void kernel_launch(void* const* d_in, const int* in_sizes, int n_in,
                              void* d_out, int out_size)
{
    const float* queries   = (const float*)d_in[0];
    const float* memory    = (const float*)d_in[1];
    const float* memory_pos= (const float*)d_in[2];
    const float* query_pos = (const float*)d_in[3];
    const float* sa_in_w   = (const float*)d_in[4];
    const float* sa_in_b   = (const float*)d_in[5];
    const float* sa_out_w  = (const float*)d_in[6];
    const float* sa_out_b  = (const float*)d_in[7];
    const float* norm1_g   = (const float*)d_in[8];
    const float* norm1_b   = (const float*)d_in[9];
    const float* q_w       = (const float*)d_in[10];
    const float* q_b       = (const float*)d_in[11];
    const float* k_w       = (const float*)d_in[12];
    const float* k_b       = (const float*)d_in[13];
    const float* v_w       = (const float*)d_in[14];
    const float* v_b       = (const float*)d_in[15];
    const float* o_w       = (const float*)d_in[16];
    const float* o_b       = (const float*)d_in[17];
    const float* norm2_g   = (const float*)d_in[18];
    const float* norm2_b   = (const float*)d_in[19];
    const float* beta      = (const float*)d_in[20];
    const float* dk_w1     = (const float*)d_in[21];
    const float* dk_b1     = (const float*)d_in[22];
    const float* dk_w2     = (const float*)d_in[23];
    const float* dk_b2     = (const float*)d_in[24];
    const float* ffn_w1    = (const float*)d_in[25];
    const float* ffn_b1    = (const float*)d_in[26];
    const float* ffn_w2    = (const float*)d_in[27];
    const float* ffn_b2    = (const float*)d_in[28];
    const float* norm3_g   = (const float*)d_in[29];
    const float* norm3_b   = (const float*)d_in[30];

    float *g_qkv, *g_x1, *g_x2, *g_q, *g_k, *g_v, *g_bias,
          *g_part, *g_pm, *g_pl, *g_pacc;
    cudaGetSymbolAddress((void**)&g_qkv,  s_qkv);
    cudaGetSymbolAddress((void**)&g_x1,   s_x1);
    cudaGetSymbolAddress((void**)&g_x2,   s_x2);
    cudaGetSymbolAddress((void**)&g_q,    s_q);
    cudaGetSymbolAddress((void**)&g_k,    s_k);
    cudaGetSymbolAddress((void**)&g_v,    s_v);
    cudaGetSymbolAddress((void**)&g_bias, s_bias);
    cudaGetSymbolAddress((void**)&g_part, s_part);
    cudaGetSymbolAddress((void**)&g_pm,   s_pm);
    cudaGetSymbolAddress((void**)&g_pl,   s_pl);
    cudaGetSymbolAddress((void**)&g_pacc, s_pacc);

    __half *hq, *hm, *h_siw, *h_sow, *h_qw, *h_kw, *h_vw, *h_ow,
           *h_fw1, *h_fw2, *hsa, *hca, *hx1, *hx2, *hffn;
    cudaGetSymbolAddress((void**)&hq,    h_queries);
    cudaGetSymbolAddress((void**)&hm,    h_memory);
    cudaGetSymbolAddress((void**)&h_siw, h_sa_in_w);
    cudaGetSymbolAddress((void**)&h_sow, h_sa_out_w);
    cudaGetSymbolAddress((void**)&h_qw,  h_q_w);
    cudaGetSymbolAddress((void**)&h_kw,  h_k_w);
    cudaGetSymbolAddress((void**)&h_vw,  h_v_w);
    cudaGetSymbolAddress((void**)&h_ow,  h_o_w);
    cudaGetSymbolAddress((void**)&h_fw1, h_ffn_w1);
    cudaGetSymbolAddress((void**)&h_fw2, h_ffn_w2);
    cudaGetSymbolAddress((void**)&hsa,   h_sa);
    cudaGetSymbolAddress((void**)&hca,   h_ca);
    cudaGetSymbolAddress((void**)&hx1,   h_x1);
    cudaGetSymbolAddress((void**)&hx2,   h_x2);
    cudaGetSymbolAddress((void**)&hffn,  h_ffn);

    static cudaStream_t st2 = nullptr, st3 = nullptr, st4 = nullptr;
    static cudaEvent_t ev0 = nullptr, ev2 = nullptr, ev3 = nullptr,
                       ev4 = nullptr, ev5 = nullptr;
    if (st2 == nullptr) {
        cudaStreamCreateWithFlags(&st2, cudaStreamNonBlocking);
        cudaStreamCreateWithFlags(&st3, cudaStreamNonBlocking);
        cudaStreamCreateWithFlags(&st4, cudaStreamNonBlocking);
        cudaEventCreateWithFlags(&ev0, cudaEventDisableTiming);
        cudaEventCreateWithFlags(&ev2, cudaEventDisableTiming);
        cudaEventCreateWithFlags(&ev3, cudaEventDisableTiming);
        cudaEventCreateWithFlags(&ev4, cudaEventDisableTiming);
        cudaEventCreateWithFlags(&ev5, cudaEventDisableTiming);
    }

    const int Mq = BB * QQ;   // 2400
    const int Mm = BB * LL;   // 8192
    const int NCOMB = BB * HH * QQ * (HD / 2);

    auto conv = [](const float* s, __half* d, int n, cudaStream_t st) {
        f2h_kernel<<<cdiv(n / 8, 256), 256, 0, st>>>(s, d, n);
    };

    // ---- fork ----
    cudaEventRecord(ev0, 0);
    cudaStreamWaitEvent(st2, ev0, 0);
    cudaStreamWaitEvent(st3, ev0, 0);
    cudaStreamWaitEvent(st4, ev0, 0);

    // st2: memory + KV weights conversion, then fused KV GEMM
    conv(memory, hm, Mm * DD, st2);
    conv(k_w, h_kw, DD * DD, st2);
    conv(v_w, h_vw, DD * DD, st2);
    gemm_f16_kernel<2><<<dim3(2 * DD / 64, cdiv(Mm, 128), 1), 256, 0, st2>>>(
        hm, h_kw, k_b, g_k, nullptr, Mm, DD, DD, 0, h_vw, v_b, g_v, nullptr);
    cudaEventRecord(ev2, st2);

    // st3: GASA bias
    gasa_bias_kernel<<<dim3(LL, BB), 128, 0, st3>>>(
        query_pos, memory_pos, dk_w1, dk_b1, dk_w2, dk_b2, beta, g_bias);
    cudaEventRecord(ev3, st3);

    // st4: sa_in_w first (critical for GEMM1), then fused remaining weights
    conv(sa_in_w, h_siw, 3 * DD * DD, st4);
    cudaEventRecord(ev5, st4);
    {
        int total = 3 * WSEG + 2 * WF;
        f2h_weights_kernel<<<cdiv(total / 8, 256), 256, 0, st4>>>(
            sa_out_w, q_w, o_w, ffn_w1, ffn_w2,
            h_sow, h_qw, h_ow, h_fw1, h_fw2);
    }
    cudaEventRecord(ev4, st4);

    // ---- main chain ----
    conv(queries, hq, Mq * DD, 0);
    cudaStreamWaitEvent(0, ev5, 0);

    // 1) self-attn packed in-proj (fp32 out for attention)
    gemm_f16_kernel<2><<<dim3(3 * DD / 64, cdiv(Mq, 128), 1), 256>>>(
        hq, h_siw, sa_in_b, g_qkv, nullptr, Mq, 3 * DD, DD, 0);

    // 2) self-attention, split S=2 -> combine -> h_sa (fp16)
    {
        int S = 2, step = cdiv(QQ, S * 16) * 16;   // 304
        attn_mma_kernel<<<dim3(NQT * S, HH, BB), 128>>>(
            g_qkv, 3 * DD, g_qkv + DD, g_qkv + 2 * DD, 3 * DD,
            nullptr, QQ, S, step, g_pm, g_pl, g_pacc, 0);
        attn_combine_kernel<<<cdiv(NCOMB, 256), 256>>>(g_pm, g_pl, g_pacc, S, hsa);
    }

    cudaStreamWaitEvent(0, ev4, 0);

    // 3) SA out-proj split-K=2 + LN1 (x1 fp32 + fp16)
    gemm_f16_kernel<1><<<dim3(DD / 64, cdiv(Mq, 64), 2), 256>>>(
        hsa, h_sow, sa_out_b, g_part, nullptr, Mq, DD, DD, 0);
    ln_split_kernel<<<Mq / 8, 256>>>(queries, g_part, sa_out_b,
                                     norm1_g, norm1_b, g_x1, hx1, 2);

    // 4) Q projection (fp32 out for attention)
    gemm_f16_kernel<1><<<dim3(DD / 64, cdiv(Mq, 64), 1), 256>>>(
        hx1, h_qw, q_b, g_q, nullptr, Mq, DD, DD, 0);

    cudaStreamWaitEvent(0, ev2, 0);
    cudaStreamWaitEvent(0, ev3, 0);

    // 5) cross-attention, split S=4 -> combine -> h_ca (fp16)
    {
        int S = 4, step = cdiv(LL, S * 16) * 16;
        attn_mma_kernel<<<dim3(NQT * S, HH, BB), 128>>>(
            g_q, DD, g_k, g_v, DD, g_bias, LL, S, step,
            g_pm, g_pl, g_pacc, 1);
        attn_combine_kernel<<<cdiv(NCOMB, 256), 256>>>(g_pm, g_pl, g_pacc, S, hca);
    }

    // 6) O proj split-K=2 + LN2 (x2 fp32 + fp16)
    gemm_f16_kernel<1><<<dim3(DD / 64, cdiv(Mq, 64), 2), 256>>>(
        hca, h_ow, o_b, g_part, nullptr, Mq, DD, DD, 0);
    ln_split_kernel<<<Mq / 8, 256>>>(g_x1, g_part, o_b,
                                     norm2_g, norm2_b, g_x2, hx2, 2);

    // 7) FFN1 (relu) -> fp16 only
    gemm_f16_kernel<2><<<dim3(DFF / 64, cdiv(Mq, 128), 1), 256>>>(
        hx2, h_fw1, ffn_b1, nullptr, hffn, Mq, DFF, DD, 1);

    // 8) FFN2 split-K=4 partials + fused combine in LN3 -> output
    gemm_f16_kernel<1><<<dim3(DD / 64, cdiv(Mq, 64), 4), 256>>>(
        hffn, h_fw2, ffn_b2, g_part, nullptr, Mq, DD, DFF, 0);
    ln_split_kernel<<<Mq / 8, 256>>>(g_x2, g_part, ffn_b2,
                                     norm3_g, norm3_b, (float*)d_out, nullptr, 4);
}

// round 13
// speedup vs baseline: 1.2191x; 1.0062x over previous
#include <cuda_runtime.h>
#include <cuda_fp16.h>
#include <math.h>
#include <stdint.h>

// ---------------- problem constants ----------------
#define BB 4
#define QQ 600
#define LL 2048
#define DD 256
#define HH 8
#define HD 32
#define DFF 2048
#define KD 32
#define SCALE 0.17677669529663687f   // 32^-0.5
#define NQT 10                       // ceil(600/64) 64-query tiles

typedef unsigned long long u64;

// ---------------- helpers ----------------
__device__ __forceinline__ void mma16h(float c[4], uint32_t a0, uint32_t a1,
                                       uint32_t a2, uint32_t a3,
                                       uint32_t b0, uint32_t b1) {
    asm("mma.sync.aligned.m16n8k16.row.col.f32.f16.f16.f32 "
        "{%0,%1,%2,%3},{%4,%5,%6,%7},{%8,%9},{%0,%1,%2,%3};"
        : "+f"(c[0]), "+f"(c[1]), "+f"(c[2]), "+f"(c[3])
        : "r"(a0), "r"(a1), "r"(a2), "r"(a3), "r"(b0), "r"(b1));
}
__device__ __forceinline__ void ldsm4(uint32_t& r0, uint32_t& r1,
                                      uint32_t& r2, uint32_t& r3, uint32_t addr) {
    asm volatile("ldmatrix.sync.aligned.m8n8.x4.shared.b16 {%0,%1,%2,%3}, [%4];"
                 : "=r"(r0), "=r"(r1), "=r"(r2), "=r"(r3) : "r"(addr));
}
__device__ __forceinline__ void cp16(uint32_t dst, const void* src, int srcsize) {
    asm volatile("cp.async.ca.shared.global [%0], [%1], 16, %2;"
                 :: "r"(dst), "l"(src), "r"(srcsize));
}
__device__ __forceinline__ void cp_commit() {
    asm volatile("cp.async.commit_group;");
}
template<int N>
__device__ __forceinline__ void cp_wait() {
    asm volatile("cp.async.wait_group %0;" :: "n"(N));
}
__device__ __forceinline__ uint32_t h2bits(float lo, float hi) {
    __half2 h = __floats2half2_rn(lo, hi);
    return *reinterpret_cast<uint32_t*>(&h);
}
__device__ __forceinline__ uint32_t hmul2b(uint32_t a, uint32_t b) {
    __half2 x = *reinterpret_cast<__half2*>(&a);
    __half2 y = *reinterpret_cast<__half2*>(&b);
    __half2 r = __hmul2(x, y);
    return *reinterpret_cast<uint32_t*>(&r);
}

// ---------------- scratch (device globals) ----------------
__device__ float s_x1  [BB*QQ*DD];
__device__ float s_x2  [BB*QQ*DD];
__device__ float s_bias[BB*LL*QQ];
__device__ float s_part[4*BB*QQ*DD];
__device__ float s_pm  [BB*HH*8*QQ];
__device__ float s_pl  [BB*HH*8*QQ];
__device__ float s_pacc[BB*HH*8*QQ*HD];
// fp16 tensors
__device__ __half h_queries[BB*QQ*DD];
__device__ __half h_memory [BB*LL*DD];
__device__ __half h_sa_in_w[3*DD*DD];
__device__ __half h_sa_out_w[DD*DD];
__device__ __half h_q_w[DD*DD];
__device__ __half h_k_w[DD*DD];
__device__ __half h_v_w[DD*DD];
__device__ __half h_o_w[DD*DD];
__device__ __half h_ffn_w1[DFF*DD];
__device__ __half h_ffn_w2[DD*DFF];
__device__ __half h_qkv[BB*QQ*3*DD];
__device__ __half h_qx [BB*QQ*DD];
__device__ __half h_kk [BB*LL*DD];
__device__ __half h_vv [BB*LL*DD];
__device__ __half h_sa [BB*QQ*DD];
__device__ __half h_ca [BB*QQ*DD];
__device__ __half h_x1 [BB*QQ*DD];
__device__ __half h_x2 [BB*QQ*DD];
__device__ __half h_ffn[BB*QQ*DFF];

// ---------------- fp32 -> fp16 convert (8 elts/thread) ----------------
__device__ __forceinline__ void conv8(const float* src, __half* dst, int i) {
    float4 x0 = *reinterpret_cast<const float4*>(src + i);
    float4 x1 = *reinterpret_cast<const float4*>(src + i + 4);
    uint4 u;
    u.x = h2bits(x0.x, x0.y);
    u.y = h2bits(x0.z, x0.w);
    u.z = h2bits(x1.x, x1.y);
    u.w = h2bits(x1.z, x1.w);
    *reinterpret_cast<uint4*>(dst + i) = u;
}

__global__ __launch_bounds__(256) void f2h_kernel(
    const float* __restrict__ src, __half* __restrict__ dst, int n)
{
    int i = (blockIdx.x * 256 + threadIdx.x) * 8;
    if (i >= n) return;
    conv8(src, dst, i);
}

// fused 5-way weight conversion
#define WSEG (DD * DD)
#define WF   (DFF * DD)
__global__ __launch_bounds__(256) void f2h_weights_kernel(
    const float* __restrict__ sow, const float* __restrict__ qw,
    const float* __restrict__ ow, const float* __restrict__ fw1,
    const float* __restrict__ fw2,
    __half* __restrict__ hsow, __half* __restrict__ hqw,
    __half* __restrict__ how, __half* __restrict__ hfw1,
    __half* __restrict__ hfw2)
{
    int i = (blockIdx.x * 256 + threadIdx.x) * 8;
    if (i < WSEG) { conv8(sow, hsow, i); return; }
    i -= WSEG;
    if (i < WSEG) { conv8(qw, hqw, i); return; }
    i -= WSEG;
    if (i < WSEG) { conv8(ow, how, i); return; }
    i -= WSEG;
    if (i < WF) { conv8(fw1, hfw1, i); return; }
    i -= WF;
    if (i < WF) conv8(fw2, hfw2, i);
}

// ---------------- FP16 tensor-core GEMM (cp.async + ldmatrix, 32k stages) --
#define KP 40
#define NST 3

template<int MF>
__global__ __launch_bounds__(256) void gemm_f16_kernel(
    const __half* __restrict__ A, const __half* __restrict__ W,
    const float* __restrict__ bias, float* C, __half* Ch,
    int M, int N, int K, int relu,
    const __half* __restrict__ W2 = nullptr,
    const float* __restrict__ bias2 = nullptr,
    float* C2 = nullptr, __half* C2h = nullptr)
{
    __shared__ __align__(16) __half As[NST][64 * MF][KP];
    __shared__ __align__(16) __half Ws[NST][64][KP];

    const int tid = threadIdx.x;
    const int lane = tid & 31;
    const int w = tid >> 5;
    const int wm = w & 3;
    const int wn = w >> 2;
    const int g = lane >> 2;
    const int t = lane & 3;

    int bx = blockIdx.x;
    const int nblk = N / 64;
    if (W2 != nullptr && bx >= nblk) {
        bx -= nblk;
        W = W2; bias = bias2; C = C2; Ch = C2h;
    }

    const int m0 = blockIdx.y * (64 * MF);
    const int n0 = bx * 64;

    const int nsplit = gridDim.z;
    const int Klen = K / nsplit;
    const int kstart = blockIdx.z * Klen;
    float* Cout = (C && nsplit > 1) ? (C + (size_t)blockIdx.z * M * N) : C;

    const uint32_t as_base = (uint32_t)__cvta_generic_to_shared(&As[0][0][0]);
    const uint32_t ws_base = (uint32_t)__cvta_generic_to_shared(&Ws[0][0][0]);

    float acc[MF][4][4];
    #pragma unroll
    for (int i = 0; i < MF; i++)
        #pragma unroll
        for (int j = 0; j < 4; j++)
            #pragma unroll
            for (int e = 0; e < 4; e++) acc[i][j][e] = 0.f;

    const int m_warp = wm * (16 * MF);
    const int n_warp = wn * 32;
    const int nIter = Klen / 32;

    const int lr8 = lane & 7;
    const int lb1 = (lane >> 3) & 1;
    const int lb2 = (lane >> 4) & 1;
    uint32_t aAddr[MF];
    #pragma unroll
    for (int mi = 0; mi < MF; mi++) {
        int row = m_warp + mi * 16 + lr8 + lb1 * 8;
        aAddr[mi] = as_base + (row * KP + lb2 * 8) * 2;
    }
    uint32_t bAddr[2];
    #pragma unroll
    for (int p = 0; p < 2; p++) {
        int row = n_warp + p * 16 + lb2 * 8 + lr8;
        bAddr[p] = ws_base + (row * KP + lb1 * 8) * 2;
    }
    const uint32_t aStride = (64 * MF) * KP * 2;
    const uint32_t bStride = 64 * KP * 2;

    auto load_stage = [&](int st, int it) {
        const int kg = kstart + it * 32;
        if (MF == 2) {
            #pragma unroll
            for (int s = 0; s < 2; s++) {
                int idx = tid + s * 256;
                int r = idx >> 2, kc = (idx & 3) * 8;
                int arow = m0 + r;
                uint32_t dst = as_base + ((st * 128 + r) * KP + kc) * 2;
                cp16(dst, A + (size_t)arow * K + kg + kc, (arow < M) ? 16 : 0);
            }
            {
                int r = tid >> 2, kc = (tid & 3) * 8;
                uint32_t dst = ws_base + ((st * 64 + r) * KP + kc) * 2;
                cp16(dst, W + (size_t)(n0 + r) * K + kg + kc, 16);
            }
        } else {
            int r = tid >> 2, kc = (tid & 3) * 8;
            int arow = m0 + r;
            uint32_t dst = as_base + ((st * 64 + r) * KP + kc) * 2;
            cp16(dst, A + (size_t)arow * K + kg + kc, (arow < M) ? 16 : 0);
            uint32_t dst2 = ws_base + ((st * 64 + r) * KP + kc) * 2;
            cp16(dst2, W + (size_t)(n0 + r) * K + kg + kc, 16);
        }
        cp_commit();
    };

    load_stage(0, 0);
    load_stage(1, 1);

    for (int it = 0; it < nIter; it++) {
        cp_wait<NST - 2>();
        __syncthreads();
        if (it + NST - 1 < nIter) load_stage((it + NST - 1) % NST, it + NST - 1);
        else cp_commit();

        const int st = it % NST;
        #pragma unroll
        for (int kk = 0; kk < 32; kk += 16) {
            uint32_t b0[4], b1[4];
            ldsm4(b0[0], b1[0], b0[1], b1[1], bAddr[0] + st * bStride + kk * 2);
            ldsm4(b0[2], b1[2], b0[3], b1[3], bAddr[1] + st * bStride + kk * 2);
            #pragma unroll
            for (int mi = 0; mi < MF; mi++) {
                uint32_t a0, a1, a2, a3;
                ldsm4(a0, a1, a2, a3, aAddr[mi] + st * aStride + kk * 2);
                #pragma unroll
                for (int ni = 0; ni < 4; ni++)
                    mma16h(acc[mi][ni], a0, a1, a2, a3, b0[ni], b1[ni]);
            }
        }
    }

    #pragma unroll
    for (int mi = 0; mi < MF; mi++) {
        #pragma unroll
        for (int ni = 0; ni < 4; ni++) {
            int col = n0 + n_warp + ni * 8 + 2 * t;
            float bz0 = 0.f, bz1 = 0.f;
            if (nsplit == 1) { bz0 = bias[col]; bz1 = bias[col + 1]; }
            int r0 = m0 + m_warp + mi * 16 + g;
            int r1 = r0 + 8;
            float v0 = acc[mi][ni][0] + bz0, v1 = acc[mi][ni][1] + bz1;
            float v2 = acc[mi][ni][2] + bz0, v3 = acc[mi][ni][3] + bz1;
            if (relu) {
                v0 = fmaxf(v0, 0.f); v1 = fmaxf(v1, 0.f);
                v2 = fmaxf(v2, 0.f); v3 = fmaxf(v3, 0.f);
            }
            if (Cout) {
                if (r0 < M) *reinterpret_cast<float2*>(Cout + (size_t)r0 * N + col) = make_float2(v0, v1);
                if (r1 < M) *reinterpret_cast<float2*>(Cout + (size_t)r1 * N + col) = make_float2(v2, v3);
            }
            if (Ch) {
                if (r0 < M) {
                    uint32_t hv = h2bits(v0, v1);
                    *reinterpret_cast<uint32_t*>(Ch + (size_t)r0 * N + col) = hv;
                }
                if (r1 < M) {
                    uint32_t hv = h2bits(v2, v3);
                    *reinterpret_cast<uint32_t*>(Ch + (size_t)r1 * N + col) = hv;
                }
            }
        }
    }
}

// ---------------- warp-per-row LayerNorm core ----------------
__device__ __forceinline__ void lnw_finish(
    float v[8], int lane, const float* g, const float* bt,
    float* out, __half* outh, size_t row)
{
    float s1 = 0.f, s2 = 0.f;
    #pragma unroll
    for (int i = 0; i < 8; i++) { s1 += v[i]; s2 += v[i] * v[i]; }
    #pragma unroll
    for (int o = 16; o > 0; o >>= 1) {
        s1 += __shfl_xor_sync(0xffffffffu, s1, o);
        s2 += __shfl_xor_sync(0xffffffffu, s2, o);
    }
    float mean = s1 * (1.f / DD);
    float var = s2 * (1.f / DD) - mean * mean;
    float rstd = rsqrtf(var + 1e-5f);
    int c0 = lane * 8;
    float r[8];
    #pragma unroll
    for (int i = 0; i < 8; i++)
        r[i] = (v[i] - mean) * rstd * g[c0 + i] + bt[c0 + i];
    if (out) {
        *reinterpret_cast<float4*>(out + row * DD + c0) = make_float4(r[0], r[1], r[2], r[3]);
        *reinterpret_cast<float4*>(out + row * DD + c0 + 4) = make_float4(r[4], r[5], r[6], r[7]);
    }
    if (outh) {
        uint4 u;
        u.x = h2bits(r[0], r[1]);
        u.y = h2bits(r[2], r[3]);
        u.z = h2bits(r[4], r[5]);
        u.w = h2bits(r[6], r[7]);
        *reinterpret_cast<uint4*>(outh + row * DD + c0) = u;
    }
}

__global__ __launch_bounds__(256) void ln_split_kernel(
    const float* __restrict__ X, const float* __restrict__ parts,
    const float* __restrict__ fbias,
    const float* __restrict__ g, const float* __restrict__ bt,
    float* out, __half* outh, int nsplit)
{
    const int lane = threadIdx.x & 31;
    const size_t row = blockIdx.x * 8 + (threadIdx.x >> 5);
    const size_t stride = (size_t)BB * QQ * DD;
    int c0 = lane * 8;
    float v[8];
    float4 x0 = *reinterpret_cast<const float4*>(X + row * DD + c0);
    float4 x1 = *reinterpret_cast<const float4*>(X + row * DD + c0 + 4);
    float4 f0 = *reinterpret_cast<const float4*>(fbias + c0);
    float4 f1 = *reinterpret_cast<const float4*>(fbias + c0 + 4);
    v[0] = x0.x + f0.x; v[1] = x0.y + f0.y; v[2] = x0.z + f0.z; v[3] = x0.w + f0.w;
    v[4] = x1.x + f1.x; v[5] = x1.y + f1.y; v[6] = x1.z + f1.z; v[7] = x1.w + f1.w;
    for (int s = 0; s < nsplit; s++) {
        float4 p0 = *reinterpret_cast<const float4*>(parts + s * stride + row * DD + c0);
        float4 p1 = *reinterpret_cast<const float4*>(parts + s * stride + row * DD + c0 + 4);
        v[0] += p0.x; v[1] += p0.y; v[2] += p0.z; v[3] += p0.w;
        v[4] += p1.x; v[5] += p1.y; v[6] += p1.z; v[7] += p1.w;
    }
    lnw_finish(v, lane, g, bt, out, outh, row);
}

// ---------------- GASA geometric bias: block per (b,l) ----------------
__global__ __launch_bounds__(128) void gasa_bias_kernel(
    const float* __restrict__ qpos, const float* __restrict__ mpos,
    const float* __restrict__ w1, const float* __restrict__ b1,
    const float* __restrict__ w2, const float* __restrict__ b2,
    const float* __restrict__ betap, float* __restrict__ biasT)
{
    const int l = blockIdx.x;
    const int b = blockIdx.y;
    const int tid = threadIdx.x;

    __shared__ float sw1[KD], sb1[KD], sw2[KD], smp[3], sb2, sbeta;
    if (tid < KD) {
        sw1[tid] = w1[tid];
        sb1[tid] = b1[tid];
        sw2[tid] = w2[tid];
    }
    if (tid < 3) smp[tid] = mpos[((size_t)b * LL + l) * 3 + tid];
    if (tid == 3) sb2 = b2[0];
    if (tid == 4) sbeta = betap[0];
    __syncthreads();

    const float mx = smp[0], my = smp[1], mz = smp[2];
    const float bb2 = sb2, bet = sbeta;
    float* orow = biasT + ((size_t)b * LL + l) * QQ;

    for (int q = tid; q < QQ; q += 128) {
        const float* qp = qpos + ((size_t)b * QQ + q) * 3;
        float dx = qp[0] - mx, dy = qp[1] - my, dz = qp[2] - mz;
        float dist = sqrtf(fmaxf(dx * dx + dy * dy + dz * dz, 0.f));
        float s = 0.f;
        #pragma unroll
        for (int k = 0; k < KD; k++) {
            float h = fmaxf(dist * sw1[k] + sb1[k], 0.f);
            s += h * sw2[k];
        }
        s += bb2;
        s = fminf(fmaxf(s, -10.f), 0.f);
        orow[q] = s * bet;
    }
}

// ---------------- fp16 flash attention partials (fp16 Q/K/V I/O) ----------
__global__ __launch_bounds__(128) void attn_mma_kernel(
    const __half* __restrict__ Qp, int qstride,
    const __half* __restrict__ Kp, const __half* __restrict__ Vp, int kvstride,
    const float* __restrict__ biasT, int Lk, int S, int step,
    float* __restrict__ pm, float* __restrict__ pl, float* __restrict__ pacc,
    int useBias)
{
    const int b = blockIdx.z, h = blockIdx.y;
    const int sp = blockIdx.x / NQT;
    const int qt = blockIdx.x % NQT;
    const int tid = threadIdx.x;
    const int lane = tid & 31;
    const int warp = tid >> 5;
    const int g = lane >> 2;
    const int t = lane & 3;

    const int q0 = qt * 64 + warp * 16;
    const int qg  = q0 + g;
    const int qg8 = q0 + g + 8;
    const int qgc  = min(qg, QQ - 1);
    const int qg8c = min(qg8, QQ - 1);

    const int ls = sp * step;
    const int le = min(ls + step, Lk);

    // Q a-fragments: fp16 loads, scaled by SCALE via HMUL2
    uint32_t qa[2][4];
    {
        const uint32_t s2 = h2bits(SCALE, SCALE);
        const __half* q0p = Qp + ((size_t)(b * QQ + qgc)) * qstride + h * HD;
        const __half* q1p = Qp + ((size_t)(b * QQ + qg8c)) * qstride + h * HD;
        #pragma unroll
        for (int ks = 0; ks < 2; ks++) {
            int d = ks * 16 + 2 * t;
            qa[ks][0] = hmul2b(*reinterpret_cast<const uint32_t*>(q0p + d), s2);
            qa[ks][1] = hmul2b(*reinterpret_cast<const uint32_t*>(q1p + d), s2);
            qa[ks][2] = hmul2b(*reinterpret_cast<const uint32_t*>(q0p + d + 8), s2);
            qa[ks][3] = hmul2b(*reinterpret_cast<const uint32_t*>(q1p + d + 8), s2);
        }
    }

    __shared__ __align__(16) __half Kh[16][40];   // [key][d], 80B pitch
    __shared__ __align__(16) __half Vh[HD][24];   // [d][key], 48B pitch
    __shared__ float Bsm[16][68];

    float oacc[4][4];
    #pragma unroll
    for (int i = 0; i < 4; i++)
        #pragma unroll
        for (int j = 0; j < 4; j++) oacc[i][j] = 0.f;
    float om0 = -INFINITY, om1 = -INFINITY;
    float ol0 = 0.f, ol1 = 0.f;

    const int key_l = tid >> 3;
    const int d0 = (tid & 7) * 4;
    const int bq0 = (tid & 7) * 8;
    const bool qtail = (qt == NQT - 1);

    const uint32_t kh_base = (uint32_t)__cvta_generic_to_shared(&Kh[0][0]);
    const uint32_t vh_base = (uint32_t)__cvta_generic_to_shared(&Vh[0][0]);
    const int lr8 = lane & 7;
    const int lb1 = (lane >> 3) & 1;
    const int lb2 = (lane >> 4) & 1;
    const uint32_t kAddr = kh_base + ((lb2 * 8 + lr8) * 40 + lb1 * 8) * 2;
    uint32_t vAddr[2];
    #pragma unroll
    for (int p = 0; p < 2; p++)
        vAddr[p] = vh_base + ((p * 16 + lb2 * 8 + lr8) * 24 + lb1 * 8) * 2;

    uint2 kreg, vreg;
    float4 breg0, breg1;

    auto prefetch = [&](int l0) {
        int grow = b * Lk + min(l0 + key_l, Lk - 1);
        kreg = *reinterpret_cast<const uint2*>(
            Kp + (size_t)grow * kvstride + h * HD + d0);
        vreg = *reinterpret_cast<const uint2*>(
            Vp + (size_t)grow * kvstride + h * HD + d0);
        if (useBias) {
            const float* brow = biasT + ((size_t)(b * Lk + l0 + key_l)) * QQ
                                + qt * 64 + bq0;
            if (!qtail) {
                breg0 = *reinterpret_cast<const float4*>(brow);
                breg1 = *reinterpret_cast<const float4*>(brow + 4);
            } else {
                int qb = qt * 64 + bq0;
                float e[8];
                #pragma unroll
                for (int i = 0; i < 8; i++)
                    e[i] = (qb + i < QQ) ? brow[i] : 0.f;
                breg0 = make_float4(e[0], e[1], e[2], e[3]);
                breg1 = make_float4(e[4], e[5], e[6], e[7]);
            }
        }
    };

    prefetch(ls);

    for (int l0 = ls; l0 < le; l0 += 16) {
        __syncthreads();
        {
            // K: raw fp16 copy
            *reinterpret_cast<uint2*>(&Kh[key_l][d0]) = kreg;
            // V: fp16 transpose
            const __half* vh = reinterpret_cast<const __half*>(&vreg);
            Vh[d0 + 0][key_l] = vh[0];
            Vh[d0 + 1][key_l] = vh[1];
            Vh[d0 + 2][key_l] = vh[2];
            Vh[d0 + 3][key_l] = vh[3];
            if (useBias) {
                *reinterpret_cast<float4*>(&Bsm[key_l][bq0]) = breg0;
                *reinterpret_cast<float4*>(&Bsm[key_l][bq0 + 4]) = breg1;
            }
        }
        if (l0 + 16 < le) prefetch(l0 + 16);
        __syncthreads();

        // --- scores: S = Qs @ K^T ---
        float sc[2][4];
        sc[0][0] = sc[0][1] = sc[0][2] = sc[0][3] = 0.f;
        sc[1][0] = sc[1][1] = sc[1][2] = sc[1][3] = 0.f;
        #pragma unroll
        for (int ks = 0; ks < 2; ks++) {
            uint32_t r0, r1, r2, r3;
            ldsm4(r0, r1, r2, r3, kAddr + ks * 32);
            mma16h(sc[0], qa[ks][0], qa[ks][1], qa[ks][2], qa[ks][3], r0, r1);
            mma16h(sc[1], qa[ks][0], qa[ks][1], qa[ks][2], qa[ks][3], r2, r3);
        }

        // --- bias + key-bound mask ---
        #pragma unroll
        for (int nf = 0; nf < 2; nf++) {
            if (useBias) {
                int brow = nf * 8 + 2 * t;
                int c0 = warp * 16 + g;
                sc[nf][0] += Bsm[brow][c0];
                sc[nf][1] += Bsm[brow + 1][c0];
                sc[nf][2] += Bsm[brow][c0 + 8];
                sc[nf][3] += Bsm[brow + 1][c0 + 8];
            }
            int kc = l0 + nf * 8 + 2 * t;
            if (kc >= le)     { sc[nf][0] = -1e30f; sc[nf][2] = -1e30f; }
            if (kc + 1 >= le) { sc[nf][1] = -1e30f; sc[nf][3] = -1e30f; }
        }

        // --- row max + online rescale ---
        float mx0 = fmaxf(fmaxf(sc[0][0], sc[0][1]), fmaxf(sc[1][0], sc[1][1]));
        float mx1 = fmaxf(fmaxf(sc[0][2], sc[0][3]), fmaxf(sc[1][2], sc[1][3]));
        mx0 = fmaxf(mx0, __shfl_xor_sync(0xffffffffu, mx0, 1));
        mx0 = fmaxf(mx0, __shfl_xor_sync(0xffffffffu, mx0, 2));
        mx1 = fmaxf(mx1, __shfl_xor_sync(0xffffffffu, mx1, 1));
        mx1 = fmaxf(mx1, __shfl_xor_sync(0xffffffffu, mx1, 2));

        float nm0 = fmaxf(om0, mx0), nm1 = fmaxf(om1, mx1);
        float cr0 = __expf(om0 - nm0), cr1 = __expf(om1 - nm1);
        om0 = nm0; om1 = nm1;
        ol0 *= cr0; ol1 *= cr1;
        #pragma unroll
        for (int nd = 0; nd < 4; nd++) {
            oacc[nd][0] *= cr0; oacc[nd][1] *= cr0;
            oacc[nd][2] *= cr1; oacc[nd][3] *= cr1;
        }

        // --- P = exp(S - m) ---
        #pragma unroll
        for (int nf = 0; nf < 2; nf++) {
            sc[nf][0] = __expf(sc[nf][0] - nm0);
            sc[nf][1] = __expf(sc[nf][1] - nm0);
            sc[nf][2] = __expf(sc[nf][2] - nm1);
            sc[nf][3] = __expf(sc[nf][3] - nm1);
            ol0 += sc[nf][0] + sc[nf][1];
            ol1 += sc[nf][2] + sc[nf][3];
        }

        // --- PV: C-frag == A-frag (no transpose) ---
        uint32_t pa0 = h2bits(sc[0][0], sc[0][1]);
        uint32_t pa1 = h2bits(sc[0][2], sc[0][3]);
        uint32_t pa2 = h2bits(sc[1][0], sc[1][1]);
        uint32_t pa3 = h2bits(sc[1][2], sc[1][3]);
        uint32_t b0[4], b1[4];
        ldsm4(b0[0], b1[0], b0[1], b1[1], vAddr[0]);
        ldsm4(b0[2], b1[2], b0[3], b1[3], vAddr[1]);
        #pragma unroll
        for (int nd = 0; nd < 4; nd++)
            mma16h(oacc[nd], pa0, pa1, pa2, pa3, b0[nd], b1[nd]);
    }

    ol0 += __shfl_xor_sync(0xffffffffu, ol0, 1);
    ol0 += __shfl_xor_sync(0xffffffffu, ol0, 2);
    ol1 += __shfl_xor_sync(0xffffffffu, ol1, 1);
    ol1 += __shfl_xor_sync(0xffffffffu, ol1, 2);

    size_t pbase = ((size_t)((b * HH + h) * S + sp)) * QQ;
    if (qg < QQ) {
        if (t == 0) { pm[pbase + qg] = om0; pl[pbase + qg] = ol0; }
        float* ap = pacc + (pbase + qg) * HD;
        #pragma unroll
        for (int nd = 0; nd < 4; nd++)
            *reinterpret_cast<float2*>(ap + nd * 8 + 2 * t) =
                make_float2(oacc[nd][0], oacc[nd][1]);
    }
    if (qg8 < QQ) {
        if (t == 0) { pm[pbase + qg8] = om1; pl[pbase + qg8] = ol1; }
        float* ap = pacc + (pbase + qg8) * HD;
        #pragma unroll
        for (int nd = 0; nd < 4; nd++)
            *reinterpret_cast<float2*>(ap + nd * 8 + 2 * t) =
                make_float2(oacc[nd][2], oacc[nd][3]);
    }
}

// ---------------- split combine (writes fp16 for GEMM consumption) --------
__global__ __launch_bounds__(256) void attn_combine_kernel(
    const float* __restrict__ pm, const float* __restrict__ pl,
    const float* __restrict__ pacc, int S, __half* __restrict__ out)
{
    int tt = blockIdx.x * 256 + threadIdx.x;
    if (tt >= BB * HH * QQ * (HD / 2)) return;
    int dp = tt & (HD / 2 - 1);
    int idx = tt >> 4;
    int q = idx % QQ;
    int bh = idx / QQ;
    int b = bh / HH, h = bh % HH;

    float mg = -INFINITY;
    for (int s = 0; s < S; s++)
        mg = fmaxf(mg, pm[((size_t)bh * S + s) * QQ + q]);
    float Lsum = 0.f;
    float olo = 0.f, ohi = 0.f;
    for (int s = 0; s < S; s++) {
        size_t pidx = ((size_t)bh * S + s) * QQ + q;
        float w = __expf(pm[pidx] - mg);
        Lsum += pl[pidx] * w;
        float2 a = *reinterpret_cast<const float2*>(pacc + pidx * HD + 2 * dp);
        olo += w * a.x; ohi += w * a.y;
    }
    float inv = 1.f / Lsum;
    uint32_t hv = h2bits(olo * inv, ohi * inv);
    *reinterpret_cast<uint32_t*>(
        out + ((size_t)(b * QQ + q)) * DD + h * HD + 2 * dp) = hv;
}

// ---------------- host launcher ----------------
static inline int cdiv(int a, int b) { return (a + b - 1) / b; }

extern "C" void kernel_launch(void* const* d_in, const int* in_sizes, int n_in,
                              void* d_out, int out_size)
{
    const float* queries   = (const float*)d_in[0];
    const float* memory    = (const float*)d_in[1];
    const float* memory_pos= (const float*)d_in[2];
    const float* query_pos = (const float*)d_in[3];
    const float* sa_in_w   = (const float*)d_in[4];
    const float* sa_in_b   = (const float*)d_in[5];
    const float* sa_out_w  = (const float*)d_in[6];
    const float* sa_out_b  = (const float*)d_in[7];
    const float* norm1_g   = (const float*)d_in[8];
    const float* norm1_b   = (const float*)d_in[9];
    const float* q_w       = (const float*)d_in[10];
    const float* q_b       = (const float*)d_in[11];
    const float* k_w       = (const float*)d_in[12];
    const float* k_b       = (const float*)d_in[13];
    const float* v_w       = (const float*)d_in[14];
    const float* v_b       = (const float*)d_in[15];
    const float* o_w       = (const float*)d_in[16];
    const float* o_b       = (const float*)d_in[17];
    const float* norm2_g   = (const float*)d_in[18];
    const float* norm2_b   = (const float*)d_in[19];
    const float* beta      = (const float*)d_in[20];
    const float* dk_w1     = (const float*)d_in[21];
    const float* dk_b1     = (const float*)d_in[22];
    const float* dk_w2     = (const float*)d_in[23];
    const float* dk_b2     = (const float*)d_in[24];
    const float* ffn_w1    = (const float*)d_in[25];
    const float* ffn_b1    = (const float*)d_in[26];
    const float* ffn_w2    = (const float*)d_in[27];
    const float* ffn_b2    = (const float*)d_in[28];
    const float* norm3_g   = (const float*)d_in[29];
    const float* norm3_b   = (const float*)d_in[30];

    float *g_x1, *g_x2, *g_bias, *g_part, *g_pm, *g_pl, *g_pacc;
    cudaGetSymbolAddress((void**)&g_x1,   s_x1);
    cudaGetSymbolAddress((void**)&g_x2,   s_x2);
    cudaGetSymbolAddress((void**)&g_bias, s_bias);
    cudaGetSymbolAddress((void**)&g_part, s_part);
    cudaGetSymbolAddress((void**)&g_pm,   s_pm);
    cudaGetSymbolAddress((void**)&g_pl,   s_pl);
    cudaGetSymbolAddress((void**)&g_pacc, s_pacc);

    __half *hq, *hm, *h_siw, *h_sow, *h_qw, *h_kw, *h_vw, *h_ow,
           *h_fw1, *h_fw2, *hqkv, *hqx, *hkk, *hvv, *hsa, *hca,
           *hx1, *hx2, *hffn;
    cudaGetSymbolAddress((void**)&hq,    h_queries);
    cudaGetSymbolAddress((void**)&hm,    h_memory);
    cudaGetSymbolAddress((void**)&h_siw, h_sa_in_w);
    cudaGetSymbolAddress((void**)&h_sow, h_sa_out_w);
    cudaGetSymbolAddress((void**)&h_qw,  h_q_w);
    cudaGetSymbolAddress((void**)&h_kw,  h_k_w);
    cudaGetSymbolAddress((void**)&h_vw,  h_v_w);
    cudaGetSymbolAddress((void**)&h_ow,  h_o_w);
    cudaGetSymbolAddress((void**)&h_fw1, h_ffn_w1);
    cudaGetSymbolAddress((void**)&h_fw2, h_ffn_w2);
    cudaGetSymbolAddress((void**)&hqkv,  h_qkv);
    cudaGetSymbolAddress((void**)&hqx,   h_qx);
    cudaGetSymbolAddress((void**)&hkk,   h_kk);
    cudaGetSymbolAddress((void**)&hvv,   h_vv);
    cudaGetSymbolAddress((void**)&hsa,   h_sa);
    cudaGetSymbolAddress((void**)&hca,   h_ca);
    cudaGetSymbolAddress((void**)&hx1,   h_x1);
    cudaGetSymbolAddress((void**)&hx2,   h_x2);
    cudaGetSymbolAddress((void**)&hffn,  h_ffn);

    static cudaStream_t st2 = nullptr, st3 = nullptr, st4 = nullptr;
    static cudaEvent_t ev0 = nullptr, ev2 = nullptr, ev3 = nullptr,
                       ev4 = nullptr, ev5 = nullptr;
    if (st2 == nullptr) {
        cudaStreamCreateWithFlags(&st2, cudaStreamNonBlocking);
        cudaStreamCreateWithFlags(&st3, cudaStreamNonBlocking);
        cudaStreamCreateWithFlags(&st4, cudaStreamNonBlocking);
        cudaEventCreateWithFlags(&ev0, cudaEventDisableTiming);
        cudaEventCreateWithFlags(&ev2, cudaEventDisableTiming);
        cudaEventCreateWithFlags(&ev3, cudaEventDisableTiming);
        cudaEventCreateWithFlags(&ev4, cudaEventDisableTiming);
        cudaEventCreateWithFlags(&ev5, cudaEventDisableTiming);
    }

    const int Mq = BB * QQ;   // 2400
    const int Mm = BB * LL;   // 8192
    const int NCOMB = BB * HH * QQ * (HD / 2);

    auto conv = [](const float* s, __half* d, int n, cudaStream_t st) {
        f2h_kernel<<<cdiv(n / 8, 256), 256, 0, st>>>(s, d, n);
    };

    // ---- fork ----
    cudaEventRecord(ev0, 0);
    cudaStreamWaitEvent(st2, ev0, 0);
    cudaStreamWaitEvent(st3, ev0, 0);
    cudaStreamWaitEvent(st4, ev0, 0);

    // st2: memory + KV weights conversion, then fused KV GEMM (fp16 out)
    conv(memory, hm, Mm * DD, st2);
    conv(k_w, h_kw, DD * DD, st2);
    conv(v_w, h_vw, DD * DD, st2);
    gemm_f16_kernel<2><<<dim3(2 * DD / 64, cdiv(Mm, 128), 1), 256, 0, st2>>>(
        hm, h_kw, k_b, nullptr, hkk, Mm, DD, DD, 0, h_vw, v_b, nullptr, hvv);
    cudaEventRecord(ev2, st2);

    // st3: GASA bias
    gasa_bias_kernel<<<dim3(LL, BB), 128, 0, st3>>>(
        query_pos, memory_pos, dk_w1, dk_b1, dk_w2, dk_b2, beta, g_bias);
    cudaEventRecord(ev3, st3);

    // st4: sa_in_w first, then fused remaining weights
    conv(sa_in_w, h_siw, 3 * DD * DD, st4);
    cudaEventRecord(ev5, st4);
    {
        int total = 3 * WSEG + 2 * WF;
        f2h_weights_kernel<<<cdiv(total / 8, 256), 256, 0, st4>>>(
            sa_out_w, q_w, o_w, ffn_w1, ffn_w2,
            h_sow, h_qw, h_ow, h_fw1, h_fw2);
    }
    cudaEventRecord(ev4, st4);

    // ---- main chain ----
    conv(queries, hq, Mq * DD, 0);
    cudaStreamWaitEvent(0, ev5, 0);

    // 1) self-attn packed in-proj -> fp16 qkv
    gemm_f16_kernel<2><<<dim3(3 * DD / 64, cdiv(Mq, 128), 1), 256>>>(
        hq, h_siw, sa_in_b, nullptr, hqkv, Mq, 3 * DD, DD, 0);

    // 2) self-attention, split S=2 -> combine -> h_sa (fp16)
    {
        int S = 2, step = cdiv(QQ, S * 16) * 16;   // 304
        attn_mma_kernel<<<dim3(NQT * S, HH, BB), 128>>>(
            hqkv, 3 * DD, hqkv + DD, hqkv + 2 * DD, 3 * DD,
            nullptr, QQ, S, step, g_pm, g_pl, g_pacc, 0);
        attn_combine_kernel<<<cdiv(NCOMB, 256), 256>>>(g_pm, g_pl, g_pacc, S, hsa);
    }

    cudaStreamWaitEvent(0, ev4, 0);

    // 3) SA out-proj split-K=2 + LN1 (x1 fp32 + fp16)
    gemm_f16_kernel<1><<<dim3(DD / 64, cdiv(Mq, 64), 2), 256>>>(
        hsa, h_sow, sa_out_b, g_part, nullptr, Mq, DD, DD, 0);
    ln_split_kernel<<<Mq / 8, 256>>>(queries, g_part, sa_out_b,
                                     norm1_g, norm1_b, g_x1, hx1, 2);

    // 4) Q projection -> fp16
    gemm_f16_kernel<1><<<dim3(DD / 64, cdiv(Mq, 64), 1), 256>>>(
        hx1, h_qw, q_b, nullptr, hqx, Mq, DD, DD, 0);

    cudaStreamWaitEvent(0, ev2, 0);
    cudaStreamWaitEvent(0, ev3, 0);

    // 5) cross-attention, split S=4 -> combine -> h_ca (fp16)
    {
        int S = 4, step = cdiv(LL, S * 16) * 16;
        attn_mma_kernel<<<dim3(NQT * S, HH, BB), 128>>>(
            hqx, DD, hkk, hvv, DD, g_bias, LL, S, step,
            g_pm, g_pl, g_pacc, 1);
        attn_combine_kernel<<<cdiv(NCOMB, 256), 256>>>(g_pm, g_pl, g_pacc, S, hca);
    }

    // 6) O proj split-K=2 + LN2 (x2 fp32 + fp16)
    gemm_f16_kernel<1><<<dim3(DD / 64, cdiv(Mq, 64), 2), 256>>>(
        hca, h_ow, o_b, g_part, nullptr, Mq, DD, DD, 0);
    ln_split_kernel<<<Mq / 8, 256>>>(g_x1, g_part, o_b,
                                     norm2_g, norm2_b, g_x2, hx2, 2);

    // 7) FFN1 (relu) -> fp16 only
    gemm_f16_kernel<2><<<dim3(DFF / 64, cdiv(Mq, 128), 1), 256>>>(
        hx2, h_fw1, ffn_b1, nullptr, hffn, Mq, DFF, DD, 1);

    // 8) FFN2 split-K=4 partials + fused combine in LN3 -> output
    gemm_f16_kernel<1><<<dim3(DD / 64, cdiv(Mq, 64), 4), 256>>>(
        hffn, h_fw2, ffn_b2, g_part, nullptr, Mq, DD, DFF, 0);
    ln_split_kernel<<<Mq / 8, 256>>>(g_x2, g_part, ffn_b2,
                                     norm3_g, norm3_b, (float*)d_out, nullptr, 4);
}

// round 14
// speedup vs baseline: 1.2483x; 1.0240x over previous
#include <cuda_runtime.h>
#include <cuda_fp16.h>
#include <math.h>
#include <stdint.h>

// ---------------- problem constants ----------------
#define BB 4
#define QQ 600
#define LL 2048
#define DD 256
#define HH 8
#define HD 32
#define DFF 2048
#define KD 32
#define SCALE 0.17677669529663687f   // 32^-0.5
#define NQT 10                       // ceil(600/64) 64-query tiles

typedef unsigned long long u64;

// ---------------- helpers ----------------
__device__ __forceinline__ void gdep_wait() {
    asm volatile("griddepcontrol.wait;" ::: "memory");
}
__device__ __forceinline__ void mma16h(float c[4], uint32_t a0, uint32_t a1,
                                       uint32_t a2, uint32_t a3,
                                       uint32_t b0, uint32_t b1) {
    asm("mma.sync.aligned.m16n8k16.row.col.f32.f16.f16.f32 "
        "{%0,%1,%2,%3},{%4,%5,%6,%7},{%8,%9},{%0,%1,%2,%3};"
        : "+f"(c[0]), "+f"(c[1]), "+f"(c[2]), "+f"(c[3])
        : "r"(a0), "r"(a1), "r"(a2), "r"(a3), "r"(b0), "r"(b1));
}
__device__ __forceinline__ void ldsm4(uint32_t& r0, uint32_t& r1,
                                      uint32_t& r2, uint32_t& r3, uint32_t addr) {
    asm volatile("ldmatrix.sync.aligned.m8n8.x4.shared.b16 {%0,%1,%2,%3}, [%4];"
                 : "=r"(r0), "=r"(r1), "=r"(r2), "=r"(r3) : "r"(addr));
}
__device__ __forceinline__ void cp16(uint32_t dst, const void* src, int srcsize) {
    asm volatile("cp.async.ca.shared.global [%0], [%1], 16, %2;"
                 :: "r"(dst), "l"(src), "r"(srcsize));
}
__device__ __forceinline__ void cp_commit() {
    asm volatile("cp.async.commit_group;");
}
template<int N>
__device__ __forceinline__ void cp_wait() {
    asm volatile("cp.async.wait_group %0;" :: "n"(N));
}
__device__ __forceinline__ uint32_t h2bits(float lo, float hi) {
    __half2 h = __floats2half2_rn(lo, hi);
    return *reinterpret_cast<uint32_t*>(&h);
}
__device__ __forceinline__ uint32_t hmul2b(uint32_t a, uint32_t b) {
    __half2 x = *reinterpret_cast<__half2*>(&a);
    __half2 y = *reinterpret_cast<__half2*>(&b);
    __half2 r = __hmul2(x, y);
    return *reinterpret_cast<uint32_t*>(&r);
}

// ---------------- scratch (device globals) ----------------
__device__ float s_x1  [BB*QQ*DD];
__device__ float s_x2  [BB*QQ*DD];
__device__ float s_bias[BB*LL*QQ];
__device__ float s_part[4*BB*QQ*DD];
__device__ float s_pm  [BB*HH*8*QQ];
__device__ float s_pl  [BB*HH*8*QQ];
__device__ float s_pacc[BB*HH*8*QQ*HD];
// fp16 tensors
__device__ __half h_queries[BB*QQ*DD];
__device__ __half h_memory [BB*LL*DD];
__device__ __half h_sa_in_w[3*DD*DD];
__device__ __half h_sa_out_w[DD*DD];
__device__ __half h_q_w[DD*DD];
__device__ __half h_k_w[DD*DD];
__device__ __half h_v_w[DD*DD];
__device__ __half h_o_w[DD*DD];
__device__ __half h_ffn_w1[DFF*DD];
__device__ __half h_ffn_w2[DD*DFF];
__device__ __half h_qkv[BB*QQ*3*DD];
__device__ __half h_qx [BB*QQ*DD];
__device__ __half h_kk [BB*LL*DD];
__device__ __half h_vv [BB*LL*DD];
__device__ __half h_sa [BB*QQ*DD];
__device__ __half h_ca [BB*QQ*DD];
__device__ __half h_x1 [BB*QQ*DD];
__device__ __half h_x2 [BB*QQ*DD];
__device__ __half h_ffn[BB*QQ*DFF];

// ---------------- fp32 -> fp16 convert (8 elts/thread) ----------------
__device__ __forceinline__ void conv8(const float* src, __half* dst, int i) {
    float4 x0 = *reinterpret_cast<const float4*>(src + i);
    float4 x1 = *reinterpret_cast<const float4*>(src + i + 4);
    uint4 u;
    u.x = h2bits(x0.x, x0.y);
    u.y = h2bits(x0.z, x0.w);
    u.z = h2bits(x1.x, x1.y);
    u.w = h2bits(x1.z, x1.w);
    *reinterpret_cast<uint4*>(dst + i) = u;
}

__global__ __launch_bounds__(256) void f2h_kernel(
    const float* __restrict__ src, __half* __restrict__ dst, int n)
{
    gdep_wait();
    int i = (blockIdx.x * 256 + threadIdx.x) * 8;
    if (i >= n) return;
    conv8(src, dst, i);
}

// fused 6-way conversion: queries + sa_in_w first (ev5 chunk handled by order)
#define WSEG (DD * DD)
#define WF   (DFF * DD)
__global__ __launch_bounds__(256) void f2h_weights_kernel(
    const float* __restrict__ sow, const float* __restrict__ qw,
    const float* __restrict__ ow, const float* __restrict__ fw1,
    const float* __restrict__ fw2,
    __half* __restrict__ hsow, __half* __restrict__ hqw,
    __half* __restrict__ how, __half* __restrict__ hfw1,
    __half* __restrict__ hfw2)
{
    gdep_wait();
    int i = (blockIdx.x * 256 + threadIdx.x) * 8;
    if (i < WSEG) { conv8(sow, hsow, i); return; }
    i -= WSEG;
    if (i < WSEG) { conv8(qw, hqw, i); return; }
    i -= WSEG;
    if (i < WSEG) { conv8(ow, how, i); return; }
    i -= WSEG;
    if (i < WF) { conv8(fw1, hfw1, i); return; }
    i -= WF;
    if (i < WF) conv8(fw2, hfw2, i);
}

// ---------------- FP16 tensor-core GEMM (cp.async + ldmatrix, 32k stages) --
#define KP 40
#define NST 3

template<int MF>
__global__ __launch_bounds__(256) void gemm_f16_kernel(
    const __half* __restrict__ A, const __half* __restrict__ W,
    const float* __restrict__ bias, float* C, __half* Ch,
    int M, int N, int K, int relu,
    const __half* __restrict__ W2,
    const float* __restrict__ bias2,
    float* C2, __half* C2h)
{
    __shared__ __align__(16) __half As[NST][64 * MF][KP];
    __shared__ __align__(16) __half Ws[NST][64][KP];

    const int tid = threadIdx.x;
    const int lane = tid & 31;
    const int w = tid >> 5;
    const int wm = w & 3;
    const int wn = w >> 2;
    const int g = lane >> 2;
    const int t = lane & 3;

    int bx = blockIdx.x;
    const int nblk = N / 64;
    if (W2 != nullptr && bx >= nblk) {
        bx -= nblk;
        W = W2; bias = bias2; C = C2; Ch = C2h;
    }

    const int m0 = blockIdx.y * (64 * MF);
    const int n0 = bx * 64;

    const int nsplit = gridDim.z;
    const int Klen = K / nsplit;
    const int kstart = blockIdx.z * Klen;
    float* Cout = (C && nsplit > 1) ? (C + (size_t)blockIdx.z * M * N) : C;

    const uint32_t as_base = (uint32_t)__cvta_generic_to_shared(&As[0][0][0]);
    const uint32_t ws_base = (uint32_t)__cvta_generic_to_shared(&Ws[0][0][0]);

    float acc[MF][4][4];
    #pragma unroll
    for (int i = 0; i < MF; i++)
        #pragma unroll
        for (int j = 0; j < 4; j++)
            #pragma unroll
            for (int e = 0; e < 4; e++) acc[i][j][e] = 0.f;

    const int m_warp = wm * (16 * MF);
    const int n_warp = wn * 32;
    const int nIter = Klen / 32;

    const int lr8 = lane & 7;
    const int lb1 = (lane >> 3) & 1;
    const int lb2 = (lane >> 4) & 1;
    uint32_t aAddr[MF];
    #pragma unroll
    for (int mi = 0; mi < MF; mi++) {
        int row = m_warp + mi * 16 + lr8 + lb1 * 8;
        aAddr[mi] = as_base + (row * KP + lb2 * 8) * 2;
    }
    uint32_t bAddr[2];
    #pragma unroll
    for (int p = 0; p < 2; p++) {
        int row = n_warp + p * 16 + lb2 * 8 + lr8;
        bAddr[p] = ws_base + (row * KP + lb1 * 8) * 2;
    }
    const uint32_t aStride = (64 * MF) * KP * 2;
    const uint32_t bStride = 64 * KP * 2;

    auto load_stage = [&](int st, int it) {
        const int kg = kstart + it * 32;
        if (MF == 2) {
            #pragma unroll
            for (int s = 0; s < 2; s++) {
                int idx = tid + s * 256;
                int r = idx >> 2, kc = (idx & 3) * 8;
                int arow = m0 + r;
                uint32_t dst = as_base + ((st * 128 + r) * KP + kc) * 2;
                cp16(dst, A + (size_t)arow * K + kg + kc, (arow < M) ? 16 : 0);
            }
            {
                int r = tid >> 2, kc = (tid & 3) * 8;
                uint32_t dst = ws_base + ((st * 64 + r) * KP + kc) * 2;
                cp16(dst, W + (size_t)(n0 + r) * K + kg + kc, 16);
            }
        } else {
            int r = tid >> 2, kc = (tid & 3) * 8;
            int arow = m0 + r;
            uint32_t dst = as_base + ((st * 64 + r) * KP + kc) * 2;
            cp16(dst, A + (size_t)arow * K + kg + kc, (arow < M) ? 16 : 0);
            uint32_t dst2 = ws_base + ((st * 64 + r) * KP + kc) * 2;
            cp16(dst2, W + (size_t)(n0 + r) * K + kg + kc, 16);
        }
        cp_commit();
    };

    gdep_wait();           // PDL: producer done; safe to read A/W
    load_stage(0, 0);
    load_stage(1, 1);

    for (int it = 0; it < nIter; it++) {
        cp_wait<NST - 2>();
        __syncthreads();
        if (it + NST - 1 < nIter) load_stage((it + NST - 1) % NST, it + NST - 1);
        else cp_commit();

        const int st = it % NST;
        #pragma unroll
        for (int kk = 0; kk < 32; kk += 16) {
            uint32_t b0[4], b1[4];
            ldsm4(b0[0], b1[0], b0[1], b1[1], bAddr[0] + st * bStride + kk * 2);
            ldsm4(b0[2], b1[2], b0[3], b1[3], bAddr[1] + st * bStride + kk * 2);
            #pragma unroll
            for (int mi = 0; mi < MF; mi++) {
                uint32_t a0, a1, a2, a3;
                ldsm4(a0, a1, a2, a3, aAddr[mi] + st * aStride + kk * 2);
                #pragma unroll
                for (int ni = 0; ni < 4; ni++)
                    mma16h(acc[mi][ni], a0, a1, a2, a3, b0[ni], b1[ni]);
            }
        }
    }

    #pragma unroll
    for (int mi = 0; mi < MF; mi++) {
        #pragma unroll
        for (int ni = 0; ni < 4; ni++) {
            int col = n0 + n_warp + ni * 8 + 2 * t;
            float bz0 = 0.f, bz1 = 0.f;
            if (nsplit == 1) { bz0 = bias[col]; bz1 = bias[col + 1]; }
            int r0 = m0 + m_warp + mi * 16 + g;
            int r1 = r0 + 8;
            float v0 = acc[mi][ni][0] + bz0, v1 = acc[mi][ni][1] + bz1;
            float v2 = acc[mi][ni][2] + bz0, v3 = acc[mi][ni][3] + bz1;
            if (relu) {
                v0 = fmaxf(v0, 0.f); v1 = fmaxf(v1, 0.f);
                v2 = fmaxf(v2, 0.f); v3 = fmaxf(v3, 0.f);
            }
            if (Cout) {
                if (r0 < M) *reinterpret_cast<float2*>(Cout + (size_t)r0 * N + col) = make_float2(v0, v1);
                if (r1 < M) *reinterpret_cast<float2*>(Cout + (size_t)r1 * N + col) = make_float2(v2, v3);
            }
            if (Ch) {
                if (r0 < M) {
                    uint32_t hv = h2bits(v0, v1);
                    *reinterpret_cast<uint32_t*>(Ch + (size_t)r0 * N + col) = hv;
                }
                if (r1 < M) {
                    uint32_t hv = h2bits(v2, v3);
                    *reinterpret_cast<uint32_t*>(Ch + (size_t)r1 * N + col) = hv;
                }
            }
        }
    }
}

// ---------------- warp-per-row LayerNorm core ----------------
__device__ __forceinline__ void lnw_finish(
    float v[8], int lane, const float* g, const float* bt,
    float* out, __half* outh, size_t row)
{
    float s1 = 0.f, s2 = 0.f;
    #pragma unroll
    for (int i = 0; i < 8; i++) { s1 += v[i]; s2 += v[i] * v[i]; }
    #pragma unroll
    for (int o = 16; o > 0; o >>= 1) {
        s1 += __shfl_xor_sync(0xffffffffu, s1, o);
        s2 += __shfl_xor_sync(0xffffffffu, s2, o);
    }
    float mean = s1 * (1.f / DD);
    float var = s2 * (1.f / DD) - mean * mean;
    float rstd = rsqrtf(var + 1e-5f);
    int c0 = lane * 8;
    float r[8];
    #pragma unroll
    for (int i = 0; i < 8; i++)
        r[i] = (v[i] - mean) * rstd * g[c0 + i] + bt[c0 + i];
    if (out) {
        *reinterpret_cast<float4*>(out + row * DD + c0) = make_float4(r[0], r[1], r[2], r[3]);
        *reinterpret_cast<float4*>(out + row * DD + c0 + 4) = make_float4(r[4], r[5], r[6], r[7]);
    }
    if (outh) {
        uint4 u;
        u.x = h2bits(r[0], r[1]);
        u.y = h2bits(r[2], r[3]);
        u.z = h2bits(r[4], r[5]);
        u.w = h2bits(r[6], r[7]);
        *reinterpret_cast<uint4*>(outh + row * DD + c0) = u;
    }
}

__global__ __launch_bounds__(256) void ln_split_kernel(
    const float* __restrict__ X, const float* __restrict__ parts,
    const float* __restrict__ fbias,
    const float* __restrict__ g, const float* __restrict__ bt,
    float* out, __half* outh, int nsplit)
{
    gdep_wait();
    const int lane = threadIdx.x & 31;
    const size_t row = blockIdx.x * 8 + (threadIdx.x >> 5);
    const size_t stride = (size_t)BB * QQ * DD;
    int c0 = lane * 8;
    float v[8];
    float4 x0 = *reinterpret_cast<const float4*>(X + row * DD + c0);
    float4 x1 = *reinterpret_cast<const float4*>(X + row * DD + c0 + 4);
    float4 f0 = *reinterpret_cast<const float4*>(fbias + c0);
    float4 f1 = *reinterpret_cast<const float4*>(fbias + c0 + 4);
    v[0] = x0.x + f0.x; v[1] = x0.y + f0.y; v[2] = x0.z + f0.z; v[3] = x0.w + f0.w;
    v[4] = x1.x + f1.x; v[5] = x1.y + f1.y; v[6] = x1.z + f1.z; v[7] = x1.w + f1.w;
    for (int s = 0; s < nsplit; s++) {
        float4 p0 = *reinterpret_cast<const float4*>(parts + s * stride + row * DD + c0);
        float4 p1 = *reinterpret_cast<const float4*>(parts + s * stride + row * DD + c0 + 4);
        v[0] += p0.x; v[1] += p0.y; v[2] += p0.z; v[3] += p0.w;
        v[4] += p1.x; v[5] += p1.y; v[6] += p1.z; v[7] += p1.w;
    }
    lnw_finish(v, lane, g, bt, out, outh, row);
}

// ---------------- GASA geometric bias: block per (b,l) ----------------
__global__ __launch_bounds__(128) void gasa_bias_kernel(
    const float* __restrict__ qpos, const float* __restrict__ mpos,
    const float* __restrict__ w1, const float* __restrict__ b1,
    const float* __restrict__ w2, const float* __restrict__ b2,
    const float* __restrict__ betap, float* __restrict__ biasT)
{
    const int l = blockIdx.x;
    const int b = blockIdx.y;
    const int tid = threadIdx.x;

    __shared__ float sw1[KD], sb1[KD], sw2[KD], smp[3], sb2, sbeta;
    if (tid < KD) {
        sw1[tid] = w1[tid];
        sb1[tid] = b1[tid];
        sw2[tid] = w2[tid];
    }
    if (tid < 3) smp[tid] = mpos[((size_t)b * LL + l) * 3 + tid];
    if (tid == 3) sb2 = b2[0];
    if (tid == 4) sbeta = betap[0];
    __syncthreads();

    const float mx = smp[0], my = smp[1], mz = smp[2];
    const float bb2 = sb2, bet = sbeta;
    float* orow = biasT + ((size_t)b * LL + l) * QQ;

    for (int q = tid; q < QQ; q += 128) {
        const float* qp = qpos + ((size_t)b * QQ + q) * 3;
        float dx = qp[0] - mx, dy = qp[1] - my, dz = qp[2] - mz;
        float dist = sqrtf(fmaxf(dx * dx + dy * dy + dz * dz, 0.f));
        float s = 0.f;
        #pragma unroll
        for (int k = 0; k < KD; k++) {
            float h = fmaxf(dist * sw1[k] + sb1[k], 0.f);
            s += h * sw2[k];
        }
        s += bb2;
        s = fminf(fmaxf(s, -10.f), 0.f);
        orow[q] = s * bet;
    }
}

// ---------------- fp16 flash attention partials (fp16 Q/K/V I/O) ----------
__global__ __launch_bounds__(128) void attn_mma_kernel(
    const __half* __restrict__ Qp, int qstride,
    const __half* __restrict__ Kp, const __half* __restrict__ Vp, int kvstride,
    const float* __restrict__ biasT, int Lk, int S, int step,
    float* __restrict__ pm, float* __restrict__ pl, float* __restrict__ pacc,
    int useBias)
{
    const int b = blockIdx.z, h = blockIdx.y;
    const int sp = blockIdx.x / NQT;
    const int qt = blockIdx.x % NQT;
    const int tid = threadIdx.x;
    const int lane = tid & 31;
    const int warp = tid >> 5;
    const int g = lane >> 2;
    const int t = lane & 3;

    const int q0 = qt * 64 + warp * 16;
    const int qg  = q0 + g;
    const int qg8 = q0 + g + 8;
    const int qgc  = min(qg, QQ - 1);
    const int qg8c = min(qg8, QQ - 1);

    const int ls = sp * step;
    const int le = min(ls + step, Lk);

    gdep_wait();

    // Q a-fragments: fp16 loads, scaled by SCALE via HMUL2
    uint32_t qa[2][4];
    {
        const uint32_t s2 = h2bits(SCALE, SCALE);
        const __half* q0p = Qp + ((size_t)(b * QQ + qgc)) * qstride + h * HD;
        const __half* q1p = Qp + ((size_t)(b * QQ + qg8c)) * qstride + h * HD;
        #pragma unroll
        for (int ks = 0; ks < 2; ks++) {
            int d = ks * 16 + 2 * t;
            qa[ks][0] = hmul2b(*reinterpret_cast<const uint32_t*>(q0p + d), s2);
            qa[ks][1] = hmul2b(*reinterpret_cast<const uint32_t*>(q1p + d), s2);
            qa[ks][2] = hmul2b(*reinterpret_cast<const uint32_t*>(q0p + d + 8), s2);
            qa[ks][3] = hmul2b(*reinterpret_cast<const uint32_t*>(q1p + d + 8), s2);
        }
    }

    __shared__ __align__(16) __half Kh[16][40];
    __shared__ __align__(16) __half Vh[HD][24];
    __shared__ float Bsm[16][68];

    float oacc[4][4];
    #pragma unroll
    for (int i = 0; i < 4; i++)
        #pragma unroll
        for (int j = 0; j < 4; j++) oacc[i][j] = 0.f;
    float om0 = -INFINITY, om1 = -INFINITY;
    float ol0 = 0.f, ol1 = 0.f;

    const int key_l = tid >> 3;
    const int d0 = (tid & 7) * 4;
    const int bq0 = (tid & 7) * 8;
    const bool qtail = (qt == NQT - 1);

    const uint32_t kh_base = (uint32_t)__cvta_generic_to_shared(&Kh[0][0]);
    const uint32_t vh_base = (uint32_t)__cvta_generic_to_shared(&Vh[0][0]);
    const int lr8 = lane & 7;
    const int lb1 = (lane >> 3) & 1;
    const int lb2 = (lane >> 4) & 1;
    const uint32_t kAddr = kh_base + ((lb2 * 8 + lr8) * 40 + lb1 * 8) * 2;
    uint32_t vAddr[2];
    #pragma unroll
    for (int p = 0; p < 2; p++)
        vAddr[p] = vh_base + ((p * 16 + lb2 * 8 + lr8) * 24 + lb1 * 8) * 2;

    uint2 kreg, vreg;
    float4 breg0, breg1;

    auto prefetch = [&](int l0) {
        int grow = b * Lk + min(l0 + key_l, Lk - 1);
        kreg = *reinterpret_cast<const uint2*>(
            Kp + (size_t)grow * kvstride + h * HD + d0);
        vreg = *reinterpret_cast<const uint2*>(
            Vp + (size_t)grow * kvstride + h * HD + d0);
        if (useBias) {
            const float* brow = biasT + ((size_t)(b * Lk + l0 + key_l)) * QQ
                                + qt * 64 + bq0;
            if (!qtail) {
                breg0 = *reinterpret_cast<const float4*>(brow);
                breg1 = *reinterpret_cast<const float4*>(brow + 4);
            } else {
                int qb = qt * 64 + bq0;
                float e[8];
                #pragma unroll
                for (int i = 0; i < 8; i++)
                    e[i] = (qb + i < QQ) ? brow[i] : 0.f;
                breg0 = make_float4(e[0], e[1], e[2], e[3]);
                breg1 = make_float4(e[4], e[5], e[6], e[7]);
            }
        }
    };

    prefetch(ls);

    for (int l0 = ls; l0 < le; l0 += 16) {
        __syncthreads();
        {
            *reinterpret_cast<uint2*>(&Kh[key_l][d0]) = kreg;
            const __half* vh = reinterpret_cast<const __half*>(&vreg);
            Vh[d0 + 0][key_l] = vh[0];
            Vh[d0 + 1][key_l] = vh[1];
            Vh[d0 + 2][key_l] = vh[2];
            Vh[d0 + 3][key_l] = vh[3];
            if (useBias) {
                *reinterpret_cast<float4*>(&Bsm[key_l][bq0]) = breg0;
                *reinterpret_cast<float4*>(&Bsm[key_l][bq0 + 4]) = breg1;
            }
        }
        if (l0 + 16 < le) prefetch(l0 + 16);
        __syncthreads();

        float sc[2][4];
        sc[0][0] = sc[0][1] = sc[0][2] = sc[0][3] = 0.f;
        sc[1][0] = sc[1][1] = sc[1][2] = sc[1][3] = 0.f;
        #pragma unroll
        for (int ks = 0; ks < 2; ks++) {
            uint32_t r0, r1, r2, r3;
            ldsm4(r0, r1, r2, r3, kAddr + ks * 32);
            mma16h(sc[0], qa[ks][0], qa[ks][1], qa[ks][2], qa[ks][3], r0, r1);
            mma16h(sc[1], qa[ks][0], qa[ks][1], qa[ks][2], qa[ks][3], r2, r3);
        }

        #pragma unroll
        for (int nf = 0; nf < 2; nf++) {
            if (useBias) {
                int brow = nf * 8 + 2 * t;
                int c0 = warp * 16 + g;
                sc[nf][0] += Bsm[brow][c0];
                sc[nf][1] += Bsm[brow + 1][c0];
                sc[nf][2] += Bsm[brow][c0 + 8];
                sc[nf][3] += Bsm[brow + 1][c0 + 8];
            }
            int kc = l0 + nf * 8 + 2 * t;
            if (kc >= le)     { sc[nf][0] = -1e30f; sc[nf][2] = -1e30f; }
            if (kc + 1 >= le) { sc[nf][1] = -1e30f; sc[nf][3] = -1e30f; }
        }

        float mx0 = fmaxf(fmaxf(sc[0][0], sc[0][1]), fmaxf(sc[1][0], sc[1][1]));
        float mx1 = fmaxf(fmaxf(sc[0][2], sc[0][3]), fmaxf(sc[1][2], sc[1][3]));
        mx0 = fmaxf(mx0, __shfl_xor_sync(0xffffffffu, mx0, 1));
        mx0 = fmaxf(mx0, __shfl_xor_sync(0xffffffffu, mx0, 2));
        mx1 = fmaxf(mx1, __shfl_xor_sync(0xffffffffu, mx1, 1));
        mx1 = fmaxf(mx1, __shfl_xor_sync(0xffffffffu, mx1, 2));

        float nm0 = fmaxf(om0, mx0), nm1 = fmaxf(om1, mx1);
        float cr0 = __expf(om0 - nm0), cr1 = __expf(om1 - nm1);
        om0 = nm0; om1 = nm1;
        ol0 *= cr0; ol1 *= cr1;
        #pragma unroll
        for (int nd = 0; nd < 4; nd++) {
            oacc[nd][0] *= cr0; oacc[nd][1] *= cr0;
            oacc[nd][2] *= cr1; oacc[nd][3] *= cr1;
        }

        #pragma unroll
        for (int nf = 0; nf < 2; nf++) {
            sc[nf][0] = __expf(sc[nf][0] - nm0);
            sc[nf][1] = __expf(sc[nf][1] - nm0);
            sc[nf][2] = __expf(sc[nf][2] - nm1);
            sc[nf][3] = __expf(sc[nf][3] - nm1);
            ol0 += sc[nf][0] + sc[nf][1];
            ol1 += sc[nf][2] + sc[nf][3];
        }

        uint32_t pa0 = h2bits(sc[0][0], sc[0][1]);
        uint32_t pa1 = h2bits(sc[0][2], sc[0][3]);
        uint32_t pa2 = h2bits(sc[1][0], sc[1][1]);
        uint32_t pa3 = h2bits(sc[1][2], sc[1][3]);
        uint32_t b0[4], b1[4];
        ldsm4(b0[0], b1[0], b0[1], b1[1], vAddr[0]);
        ldsm4(b0[2], b1[2], b0[3], b1[3], vAddr[1]);
        #pragma unroll
        for (int nd = 0; nd < 4; nd++)
            mma16h(oacc[nd], pa0, pa1, pa2, pa3, b0[nd], b1[nd]);
    }

    ol0 += __shfl_xor_sync(0xffffffffu, ol0, 1);
    ol0 += __shfl_xor_sync(0xffffffffu, ol0, 2);
    ol1 += __shfl_xor_sync(0xffffffffu, ol1, 1);
    ol1 += __shfl_xor_sync(0xffffffffu, ol1, 2);

    size_t pbase = ((size_t)((b * HH + h) * S + sp)) * QQ;
    if (qg < QQ) {
        if (t == 0) { pm[pbase + qg] = om0; pl[pbase + qg] = ol0; }
        float* ap = pacc + (pbase + qg) * HD;
        #pragma unroll
        for (int nd = 0; nd < 4; nd++)
            *reinterpret_cast<float2*>(ap + nd * 8 + 2 * t) =
                make_float2(oacc[nd][0], oacc[nd][1]);
    }
    if (qg8 < QQ) {
        if (t == 0) { pm[pbase + qg8] = om1; pl[pbase + qg8] = ol1; }
        float* ap = pacc + (pbase + qg8) * HD;
        #pragma unroll
        for (int nd = 0; nd < 4; nd++)
            *reinterpret_cast<float2*>(ap + nd * 8 + 2 * t) =
                make_float2(oacc[nd][2], oacc[nd][3]);
    }
}

// ---------------- split combine (writes fp16 for GEMM consumption) --------
__global__ __launch_bounds__(256) void attn_combine_kernel(
    const float* __restrict__ pm, const float* __restrict__ pl,
    const float* __restrict__ pacc, int S, __half* __restrict__ out)
{
    gdep_wait();
    int tt = blockIdx.x * 256 + threadIdx.x;
    if (tt >= BB * HH * QQ * (HD / 2)) return;
    int dp = tt & (HD / 2 - 1);
    int idx = tt >> 4;
    int q = idx % QQ;
    int bh = idx / QQ;
    int b = bh / HH, h = bh % HH;

    float mg = -INFINITY;
    for (int s = 0; s < S; s++)
        mg = fmaxf(mg, pm[((size_t)bh * S + s) * QQ + q]);
    float Lsum = 0.f;
    float olo = 0.f, ohi = 0.f;
    for (int s = 0; s < S; s++) {
        size_t pidx = ((size_t)bh * S + s) * QQ + q;
        float w = __expf(pm[pidx] - mg);
        Lsum += pl[pidx] * w;
        float2 a = *reinterpret_cast<const float2*>(pacc + pidx * HD + 2 * dp);
        olo += w * a.x; ohi += w * a.y;
    }
    float inv = 1.f / Lsum;
    uint32_t hv = h2bits(olo * inv, ohi * inv);
    *reinterpret_cast<uint32_t*>(
        out + ((size_t)(b * QQ + q)) * DD + h * HD + 2 * dp) = hv;
}

// ---------------- host launcher ----------------
static inline int cdiv(int a, int b) { return (a + b - 1) / b; }

template<typename F, typename... Args>
static inline void lpdl(F kernel, dim3 grid, dim3 block, cudaStream_t st,
                        Args... args)
{
    cudaLaunchConfig_t cfg = {};
    cfg.gridDim = grid;
    cfg.blockDim = block;
    cfg.dynamicSmemBytes = 0;
    cfg.stream = st;
    cudaLaunchAttribute attr[1];
    attr[0].id = cudaLaunchAttributeProgrammaticStreamSerialization;
    attr[0].val.programmaticStreamSerializationAllowed = 1;
    cfg.attrs = attr;
    cfg.numAttrs = 1;
    cudaLaunchKernelEx(&cfg, kernel, args...);
}

extern "C" void kernel_launch(void* const* d_in, const int* in_sizes, int n_in,
                              void* d_out, int out_size)
{
    const float* queries   = (const float*)d_in[0];
    const float* memory    = (const float*)d_in[1];
    const float* memory_pos= (const float*)d_in[2];
    const float* query_pos = (const float*)d_in[3];
    const float* sa_in_w   = (const float*)d_in[4];
    const float* sa_in_b   = (const float*)d_in[5];
    const float* sa_out_w  = (const float*)d_in[6];
    const float* sa_out_b  = (const float*)d_in[7];
    const float* norm1_g   = (const float*)d_in[8];
    const float* norm1_b   = (const float*)d_in[9];
    const float* q_w       = (const float*)d_in[10];
    const float* q_b       = (const float*)d_in[11];
    const float* k_w       = (const float*)d_in[12];
    const float* k_b       = (const float*)d_in[13];
    const float* v_w       = (const float*)d_in[14];
    const float* v_b       = (const float*)d_in[15];
    const float* o_w       = (const float*)d_in[16];
    const float* o_b       = (const float*)d_in[17];
    const float* norm2_g   = (const float*)d_in[18];
    const float* norm2_b   = (const float*)d_in[19];
    const float* beta      = (const float*)d_in[20];
    const float* dk_w1     = (const float*)d_in[21];
    const float* dk_b1     = (const float*)d_in[22];
    const float* dk_w2     = (const float*)d_in[23];
    const float* dk_b2     = (const float*)d_in[24];
    const float* ffn_w1    = (const float*)d_in[25];
    const float* ffn_b1    = (const float*)d_in[26];
    const float* ffn_w2    = (const float*)d_in[27];
    const float* ffn_b2    = (const float*)d_in[28];
    const float* norm3_g   = (const float*)d_in[29];
    const float* norm3_b   = (const float*)d_in[30];

    float *g_x1, *g_x2, *g_bias, *g_part, *g_pm, *g_pl, *g_pacc;
    cudaGetSymbolAddress((void**)&g_x1,   s_x1);
    cudaGetSymbolAddress((void**)&g_x2,   s_x2);
    cudaGetSymbolAddress((void**)&g_bias, s_bias);
    cudaGetSymbolAddress((void**)&g_part, s_part);
    cudaGetSymbolAddress((void**)&g_pm,   s_pm);
    cudaGetSymbolAddress((void**)&g_pl,   s_pl);
    cudaGetSymbolAddress((void**)&g_pacc, s_pacc);

    __half *hq, *hm, *h_siw, *h_sow, *h_qw, *h_kw, *h_vw, *h_ow,
           *h_fw1, *h_fw2, *hqkv, *hqx, *hkk, *hvv, *hsa, *hca,
           *hx1, *hx2, *hffn;
    cudaGetSymbolAddress((void**)&hq,    h_queries);
    cudaGetSymbolAddress((void**)&hm,    h_memory);
    cudaGetSymbolAddress((void**)&h_siw, h_sa_in_w);
    cudaGetSymbolAddress((void**)&h_sow, h_sa_out_w);
    cudaGetSymbolAddress((void**)&h_qw,  h_q_w);
    cudaGetSymbolAddress((void**)&h_kw,  h_k_w);
    cudaGetSymbolAddress((void**)&h_vw,  h_v_w);
    cudaGetSymbolAddress((void**)&h_ow,  h_o_w);
    cudaGetSymbolAddress((void**)&h_fw1, h_ffn_w1);
    cudaGetSymbolAddress((void**)&h_fw2, h_ffn_w2);
    cudaGetSymbolAddress((void**)&hqkv,  h_qkv);
    cudaGetSymbolAddress((void**)&hqx,   h_qx);
    cudaGetSymbolAddress((void**)&hkk,   h_kk);
    cudaGetSymbolAddress((void**)&hvv,   h_vv);
    cudaGetSymbolAddress((void**)&hsa,   h_sa);
    cudaGetSymbolAddress((void**)&hca,   h_ca);
    cudaGetSymbolAddress((void**)&hx1,   h_x1);
    cudaGetSymbolAddress((void**)&hx2,   h_x2);
    cudaGetSymbolAddress((void**)&hffn,  h_ffn);

    static cudaStream_t st2 = nullptr, st3 = nullptr, st4 = nullptr;
    static cudaEvent_t ev0 = nullptr, ev2 = nullptr, ev3 = nullptr,
                       ev4 = nullptr, ev5 = nullptr;
    if (st2 == nullptr) {
        cudaStreamCreateWithFlags(&st2, cudaStreamNonBlocking);
        cudaStreamCreateWithFlags(&st3, cudaStreamNonBlocking);
        cudaStreamCreateWithFlags(&st4, cudaStreamNonBlocking);
        cudaEventCreateWithFlags(&ev0, cudaEventDisableTiming);
        cudaEventCreateWithFlags(&ev2, cudaEventDisableTiming);
        cudaEventCreateWithFlags(&ev3, cudaEventDisableTiming);
        cudaEventCreateWithFlags(&ev4, cudaEventDisableTiming);
        cudaEventCreateWithFlags(&ev5, cudaEventDisableTiming);
    }

    const int Mq = BB * QQ;   // 2400
    const int Mm = BB * LL;   // 8192
    const int NCOMB = BB * HH * QQ * (HD / 2);

    // ---- fork ----
    cudaEventRecord(ev0, 0);
    cudaStreamWaitEvent(st2, ev0, 0);
    cudaStreamWaitEvent(st3, ev0, 0);
    cudaStreamWaitEvent(st4, ev0, 0);

    // st2: memory + KV weights conversion, then fused KV GEMM (fp16 out)
    lpdl(f2h_kernel, cdiv(Mm * DD / 8, 256), 256, st2, memory, hm, Mm * DD);
    lpdl(f2h_kernel, cdiv(WSEG / 8, 256), 256, st2, k_w, h_kw, WSEG);
    lpdl(f2h_kernel, cdiv(WSEG / 8, 256), 256, st2, v_w, h_vw, WSEG);
    lpdl(gemm_f16_kernel<2>, dim3(2 * DD / 64, cdiv(Mm, 128), 1), 256, st2,
         (const __half*)hm, (const __half*)h_kw, k_b, (float*)nullptr, hkk,
         Mm, DD, DD, 0,
         (const __half*)h_vw, v_b, (float*)nullptr, hvv);
    cudaEventRecord(ev2, st2);

    // st3: GASA bias
    lpdl(gasa_bias_kernel, dim3(LL, BB), 128, st3,
         query_pos, memory_pos, dk_w1, dk_b1, dk_w2, dk_b2, beta, g_bias);
    cudaEventRecord(ev3, st3);

    // st4: queries + sa_in_w first (critical for GEMM1), then rest
    lpdl(f2h_kernel, cdiv(Mq * DD / 8, 256), 256, st4, queries, hq, Mq * DD);
    lpdl(f2h_kernel, cdiv(3 * WSEG / 8, 256), 256, st4, sa_in_w, h_siw, 3 * WSEG);
    cudaEventRecord(ev5, st4);
    {
        int total = 3 * WSEG + 2 * WF;
        lpdl(f2h_weights_kernel, cdiv(total / 8, 256), 256, st4,
             sa_out_w, q_w, o_w, ffn_w1, ffn_w2,
             h_sow, h_qw, h_ow, h_fw1, h_fw2);
    }
    cudaEventRecord(ev4, st4);

    // ---- main chain (PDL-linked) ----
    cudaStreamWaitEvent(0, ev5, 0);

    // 1) self-attn packed in-proj -> fp16 qkv
    lpdl(gemm_f16_kernel<2>, dim3(3 * DD / 64, cdiv(Mq, 128), 1), 256, (cudaStream_t)0,
         (const __half*)hq, (const __half*)h_siw, sa_in_b, (float*)nullptr, hqkv,
         Mq, 3 * DD, DD, 0,
         (const __half*)nullptr, (const float*)nullptr, (float*)nullptr, (__half*)nullptr);

    // 2) self-attention, split S=2 -> combine -> h_sa (fp16)
    {
        int S = 2, step = cdiv(QQ, S * 16) * 16;   // 304
        lpdl(attn_mma_kernel, dim3(NQT * S, HH, BB), 128, (cudaStream_t)0,
             (const __half*)hqkv, 3 * DD,
             (const __half*)(hqkv + DD), (const __half*)(hqkv + 2 * DD), 3 * DD,
             (const float*)nullptr, QQ, S, step, g_pm, g_pl, g_pacc, 0);
        lpdl(attn_combine_kernel, cdiv(NCOMB, 256), 256, (cudaStream_t)0,
             (const float*)g_pm, (const float*)g_pl, (const float*)g_pacc, S, hsa);
    }

    cudaStreamWaitEvent(0, ev4, 0);

    // 3) SA out-proj split-K=2 + LN1 (x1 fp32 + fp16)
    lpdl(gemm_f16_kernel<1>, dim3(DD / 64, cdiv(Mq, 64), 2), 256, (cudaStream_t)0,
         (const __half*)hsa, (const __half*)h_sow, sa_out_b, g_part, (__half*)nullptr,
         Mq, DD, DD, 0,
         (const __half*)nullptr, (const float*)nullptr, (float*)nullptr, (__half*)nullptr);
    lpdl(ln_split_kernel, Mq / 8, 256, (cudaStream_t)0,
         queries, (const float*)g_part, sa_out_b, norm1_g, norm1_b,
         g_x1, hx1, 2);

    // 4) Q projection -> fp16
    lpdl(gemm_f16_kernel<1>, dim3(DD / 64, cdiv(Mq, 64), 1), 256, (cudaStream_t)0,
         (const __half*)hx1, (const __half*)h_qw, q_b, (float*)nullptr, hqx,
         Mq, DD, DD, 0,
         (const __half*)nullptr, (const float*)nullptr, (float*)nullptr, (__half*)nullptr);

    cudaStreamWaitEvent(0, ev2, 0);
    cudaStreamWaitEvent(0, ev3, 0);

    // 5) cross-attention, split S=4 -> combine -> h_ca (fp16)
    {
        int S = 4, step = cdiv(LL, S * 16) * 16;
        lpdl(attn_mma_kernel, dim3(NQT * S, HH, BB), 128, (cudaStream_t)0,
             (const __half*)hqx, DD, (const __half*)hkk, (const __half*)hvv, DD,
             (const float*)g_bias, LL, S, step, g_pm, g_pl, g_pacc, 1);
        lpdl(attn_combine_kernel, cdiv(NCOMB, 256), 256, (cudaStream_t)0,
             (const float*)g_pm, (const float*)g_pl, (const float*)g_pacc, S, hca);
    }

    // 6) O proj split-K=2 + LN2 (x2 fp32 + fp16)
    lpdl(gemm_f16_kernel<1>, dim3(DD / 64, cdiv(Mq, 64), 2), 256, (cudaStream_t)0,
         (const __half*)hca, (const __half*)h_ow, o_b, g_part, (__half*)nullptr,
         Mq, DD, DD, 0,
         (const __half*)nullptr, (const float*)nullptr, (float*)nullptr, (__half*)nullptr);
    lpdl(ln_split_kernel, Mq / 8, 256, (cudaStream_t)0,
         (const float*)g_x1, (const float*)g_part, o_b, norm2_g, norm2_b,
         g_x2, hx2, 2);

    // 7) FFN1 (relu) -> fp16 only
    lpdl(gemm_f16_kernel<2>, dim3(DFF / 64, cdiv(Mq, 128), 1), 256, (cudaStream_t)0,
         (const __half*)hx2, (const __half*)h_fw1, ffn_b1, (float*)nullptr, hffn,
         Mq, DFF, DD, 1,
         (const __half*)nullptr, (const float*)nullptr, (float*)nullptr, (__half*)nullptr);

    // 8) FFN2 split-K=4 partials + fused combine in LN3 -> output
    lpdl(gemm_f16_kernel<1>, dim3(DD / 64, cdiv(Mq, 64), 4), 256, (cudaStream_t)0,
         (const __half*)hffn, (const __half*)h_fw2, ffn_b2, g_part, (__half*)nullptr,
         Mq, DD, DFF, 0,
         (const __half*)nullptr, (const float*)nullptr, (float*)nullptr, (__half*)nullptr);
    lpdl(ln_split_kernel, Mq / 8, 256, (cudaStream_t)0,
         (const float*)g_x2, (const float*)g_part, ffn_b2, norm3_g, norm3_b,
         (float*)d_out, (__half*)nullptr, 4);
}

// round 15
// speedup vs baseline: 1.2812x; 1.0263x over previous
#include <cuda_runtime.h>
#include <cuda_fp16.h>
#include <math.h>
#include <stdint.h>

// ---------------- problem constants ----------------
#define BB 4
#define QQ 600
#define LL 2048
#define DD 256
#define HH 8
#define HD 32
#define DFF 2048
#define KD 32
#define SCALE 0.17677669529663687f   // 32^-0.5
#define NQT 10                       // ceil(600/64) 64-query tiles

typedef unsigned long long u64;

// ---------------- helpers ----------------
__device__ __forceinline__ void gdep_wait() {
    asm volatile("griddepcontrol.wait;" ::: "memory");
}
__device__ __forceinline__ void mma16h(float c[4], uint32_t a0, uint32_t a1,
                                       uint32_t a2, uint32_t a3,
                                       uint32_t b0, uint32_t b1) {
    asm("mma.sync.aligned.m16n8k16.row.col.f32.f16.f16.f32 "
        "{%0,%1,%2,%3},{%4,%5,%6,%7},{%8,%9},{%0,%1,%2,%3};"
        : "+f"(c[0]), "+f"(c[1]), "+f"(c[2]), "+f"(c[3])
        : "r"(a0), "r"(a1), "r"(a2), "r"(a3), "r"(b0), "r"(b1));
}
__device__ __forceinline__ void ldsm4(uint32_t& r0, uint32_t& r1,
                                      uint32_t& r2, uint32_t& r3, uint32_t addr) {
    asm volatile("ldmatrix.sync.aligned.m8n8.x4.shared.b16 {%0,%1,%2,%3}, [%4];"
                 : "=r"(r0), "=r"(r1), "=r"(r2), "=r"(r3) : "r"(addr));
}
__device__ __forceinline__ void cp16(uint32_t dst, const void* src, int srcsize) {
    asm volatile("cp.async.ca.shared.global [%0], [%1], 16, %2;"
                 :: "r"(dst), "l"(src), "r"(srcsize));
}
__device__ __forceinline__ void cp_commit() {
    asm volatile("cp.async.commit_group;");
}
template<int N>
__device__ __forceinline__ void cp_wait() {
    asm volatile("cp.async.wait_group %0;" :: "n"(N));
}
__device__ __forceinline__ uint32_t h2bits(float lo, float hi) {
    __half2 h = __floats2half2_rn(lo, hi);
    return *reinterpret_cast<uint32_t*>(&h);
}
__device__ __forceinline__ uint32_t hmul2b(uint32_t a, uint32_t b) {
    __half2 x = *reinterpret_cast<__half2*>(&a);
    __half2 y = *reinterpret_cast<__half2*>(&b);
    __half2 r = __hmul2(x, y);
    return *reinterpret_cast<uint32_t*>(&r);
}

// ---------------- scratch (device globals) ----------------
__device__ float s_x1  [BB*QQ*DD];
__device__ float s_x2  [BB*QQ*DD];
__device__ float s_bias[BB*LL*QQ];
__device__ float s_part[4*BB*QQ*DD];
__device__ float s_pm  [BB*HH*8*QQ];
__device__ float s_pl  [BB*HH*8*QQ];
__device__ float s_pacc[BB*HH*8*QQ*HD];
// fp16 tensors
__device__ __half h_queries[BB*QQ*DD];
__device__ __half h_memory [BB*LL*DD];
__device__ __half h_sa_in_w[3*DD*DD];
__device__ __half h_sa_out_w[DD*DD];
__device__ __half h_q_w[DD*DD];
__device__ __half h_k_w[DD*DD];
__device__ __half h_v_w[DD*DD];
__device__ __half h_o_w[DD*DD];
__device__ __half h_ffn_w1[DFF*DD];
__device__ __half h_ffn_w2[DD*DFF];
__device__ __half h_qkv[BB*QQ*3*DD];
__device__ __half h_qx [BB*QQ*DD];
__device__ __half h_kk [BB*LL*DD];
__device__ __half h_vv [BB*LL*DD];
__device__ __half h_sa [BB*QQ*DD];
__device__ __half h_ca [BB*QQ*DD];
__device__ __half h_x1 [BB*QQ*DD];
__device__ __half h_x2 [BB*QQ*DD];
__device__ __half h_ffn[BB*QQ*DFF];

// ---------------- fp32 -> fp16 convert (8 elts/thread) ----------------
__device__ __forceinline__ void conv8(const float* src, __half* dst, int i) {
    float4 x0 = *reinterpret_cast<const float4*>(src + i);
    float4 x1 = *reinterpret_cast<const float4*>(src + i + 4);
    uint4 u;
    u.x = h2bits(x0.x, x0.y);
    u.y = h2bits(x0.z, x0.w);
    u.z = h2bits(x1.x, x1.y);
    u.w = h2bits(x1.z, x1.w);
    *reinterpret_cast<uint4*>(dst + i) = u;
}

__global__ __launch_bounds__(256) void f2h_kernel(
    const float* __restrict__ src, __half* __restrict__ dst, int n)
{
    gdep_wait();
    int i = (blockIdx.x * 256 + threadIdx.x) * 8;
    if (i >= n) return;
    conv8(src, dst, i);
}

#define WSEG (DD * DD)
#define WF   (DFF * DD)
__global__ __launch_bounds__(256) void f2h_weights_kernel(
    const float* __restrict__ sow, const float* __restrict__ qw,
    const float* __restrict__ ow, const float* __restrict__ fw1,
    const float* __restrict__ fw2,
    __half* __restrict__ hsow, __half* __restrict__ hqw,
    __half* __restrict__ how, __half* __restrict__ hfw1,
    __half* __restrict__ hfw2)
{
    gdep_wait();
    int i = (blockIdx.x * 256 + threadIdx.x) * 8;
    if (i < WSEG) { conv8(sow, hsow, i); return; }
    i -= WSEG;
    if (i < WSEG) { conv8(qw, hqw, i); return; }
    i -= WSEG;
    if (i < WSEG) { conv8(ow, how, i); return; }
    i -= WSEG;
    if (i < WF) { conv8(fw1, hfw1, i); return; }
    i -= WF;
    if (i < WF) conv8(fw2, hfw2, i);
}

// ---------------- FP16 tensor-core GEMM (dynamic smem, templated tile) ----
// MF: m-frags per warp (BM = 64*MF). NF: n-frags per warp (warp n-width NF*8,
// BN = 2*NF*8). 8 warps: 4 m-warps x 2 n-warps.
#define KP 40
#define NST 3

extern __shared__ __half g_dynsmem[];

template<int MF, int NF>
__global__ __launch_bounds__(256) void gemm_f16_kernel(
    const __half* __restrict__ A, const __half* __restrict__ W,
    const float* __restrict__ bias, float* C, __half* Ch,
    int M, int N, int K, int relu,
    const __half* __restrict__ W2,
    const float* __restrict__ bias2,
    float* C2, __half* C2h)
{
    constexpr int BM = 64 * MF;
    constexpr int BN = 2 * NF * 8;

    const int tid = threadIdx.x;
    const int lane = tid & 31;
    const int w = tid >> 5;
    const int wm = w & 3;
    const int wn = w >> 2;
    const int g = lane >> 2;
    const int t = lane & 3;

    int bx = blockIdx.x;
    const int nblk = N / BN;
    if (W2 != nullptr && bx >= nblk) {
        bx -= nblk;
        W = W2; bias = bias2; C = C2; Ch = C2h;
    }

    const int m0 = blockIdx.y * BM;
    const int n0 = bx * BN;

    const int nsplit = gridDim.z;
    const int Klen = K / nsplit;
    const int kstart = blockIdx.z * Klen;
    float* Cout = (C && nsplit > 1) ? (C + (size_t)blockIdx.z * M * N) : C;

    const uint32_t as_base = (uint32_t)__cvta_generic_to_shared(g_dynsmem);
    const uint32_t ws_base = as_base + NST * BM * KP * 2;

    float acc[MF][NF][4];
    #pragma unroll
    for (int i = 0; i < MF; i++)
        #pragma unroll
        for (int j = 0; j < NF; j++)
            #pragma unroll
            for (int e = 0; e < 4; e++) acc[i][j][e] = 0.f;

    const int m_warp = wm * (16 * MF);
    const int n_warp = wn * (NF * 8);
    const int nIter = Klen / 32;

    const int lr8 = lane & 7;
    const int lb1 = (lane >> 3) & 1;
    const int lb2 = (lane >> 4) & 1;
    uint32_t aAddr[MF];
    #pragma unroll
    for (int mi = 0; mi < MF; mi++) {
        int row = m_warp + mi * 16 + lr8 + lb1 * 8;
        aAddr[mi] = as_base + (row * KP + lb2 * 8) * 2;
    }
    uint32_t bAddr[NF / 2];
    #pragma unroll
    for (int p = 0; p < NF / 2; p++) {
        int row = n_warp + p * 16 + lb2 * 8 + lr8;
        bAddr[p] = ws_base + (row * KP + lb1 * 8) * 2;
    }
    const uint32_t aStride = BM * KP * 2;
    const uint32_t bStride = BN * KP * 2;

    auto load_stage = [&](int st, int it) {
        const int kg = kstart + it * 32;
        #pragma unroll
        for (int s = 0; s < (BM * 4) / 256; s++) {
            int idx = tid + s * 256;
            int r = idx >> 2, kc = (idx & 3) * 8;
            int arow = m0 + r;
            uint32_t dst = as_base + ((st * BM + r) * KP + kc) * 2;
            cp16(dst, A + (size_t)arow * K + kg + kc, (arow < M) ? 16 : 0);
        }
        #pragma unroll
        for (int s = 0; s < (BN * 4) / 256; s++) {
            int idx = tid + s * 256;
            int r = idx >> 2, kc = (idx & 3) * 8;
            uint32_t dst = ws_base + ((st * BN + r) * KP + kc) * 2;
            cp16(dst, W + (size_t)(n0 + r) * K + kg + kc, 16);
        }
        cp_commit();
    };

    gdep_wait();
    load_stage(0, 0);
    load_stage(1, 1);

    for (int it = 0; it < nIter; it++) {
        cp_wait<NST - 2>();
        __syncthreads();
        if (it + NST - 1 < nIter) load_stage((it + NST - 1) % NST, it + NST - 1);
        else cp_commit();

        const int st = it % NST;
        #pragma unroll
        for (int kk = 0; kk < 32; kk += 16) {
            uint32_t b0[NF], b1[NF];
            #pragma unroll
            for (int p = 0; p < NF / 2; p++)
                ldsm4(b0[2 * p], b1[2 * p], b0[2 * p + 1], b1[2 * p + 1],
                      bAddr[p] + st * bStride + kk * 2);
            #pragma unroll
            for (int mi = 0; mi < MF; mi++) {
                uint32_t a0, a1, a2, a3;
                ldsm4(a0, a1, a2, a3, aAddr[mi] + st * aStride + kk * 2);
                #pragma unroll
                for (int ni = 0; ni < NF; ni++)
                    mma16h(acc[mi][ni], a0, a1, a2, a3, b0[ni], b1[ni]);
            }
        }
    }

    #pragma unroll
    for (int mi = 0; mi < MF; mi++) {
        #pragma unroll
        for (int ni = 0; ni < NF; ni++) {
            int col = n0 + n_warp + ni * 8 + 2 * t;
            float bz0 = 0.f, bz1 = 0.f;
            if (nsplit == 1) { bz0 = bias[col]; bz1 = bias[col + 1]; }
            int r0 = m0 + m_warp + mi * 16 + g;
            int r1 = r0 + 8;
            float v0 = acc[mi][ni][0] + bz0, v1 = acc[mi][ni][1] + bz1;
            float v2 = acc[mi][ni][2] + bz0, v3 = acc[mi][ni][3] + bz1;
            if (relu) {
                v0 = fmaxf(v0, 0.f); v1 = fmaxf(v1, 0.f);
                v2 = fmaxf(v2, 0.f); v3 = fmaxf(v3, 0.f);
            }
            if (Cout) {
                if (r0 < M) *reinterpret_cast<float2*>(Cout + (size_t)r0 * N + col) = make_float2(v0, v1);
                if (r1 < M) *reinterpret_cast<float2*>(Cout + (size_t)r1 * N + col) = make_float2(v2, v3);
            }
            if (Ch) {
                if (r0 < M) {
                    uint32_t hv = h2bits(v0, v1);
                    *reinterpret_cast<uint32_t*>(Ch + (size_t)r0 * N + col) = hv;
                }
                if (r1 < M) {
                    uint32_t hv = h2bits(v2, v3);
                    *reinterpret_cast<uint32_t*>(Ch + (size_t)r1 * N + col) = hv;
                }
            }
        }
    }
}

// ---------------- warp-per-row LayerNorm core ----------------
__device__ __forceinline__ void lnw_finish(
    float v[8], int lane, const float* g, const float* bt,
    float* out, __half* outh, size_t row)
{
    float s1 = 0.f, s2 = 0.f;
    #pragma unroll
    for (int i = 0; i < 8; i++) { s1 += v[i]; s2 += v[i] * v[i]; }
    #pragma unroll
    for (int o = 16; o > 0; o >>= 1) {
        s1 += __shfl_xor_sync(0xffffffffu, s1, o);
        s2 += __shfl_xor_sync(0xffffffffu, s2, o);
    }
    float mean = s1 * (1.f / DD);
    float var = s2 * (1.f / DD) - mean * mean;
    float rstd = rsqrtf(var + 1e-5f);
    int c0 = lane * 8;
    float r[8];
    #pragma unroll
    for (int i = 0; i < 8; i++)
        r[i] = (v[i] - mean) * rstd * g[c0 + i] + bt[c0 + i];
    if (out) {
        *reinterpret_cast<float4*>(out + row * DD + c0) = make_float4(r[0], r[1], r[2], r[3]);
        *reinterpret_cast<float4*>(out + row * DD + c0 + 4) = make_float4(r[4], r[5], r[6], r[7]);
    }
    if (outh) {
        uint4 u;
        u.x = h2bits(r[0], r[1]);
        u.y = h2bits(r[2], r[3]);
        u.z = h2bits(r[4], r[5]);
        u.w = h2bits(r[6], r[7]);
        *reinterpret_cast<uint4*>(outh + row * DD + c0) = u;
    }
}

__global__ __launch_bounds__(256) void ln_split_kernel(
    const float* __restrict__ X, const float* __restrict__ parts,
    const float* __restrict__ fbias,
    const float* __restrict__ g, const float* __restrict__ bt,
    float* out, __half* outh, int nsplit)
{
    gdep_wait();
    const int lane = threadIdx.x & 31;
    const size_t row = blockIdx.x * 8 + (threadIdx.x >> 5);
    const size_t stride = (size_t)BB * QQ * DD;
    int c0 = lane * 8;
    float v[8];
    float4 x0 = *reinterpret_cast<const float4*>(X + row * DD + c0);
    float4 x1 = *reinterpret_cast<const float4*>(X + row * DD + c0 + 4);
    float4 f0 = *reinterpret_cast<const float4*>(fbias + c0);
    float4 f1 = *reinterpret_cast<const float4*>(fbias + c0 + 4);
    v[0] = x0.x + f0.x; v[1] = x0.y + f0.y; v[2] = x0.z + f0.z; v[3] = x0.w + f0.w;
    v[4] = x1.x + f1.x; v[5] = x1.y + f1.y; v[6] = x1.z + f1.z; v[7] = x1.w + f1.w;
    for (int s = 0; s < nsplit; s++) {
        float4 p0 = *reinterpret_cast<const float4*>(parts + s * stride + row * DD + c0);
        float4 p1 = *reinterpret_cast<const float4*>(parts + s * stride + row * DD + c0 + 4);
        v[0] += p0.x; v[1] += p0.y; v[2] += p0.z; v[3] += p0.w;
        v[4] += p1.x; v[5] += p1.y; v[6] += p1.z; v[7] += p1.w;
    }
    lnw_finish(v, lane, g, bt, out, outh, row);
}

// ---------------- GASA geometric bias: block per (b,l) ----------------
__global__ __launch_bounds__(128) void gasa_bias_kernel(
    const float* __restrict__ qpos, const float* __restrict__ mpos,
    const float* __restrict__ w1, const float* __restrict__ b1,
    const float* __restrict__ w2, const float* __restrict__ b2,
    const float* __restrict__ betap, float* __restrict__ biasT)
{
    const int l = blockIdx.x;
    const int b = blockIdx.y;
    const int tid = threadIdx.x;

    __shared__ float sw1[KD], sb1[KD], sw2[KD], smp[3], sb2, sbeta;
    if (tid < KD) {
        sw1[tid] = w1[tid];
        sb1[tid] = b1[tid];
        sw2[tid] = w2[tid];
    }
    if (tid < 3) smp[tid] = mpos[((size_t)b * LL + l) * 3 + tid];
    if (tid == 3) sb2 = b2[0];
    if (tid == 4) sbeta = betap[0];
    __syncthreads();

    const float mx = smp[0], my = smp[1], mz = smp[2];
    const float bb2 = sb2, bet = sbeta;
    float* orow = biasT + ((size_t)b * LL + l) * QQ;

    for (int q = tid; q < QQ; q += 128) {
        const float* qp = qpos + ((size_t)b * QQ + q) * 3;
        float dx = qp[0] - mx, dy = qp[1] - my, dz = qp[2] - mz;
        float dist = sqrtf(fmaxf(dx * dx + dy * dy + dz * dz, 0.f));
        float s = 0.f;
        #pragma unroll
        for (int k = 0; k < KD; k++) {
            float h = fmaxf(dist * sw1[k] + sb1[k], 0.f);
            s += h * sw2[k];
        }
        s += bb2;
        s = fminf(fmaxf(s, -10.f), 0.f);
        orow[q] = s * bet;
    }
}

// ---------------- fp16 flash attention partials (fp16 Q/K/V I/O) ----------
__global__ __launch_bounds__(128) void attn_mma_kernel(
    const __half* __restrict__ Qp, int qstride,
    const __half* __restrict__ Kp, const __half* __restrict__ Vp, int kvstride,
    const float* __restrict__ biasT, int Lk, int S, int step,
    float* __restrict__ pm, float* __restrict__ pl, float* __restrict__ pacc,
    int useBias)
{
    const int b = blockIdx.z, h = blockIdx.y;
    const int sp = blockIdx.x / NQT;
    const int qt = blockIdx.x % NQT;
    const int tid = threadIdx.x;
    const int lane = tid & 31;
    const int warp = tid >> 5;
    const int g = lane >> 2;
    const int t = lane & 3;

    const int q0 = qt * 64 + warp * 16;
    const int qg  = q0 + g;
    const int qg8 = q0 + g + 8;
    const int qgc  = min(qg, QQ - 1);
    const int qg8c = min(qg8, QQ - 1);

    const int ls = sp * step;
    const int le = min(ls + step, Lk);

    gdep_wait();

    uint32_t qa[2][4];
    {
        const uint32_t s2 = h2bits(SCALE, SCALE);
        const __half* q0p = Qp + ((size_t)(b * QQ + qgc)) * qstride + h * HD;
        const __half* q1p = Qp + ((size_t)(b * QQ + qg8c)) * qstride + h * HD;
        #pragma unroll
        for (int ks = 0; ks < 2; ks++) {
            int d = ks * 16 + 2 * t;
            qa[ks][0] = hmul2b(*reinterpret_cast<const uint32_t*>(q0p + d), s2);
            qa[ks][1] = hmul2b(*reinterpret_cast<const uint32_t*>(q1p + d), s2);
            qa[ks][2] = hmul2b(*reinterpret_cast<const uint32_t*>(q0p + d + 8), s2);
            qa[ks][3] = hmul2b(*reinterpret_cast<const uint32_t*>(q1p + d + 8), s2);
        }
    }

    __shared__ __align__(16) __half Kh[16][40];
    __shared__ __align__(16) __half Vh[HD][24];
    __shared__ float Bsm[16][68];

    float oacc[4][4];
    #pragma unroll
    for (int i = 0; i < 4; i++)
        #pragma unroll
        for (int j = 0; j < 4; j++) oacc[i][j] = 0.f;
    float om0 = -INFINITY, om1 = -INFINITY;
    float ol0 = 0.f, ol1 = 0.f;

    const int key_l = tid >> 3;
    const int d0 = (tid & 7) * 4;
    const int bq0 = (tid & 7) * 8;
    const bool qtail = (qt == NQT - 1);

    const uint32_t kh_base = (uint32_t)__cvta_generic_to_shared(&Kh[0][0]);
    const uint32_t vh_base = (uint32_t)__cvta_generic_to_shared(&Vh[0][0]);
    const int lr8 = lane & 7;
    const int lb1 = (lane >> 3) & 1;
    const int lb2 = (lane >> 4) & 1;
    const uint32_t kAddr = kh_base + ((lb2 * 8 + lr8) * 40 + lb1 * 8) * 2;
    uint32_t vAddr[2];
    #pragma unroll
    for (int p = 0; p < 2; p++)
        vAddr[p] = vh_base + ((p * 16 + lb2 * 8 + lr8) * 24 + lb1 * 8) * 2;

    uint2 kreg, vreg;
    float4 breg0, breg1;

    auto prefetch = [&](int l0) {
        int grow = b * Lk + min(l0 + key_l, Lk - 1);
        kreg = *reinterpret_cast<const uint2*>(
            Kp + (size_t)grow * kvstride + h * HD + d0);
        vreg = *reinterpret_cast<const uint2*>(
            Vp + (size_t)grow * kvstride + h * HD + d0);
        if (useBias) {
            const float* brow = biasT + ((size_t)(b * Lk + l0 + key_l)) * QQ
                                + qt * 64 + bq0;
            if (!qtail) {
                breg0 = *reinterpret_cast<const float4*>(brow);
                breg1 = *reinterpret_cast<const float4*>(brow + 4);
            } else {
                int qb = qt * 64 + bq0;
                float e[8];
                #pragma unroll
                for (int i = 0; i < 8; i++)
                    e[i] = (qb + i < QQ) ? brow[i] : 0.f;
                breg0 = make_float4(e[0], e[1], e[2], e[3]);
                breg1 = make_float4(e[4], e[5], e[6], e[7]);
            }
        }
    };

    prefetch(ls);

    for (int l0 = ls; l0 < le; l0 += 16) {
        __syncthreads();
        {
            *reinterpret_cast<uint2*>(&Kh[key_l][d0]) = kreg;
            const __half* vh = reinterpret_cast<const __half*>(&vreg);
            Vh[d0 + 0][key_l] = vh[0];
            Vh[d0 + 1][key_l] = vh[1];
            Vh[d0 + 2][key_l] = vh[2];
            Vh[d0 + 3][key_l] = vh[3];
            if (useBias) {
                *reinterpret_cast<float4*>(&Bsm[key_l][bq0]) = breg0;
                *reinterpret_cast<float4*>(&Bsm[key_l][bq0 + 4]) = breg1;
            }
        }
        if (l0 + 16 < le) prefetch(l0 + 16);
        __syncthreads();

        float sc[2][4];
        sc[0][0] = sc[0][1] = sc[0][2] = sc[0][3] = 0.f;
        sc[1][0] = sc[1][1] = sc[1][2] = sc[1][3] = 0.f;
        #pragma unroll
        for (int ks = 0; ks < 2; ks++) {
            uint32_t r0, r1, r2, r3;
            ldsm4(r0, r1, r2, r3, kAddr + ks * 32);
            mma16h(sc[0], qa[ks][0], qa[ks][1], qa[ks][2], qa[ks][3], r0, r1);
            mma16h(sc[1], qa[ks][0], qa[ks][1], qa[ks][2], qa[ks][3], r2, r3);
        }

        #pragma unroll
        for (int nf = 0; nf < 2; nf++) {
            if (useBias) {
                int brow = nf * 8 + 2 * t;
                int c0 = warp * 16 + g;
                sc[nf][0] += Bsm[brow][c0];
                sc[nf][1] += Bsm[brow + 1][c0];
                sc[nf][2] += Bsm[brow][c0 + 8];
                sc[nf][3] += Bsm[brow + 1][c0 + 8];
            }
            int kc = l0 + nf * 8 + 2 * t;
            if (kc >= le)     { sc[nf][0] = -1e30f; sc[nf][2] = -1e30f; }
            if (kc + 1 >= le) { sc[nf][1] = -1e30f; sc[nf][3] = -1e30f; }
        }

        float mx0 = fmaxf(fmaxf(sc[0][0], sc[0][1]), fmaxf(sc[1][0], sc[1][1]));
        float mx1 = fmaxf(fmaxf(sc[0][2], sc[0][3]), fmaxf(sc[1][2], sc[1][3]));
        mx0 = fmaxf(mx0, __shfl_xor_sync(0xffffffffu, mx0, 1));
        mx0 = fmaxf(mx0, __shfl_xor_sync(0xffffffffu, mx0, 2));
        mx1 = fmaxf(mx1, __shfl_xor_sync(0xffffffffu, mx1, 1));
        mx1 = fmaxf(mx1, __shfl_xor_sync(0xffffffffu, mx1, 2));

        float nm0 = fmaxf(om0, mx0), nm1 = fmaxf(om1, mx1);
        float cr0 = __expf(om0 - nm0), cr1 = __expf(om1 - nm1);
        om0 = nm0; om1 = nm1;
        ol0 *= cr0; ol1 *= cr1;
        #pragma unroll
        for (int nd = 0; nd < 4; nd++) {
            oacc[nd][0] *= cr0; oacc[nd][1] *= cr0;
            oacc[nd][2] *= cr1; oacc[nd][3] *= cr1;
        }

        #pragma unroll
        for (int nf = 0; nf < 2; nf++) {
            sc[nf][0] = __expf(sc[nf][0] - nm0);
            sc[nf][1] = __expf(sc[nf][1] - nm0);
            sc[nf][2] = __expf(sc[nf][2] - nm1);
            sc[nf][3] = __expf(sc[nf][3] - nm1);
            ol0 += sc[nf][0] + sc[nf][1];
            ol1 += sc[nf][2] + sc[nf][3];
        }

        uint32_t pa0 = h2bits(sc[0][0], sc[0][1]);
        uint32_t pa1 = h2bits(sc[0][2], sc[0][3]);
        uint32_t pa2 = h2bits(sc[1][0], sc[1][1]);
        uint32_t pa3 = h2bits(sc[1][2], sc[1][3]);
        uint32_t b0[4], b1[4];
        ldsm4(b0[0], b1[0], b0[1], b1[1], vAddr[0]);
        ldsm4(b0[2], b1[2], b0[3], b1[3], vAddr[1]);
        #pragma unroll
        for (int nd = 0; nd < 4; nd++)
            mma16h(oacc[nd], pa0, pa1, pa2, pa3, b0[nd], b1[nd]);
    }

    ol0 += __shfl_xor_sync(0xffffffffu, ol0, 1);
    ol0 += __shfl_xor_sync(0xffffffffu, ol0, 2);
    ol1 += __shfl_xor_sync(0xffffffffu, ol1, 1);
    ol1 += __shfl_xor_sync(0xffffffffu, ol1, 2);

    size_t pbase = ((size_t)((b * HH + h) * S + sp)) * QQ;
    if (qg < QQ) {
        if (t == 0) { pm[pbase + qg] = om0; pl[pbase + qg] = ol0; }
        float* ap = pacc + (pbase + qg) * HD;
        #pragma unroll
        for (int nd = 0; nd < 4; nd++)
            *reinterpret_cast<float2*>(ap + nd * 8 + 2 * t) =
                make_float2(oacc[nd][0], oacc[nd][1]);
    }
    if (qg8 < QQ) {
        if (t == 0) { pm[pbase + qg8] = om1; pl[pbase + qg8] = ol1; }
        float* ap = pacc + (pbase + qg8) * HD;
        #pragma unroll
        for (int nd = 0; nd < 4; nd++)
            *reinterpret_cast<float2*>(ap + nd * 8 + 2 * t) =
                make_float2(oacc[nd][2], oacc[nd][3]);
    }
}

// ---------------- split combine ----------------
__global__ __launch_bounds__(256) void attn_combine_kernel(
    const float* __restrict__ pm, const float* __restrict__ pl,
    const float* __restrict__ pacc, int S, __half* __restrict__ out)
{
    gdep_wait();
    int tt = blockIdx.x * 256 + threadIdx.x;
    if (tt >= BB * HH * QQ * (HD / 2)) return;
    int dp = tt & (HD / 2 - 1);
    int idx = tt >> 4;
    int q = idx % QQ;
    int bh = idx / QQ;
    int b = bh / HH, h = bh % HH;

    float mg = -INFINITY;
    for (int s = 0; s < S; s++)
        mg = fmaxf(mg, pm[((size_t)bh * S + s) * QQ + q]);
    float Lsum = 0.f;
    float olo = 0.f, ohi = 0.f;
    for (int s = 0; s < S; s++) {
        size_t pidx = ((size_t)bh * S + s) * QQ + q;
        float w = __expf(pm[pidx] - mg);
        Lsum += pl[pidx] * w;
        float2 a = *reinterpret_cast<const float2*>(pacc + pidx * HD + 2 * dp);
        olo += w * a.x; ohi += w * a.y;
    }
    float inv = 1.f / Lsum;
    uint32_t hv = h2bits(olo * inv, ohi * inv);
    *reinterpret_cast<uint32_t*>(
        out + ((size_t)(b * QQ + q)) * DD + h * HD + 2 * dp) = hv;
}

// ---------------- host launcher ----------------
static inline int cdiv(int a, int b) { return (a + b - 1) / b; }

// dynamic smem sizes
#define SMEM_G28 (NST * (128 + 128) * KP * 2)   // 61440
#define SMEM_G14 (NST * (64 + 64) * KP * 2)     // 30720

template<typename F, typename... Args>
static inline void lpdl(F kernel, dim3 grid, dim3 block, cudaStream_t st,
                        size_t smem, Args... args)
{
    cudaLaunchConfig_t cfg = {};
    cfg.gridDim = grid;
    cfg.blockDim = block;
    cfg.dynamicSmemBytes = smem;
    cfg.stream = st;
    cudaLaunchAttribute attr[1];
    attr[0].id = cudaLaunchAttributeProgrammaticStreamSerialization;
    attr[0].val.programmaticStreamSerializationAllowed = 1;
    cfg.attrs = attr;
    cfg.numAttrs = 1;
    cudaLaunchKernelEx(&cfg, kernel, args...);
}

extern "C" void kernel_launch(void* const* d_in, const int* in_sizes, int n_in,
                              void* d_out, int out_size)
{
    const float* queries   = (const float*)d_in[0];
    const float* memory    = (const float*)d_in[1];
    const float* memory_pos= (const float*)d_in[2];
    const float* query_pos = (const float*)d_in[3];
    const float* sa_in_w   = (const float*)d_in[4];
    const float* sa_in_b   = (const float*)d_in[5];
    const float* sa_out_w  = (const float*)d_in[6];
    const float* sa_out_b  = (const float*)d_in[7];
    const float* norm1_g   = (const float*)d_in[8];
    const float* norm1_b   = (const float*)d_in[9];
    const float* q_w       = (const float*)d_in[10];
    const float* q_b       = (const float*)d_in[11];
    const float* k_w       = (const float*)d_in[12];
    const float* k_b       = (const float*)d_in[13];
    const float* v_w       = (const float*)d_in[14];
    const float* v_b       = (const float*)d_in[15];
    const float* o_w       = (const float*)d_in[16];
    const float* o_b       = (const float*)d_in[17];
    const float* norm2_g   = (const float*)d_in[18];
    const float* norm2_b   = (const float*)d_in[19];
    const float* beta      = (const float*)d_in[20];
    const float* dk_w1     = (const float*)d_in[21];
    const float* dk_b1     = (const float*)d_in[22];
    const float* dk_w2     = (const float*)d_in[23];
    const float* dk_b2     = (const float*)d_in[24];
    const float* ffn_w1    = (const float*)d_in[25];
    const float* ffn_b1    = (const float*)d_in[26];
    const float* ffn_w2    = (const float*)d_in[27];
    const float* ffn_b2    = (const float*)d_in[28];
    const float* norm3_g   = (const float*)d_in[29];
    const float* norm3_b   = (const float*)d_in[30];

    float *g_x1, *g_x2, *g_bias, *g_part, *g_pm, *g_pl, *g_pacc;
    cudaGetSymbolAddress((void**)&g_x1,   s_x1);
    cudaGetSymbolAddress((void**)&g_x2,   s_x2);
    cudaGetSymbolAddress((void**)&g_bias, s_bias);
    cudaGetSymbolAddress((void**)&g_part, s_part);
    cudaGetSymbolAddress((void**)&g_pm,   s_pm);
    cudaGetSymbolAddress((void**)&g_pl,   s_pl);
    cudaGetSymbolAddress((void**)&g_pacc, s_pacc);

    __half *hq, *hm, *h_siw, *h_sow, *h_qw, *h_kw, *h_vw, *h_ow,
           *h_fw1, *h_fw2, *hqkv, *hqx, *hkk, *hvv, *hsa, *hca,
           *hx1, *hx2, *hffn;
    cudaGetSymbolAddress((void**)&hq,    h_queries);
    cudaGetSymbolAddress((void**)&hm,    h_memory);
    cudaGetSymbolAddress((void**)&h_siw, h_sa_in_w);
    cudaGetSymbolAddress((void**)&h_sow, h_sa_out_w);
    cudaGetSymbolAddress((void**)&h_qw,  h_q_w);
    cudaGetSymbolAddress((void**)&h_kw,  h_k_w);
    cudaGetSymbolAddress((void**)&h_vw,  h_v_w);
    cudaGetSymbolAddress((void**)&h_ow,  h_o_w);
    cudaGetSymbolAddress((void**)&h_fw1, h_ffn_w1);
    cudaGetSymbolAddress((void**)&h_fw2, h_ffn_w2);
    cudaGetSymbolAddress((void**)&hqkv,  h_qkv);
    cudaGetSymbolAddress((void**)&hqx,   h_qx);
    cudaGetSymbolAddress((void**)&hkk,   h_kk);
    cudaGetSymbolAddress((void**)&hvv,   h_vv);
    cudaGetSymbolAddress((void**)&hsa,   h_sa);
    cudaGetSymbolAddress((void**)&hca,   h_ca);
    cudaGetSymbolAddress((void**)&hx1,   h_x1);
    cudaGetSymbolAddress((void**)&hx2,   h_x2);
    cudaGetSymbolAddress((void**)&hffn,  h_ffn);

    static cudaStream_t st2 = nullptr, st3 = nullptr, st4 = nullptr;
    static cudaEvent_t ev0 = nullptr, ev2 = nullptr, ev3 = nullptr,
                       ev4 = nullptr, ev5 = nullptr;
    if (st2 == nullptr) {
        cudaStreamCreateWithFlags(&st2, cudaStreamNonBlocking);
        cudaStreamCreateWithFlags(&st3, cudaStreamNonBlocking);
        cudaStreamCreateWithFlags(&st4, cudaStreamNonBlocking);
        cudaEventCreateWithFlags(&ev0, cudaEventDisableTiming);
        cudaEventCreateWithFlags(&ev2, cudaEventDisableTiming);
        cudaEventCreateWithFlags(&ev3, cudaEventDisableTiming);
        cudaEventCreateWithFlags(&ev4, cudaEventDisableTiming);
        cudaEventCreateWithFlags(&ev5, cudaEventDisableTiming);
        cudaFuncSetAttribute(gemm_f16_kernel<2, 8>,
                             cudaFuncAttributeMaxDynamicSharedMemorySize,
                             SMEM_G28);
        cudaFuncSetAttribute(gemm_f16_kernel<1, 4>,
                             cudaFuncAttributeMaxDynamicSharedMemorySize,
                             SMEM_G14);
    }

    const int Mq = BB * QQ;   // 2400
    const int Mm = BB * LL;   // 8192
    const int NCOMB = BB * HH * QQ * (HD / 2);

    // ---- fork ----
    cudaEventRecord(ev0, 0);
    cudaStreamWaitEvent(st2, ev0, 0);
    cudaStreamWaitEvent(st3, ev0, 0);
    cudaStreamWaitEvent(st4, ev0, 0);

    // st2: memory + KV weights conversion, then fused KV GEMM (fp16 out)
    lpdl(f2h_kernel, cdiv(Mm * DD / 8, 256), 256, st2, 0, memory, hm, Mm * DD);
    lpdl(f2h_kernel, cdiv(WSEG / 8, 256), 256, st2, 0, k_w, h_kw, WSEG);
    lpdl(f2h_kernel, cdiv(WSEG / 8, 256), 256, st2, 0, v_w, h_vw, WSEG);
    lpdl(gemm_f16_kernel<2, 8>, dim3(2 * DD / 128, cdiv(Mm, 128), 1), 256, st2,
         SMEM_G28,
         (const __half*)hm, (const __half*)h_kw, k_b, (float*)nullptr, hkk,
         Mm, DD, DD, 0,
         (const __half*)h_vw, v_b, (float*)nullptr, hvv);
    cudaEventRecord(ev2, st2);

    // st3: GASA bias
    lpdl(gasa_bias_kernel, dim3(LL, BB), 128, st3, 0,
         query_pos, memory_pos, dk_w1, dk_b1, dk_w2, dk_b2, beta, g_bias);
    cudaEventRecord(ev3, st3);

    // st4: queries + sa_in_w first, then rest
    lpdl(f2h_kernel, cdiv(Mq * DD / 8, 256), 256, st4, 0, queries, hq, Mq * DD);
    lpdl(f2h_kernel, cdiv(3 * WSEG / 8, 256), 256, st4, 0, sa_in_w, h_siw, 3 * WSEG);
    cudaEventRecord(ev5, st4);
    {
        int total = 3 * WSEG + 2 * WF;
        lpdl(f2h_weights_kernel, cdiv(total / 8, 256), 256, st4, 0,
             sa_out_w, q_w, o_w, ffn_w1, ffn_w2,
             h_sow, h_qw, h_ow, h_fw1, h_fw2);
    }
    cudaEventRecord(ev4, st4);

    // ---- main chain (PDL-linked) ----
    cudaStreamWaitEvent(0, ev5, 0);

    // 1) self-attn packed in-proj -> fp16 qkv (128x128 tile)
    lpdl(gemm_f16_kernel<2, 8>, dim3(3 * DD / 128, cdiv(Mq, 128), 1), 256,
         (cudaStream_t)0, SMEM_G28,
         (const __half*)hq, (const __half*)h_siw, sa_in_b, (float*)nullptr, hqkv,
         Mq, 3 * DD, DD, 0,
         (const __half*)nullptr, (const float*)nullptr, (float*)nullptr, (__half*)nullptr);

    // 2) self-attention, split S=2 -> combine -> h_sa (fp16)
    {
        int S = 2, step = cdiv(QQ, S * 16) * 16;   // 304
        lpdl(attn_mma_kernel, dim3(NQT * S, HH, BB), 128, (cudaStream_t)0, 0,
             (const __half*)hqkv, 3 * DD,
             (const __half*)(hqkv + DD), (const __half*)(hqkv + 2 * DD), 3 * DD,
             (const float*)nullptr, QQ, S, step, g_pm, g_pl, g_pacc, 0);
        lpdl(attn_combine_kernel, cdiv(NCOMB, 256), 256, (cudaStream_t)0, 0,
             (const float*)g_pm, (const float*)g_pl, (const float*)g_pacc, S, hsa);
    }

    cudaStreamWaitEvent(0, ev4, 0);

    // 3) SA out-proj split-K=2 + LN1 (x1 fp32 + fp16)
    lpdl(gemm_f16_kernel<1, 4>, dim3(DD / 64, cdiv(Mq, 64), 2), 256,
         (cudaStream_t)0, SMEM_G14,
         (const __half*)hsa, (const __half*)h_sow, sa_out_b, g_part, (__half*)nullptr,
         Mq, DD, DD, 0,
         (const __half*)nullptr, (const float*)nullptr, (float*)nullptr, (__half*)nullptr);
    lpdl(ln_split_kernel, Mq / 8, 256, (cudaStream_t)0, 0,
         queries, (const float*)g_part, sa_out_b, norm1_g, norm1_b,
         g_x1, hx1, 2);

    // 4) Q projection -> fp16
    lpdl(gemm_f16_kernel<1, 4>, dim3(DD / 64, cdiv(Mq, 64), 1), 256,
         (cudaStream_t)0, SMEM_G14,
         (const __half*)hx1, (const __half*)h_qw, q_b, (float*)nullptr, hqx,
         Mq, DD, DD, 0,
         (const __half*)nullptr, (const float*)nullptr, (float*)nullptr, (__half*)nullptr);

    cudaStreamWaitEvent(0, ev2, 0);
    cudaStreamWaitEvent(0, ev3, 0);

    // 5) cross-attention, split S=4 -> combine -> h_ca (fp16)
    {
        int S = 4, step = cdiv(LL, S * 16) * 16;
        lpdl(attn_mma_kernel, dim3(NQT * S, HH, BB), 128, (cudaStream_t)0, 0,
             (const __half*)hqx, DD, (const __half*)hkk, (const __half*)hvv, DD,
             (const float*)g_bias, LL, S, step, g_pm, g_pl, g_pacc, 1);
        lpdl(attn_combine_kernel, cdiv(NCOMB, 256), 256, (cudaStream_t)0, 0,
             (const float*)g_pm, (const float*)g_pl, (const float*)g_pacc, S, hca);
    }

    // 6) O proj split-K=2 + LN2 (x2 fp32 + fp16)
    lpdl(gemm_f16_kernel<1, 4>, dim3(DD / 64, cdiv(Mq, 64), 2), 256,
         (cudaStream_t)0, SMEM_G14,
         (const __half*)hca, (const __half*)h_ow, o_b, g_part, (__half*)nullptr,
         Mq, DD, DD, 0,
         (const __half*)nullptr, (const float*)nullptr, (float*)nullptr, (__half*)nullptr);
    lpdl(ln_split_kernel, Mq / 8, 256, (cudaStream_t)0, 0,
         (const float*)g_x1, (const float*)g_part, o_b, norm2_g, norm2_b,
         g_x2, hx2, 2);

    // 7) FFN1 (relu) -> fp16 only (128x128 tile)
    lpdl(gemm_f16_kernel<2, 8>, dim3(DFF / 128, cdiv(Mq, 128), 1), 256,
         (cudaStream_t)0, SMEM_G28,
         (const __half*)hx2, (const __half*)h_fw1, ffn_b1, (float*)nullptr, hffn,
         Mq, DFF, DD, 1,
         (const __half*)nullptr, (const float*)nullptr, (float*)nullptr, (__half*)nullptr);

    // 8) FFN2 split-K=4 partials + fused combine in LN3 -> output
    lpdl(gemm_f16_kernel<1, 4>, dim3(DD / 64, cdiv(Mq, 64), 4), 256,
         (cudaStream_t)0, SMEM_G14,
         (const __half*)hffn, (const __half*)h_fw2, ffn_b2, g_part, (__half*)nullptr,
         Mq, DD, DFF, 0,
         (const __half*)nullptr, (const float*)nullptr, (float*)nullptr, (__half*)nullptr);
    lpdl(ln_split_kernel, Mq / 8, 256, (cudaStream_t)0, 0,
         (const float*)g_x2, (const float*)g_part, ffn_b2, norm3_g, norm3_b,
         (float*)d_out, (__half*)nullptr, 4);
}

// round 16
// speedup vs baseline: 1.2971x; 1.0125x over previous
#include <cuda_runtime.h>
#include <cuda_fp16.h>
#include <math.h>
#include <stdint.h>

// ---------------- problem constants ----------------
#define BB 4
#define QQ 600
#define LL 2048
#define DD 256
#define HH 8
#define HD 32
#define DFF 2048
#define KD 32
#define SCALE 0.17677669529663687f   // 32^-0.5
#define NQT 10                       // ceil(600/64) 64-query tiles

typedef unsigned long long u64;

// ---------------- helpers ----------------
__device__ __forceinline__ void gdep_wait() {
    asm volatile("griddepcontrol.wait;" ::: "memory");
}
__device__ __forceinline__ void mma16h(float c[4], uint32_t a0, uint32_t a1,
                                       uint32_t a2, uint32_t a3,
                                       uint32_t b0, uint32_t b1) {
    asm("mma.sync.aligned.m16n8k16.row.col.f32.f16.f16.f32 "
        "{%0,%1,%2,%3},{%4,%5,%6,%7},{%8,%9},{%0,%1,%2,%3};"
        : "+f"(c[0]), "+f"(c[1]), "+f"(c[2]), "+f"(c[3])
        : "r"(a0), "r"(a1), "r"(a2), "r"(a3), "r"(b0), "r"(b1));
}
__device__ __forceinline__ void ldsm4(uint32_t& r0, uint32_t& r1,
                                      uint32_t& r2, uint32_t& r3, uint32_t addr) {
    asm volatile("ldmatrix.sync.aligned.m8n8.x4.shared.b16 {%0,%1,%2,%3}, [%4];"
                 : "=r"(r0), "=r"(r1), "=r"(r2), "=r"(r3) : "r"(addr));
}
__device__ __forceinline__ void cp16(uint32_t dst, const void* src, int srcsize) {
    asm volatile("cp.async.ca.shared.global [%0], [%1], 16, %2;"
                 :: "r"(dst), "l"(src), "r"(srcsize));
}
__device__ __forceinline__ void cp_commit() {
    asm volatile("cp.async.commit_group;");
}
template<int N>
__device__ __forceinline__ void cp_wait() {
    asm volatile("cp.async.wait_group %0;" :: "n"(N));
}
__device__ __forceinline__ uint32_t h2bits(float lo, float hi) {
    __half2 h = __floats2half2_rn(lo, hi);
    return *reinterpret_cast<uint32_t*>(&h);
}
__device__ __forceinline__ uint32_t hmul2b(uint32_t a, uint32_t b) {
    __half2 x = *reinterpret_cast<__half2*>(&a);
    __half2 y = *reinterpret_cast<__half2*>(&b);
    __half2 r = __hmul2(x, y);
    return *reinterpret_cast<uint32_t*>(&r);
}

// ---------------- scratch (device globals) ----------------
__device__ float s_x1  [BB*QQ*DD];
__device__ float s_x2  [BB*QQ*DD];
__device__ float s_bias[BB*LL*QQ];
__device__ float s_part[4*BB*QQ*DD];
__device__ float s_pm  [BB*HH*8*QQ];
__device__ float s_pl  [BB*HH*8*QQ];
__device__ float s_pacc[BB*HH*8*QQ*HD];
// fp16 tensors
__device__ __half h_queries[BB*QQ*DD];
__device__ __half h_memory [BB*LL*DD];
__device__ __half h_sa_in_w[3*DD*DD];
__device__ __half h_sa_out_w[DD*DD];
__device__ __half h_q_w[DD*DD];
__device__ __half h_k_w[DD*DD];
__device__ __half h_v_w[DD*DD];
__device__ __half h_o_w[DD*DD];
__device__ __half h_ffn_w1[DFF*DD];
__device__ __half h_ffn_w2[DD*DFF];
__device__ __half h_qkv[BB*QQ*3*DD];
__device__ __half h_qx [BB*QQ*DD];
__device__ __half h_kk [BB*LL*DD];
__device__ __half h_vv [BB*LL*DD];
__device__ __half h_sa [BB*QQ*DD];
__device__ __half h_ca [BB*QQ*DD];
__device__ __half h_x1 [BB*QQ*DD];
__device__ __half h_x2 [BB*QQ*DD];
__device__ __half h_ffn[BB*QQ*DFF];

// ---------------- fp32 -> fp16 convert ----------------
__device__ __forceinline__ void conv8(const float* src, __half* dst, int i) {
    float4 x0 = *reinterpret_cast<const float4*>(src + i);
    float4 x1 = *reinterpret_cast<const float4*>(src + i + 4);
    uint4 u;
    u.x = h2bits(x0.x, x0.y);
    u.y = h2bits(x0.z, x0.w);
    u.z = h2bits(x1.x, x1.y);
    u.w = h2bits(x1.z, x1.w);
    *reinterpret_cast<uint4*>(dst + i) = u;
}

__global__ __launch_bounds__(256) void f2h_kernel(
    const float* __restrict__ src, __half* __restrict__ dst, int n)
{
    gdep_wait();
    int i = (blockIdx.x * 256 + threadIdx.x) * 8;
    if (i >= n) return;
    conv8(src, dst, i);
}

#define WSEG (DD * DD)
#define WF   (DFF * DD)
__global__ __launch_bounds__(256) void f2h_weights_kernel(
    const float* __restrict__ sow, const float* __restrict__ qw,
    const float* __restrict__ ow, const float* __restrict__ fw1,
    const float* __restrict__ fw2,
    __half* __restrict__ hsow, __half* __restrict__ hqw,
    __half* __restrict__ how, __half* __restrict__ hfw1,
    __half* __restrict__ hfw2)
{
    gdep_wait();
    int i = (blockIdx.x * 256 + threadIdx.x) * 8;
    if (i < WSEG) { conv8(sow, hsow, i); return; }
    i -= WSEG;
    if (i < WSEG) { conv8(qw, hqw, i); return; }
    i -= WSEG;
    if (i < WSEG) { conv8(ow, how, i); return; }
    i -= WSEG;
    if (i < WF) { conv8(fw1, hfw1, i); return; }
    i -= WF;
    if (i < WF) conv8(fw2, hfw2, i);
}

// ---------------- FP16 tensor-core GEMM (dynamic smem, templated) ---------
#define KP 40

extern __shared__ __half g_dynsmem[];

template<int MF, int NF, int NSTG>
__global__ __launch_bounds__(256) void gemm_f16_kernel(
    const __half* __restrict__ A, const __half* __restrict__ W,
    const float* __restrict__ bias, float* C, __half* Ch,
    int M, int N, int K, int relu,
    const __half* __restrict__ W2,
    const float* __restrict__ bias2,
    float* C2, __half* C2h)
{
    constexpr int BM = 64 * MF;
    constexpr int BN = 2 * NF * 8;

    const int tid = threadIdx.x;
    const int lane = tid & 31;
    const int w = tid >> 5;
    const int wm = w & 3;
    const int wn = w >> 2;
    const int g = lane >> 2;
    const int t = lane & 3;

    int bx = blockIdx.x;
    const int nblk = N / BN;
    if (W2 != nullptr && bx >= nblk) {
        bx -= nblk;
        W = W2; bias = bias2; C = C2; Ch = C2h;
    }

    const int m0 = blockIdx.y * BM;
    const int n0 = bx * BN;

    const int nsplit = gridDim.z;
    const int Klen = K / nsplit;
    const int kstart = blockIdx.z * Klen;
    float* Cout = (C && nsplit > 1) ? (C + (size_t)blockIdx.z * M * N) : C;

    const uint32_t as_base = (uint32_t)__cvta_generic_to_shared(g_dynsmem);
    const uint32_t ws_base = as_base + NSTG * BM * KP * 2;

    float acc[MF][NF][4];
    #pragma unroll
    for (int i = 0; i < MF; i++)
        #pragma unroll
        for (int j = 0; j < NF; j++)
            #pragma unroll
            for (int e = 0; e < 4; e++) acc[i][j][e] = 0.f;

    const int m_warp = wm * (16 * MF);
    const int n_warp = wn * (NF * 8);
    const int nIter = Klen / 32;

    const int lr8 = lane & 7;
    const int lb1 = (lane >> 3) & 1;
    const int lb2 = (lane >> 4) & 1;
    uint32_t aAddr[MF];
    #pragma unroll
    for (int mi = 0; mi < MF; mi++) {
        int row = m_warp + mi * 16 + lr8 + lb1 * 8;
        aAddr[mi] = as_base + (row * KP + lb2 * 8) * 2;
    }
    uint32_t bAddr[NF / 2];
    #pragma unroll
    for (int p = 0; p < NF / 2; p++) {
        int row = n_warp + p * 16 + lb2 * 8 + lr8;
        bAddr[p] = ws_base + (row * KP + lb1 * 8) * 2;
    }
    const uint32_t aStride = BM * KP * 2;
    const uint32_t bStride = BN * KP * 2;

    auto load_stage = [&](int st, int it) {
        const int kg = kstart + it * 32;
        #pragma unroll
        for (int s = 0; s < (BM * 4) / 256; s++) {
            int idx = tid + s * 256;
            int r = idx >> 2, kc = (idx & 3) * 8;
            int arow = m0 + r;
            uint32_t dst = as_base + ((st * BM + r) * KP + kc) * 2;
            cp16(dst, A + (size_t)arow * K + kg + kc, (arow < M) ? 16 : 0);
        }
        #pragma unroll
        for (int s = 0; s < (BN * 4) / 256; s++) {
            int idx = tid + s * 256;
            int r = idx >> 2, kc = (idx & 3) * 8;
            uint32_t dst = ws_base + ((st * BN + r) * KP + kc) * 2;
            cp16(dst, W + (size_t)(n0 + r) * K + kg + kc, 16);
        }
        cp_commit();
    };

    gdep_wait();
    #pragma unroll
    for (int s = 0; s < NSTG - 1; s++) load_stage(s, s);

    for (int it = 0; it < nIter; it++) {
        cp_wait<NSTG - 2>();
        __syncthreads();
        if (it + NSTG - 1 < nIter) load_stage((it + NSTG - 1) % NSTG, it + NSTG - 1);
        else cp_commit();

        const int st = it % NSTG;
        #pragma unroll
        for (int kk = 0; kk < 32; kk += 16) {
            uint32_t b0[NF], b1[NF];
            #pragma unroll
            for (int p = 0; p < NF / 2; p++)
                ldsm4(b0[2 * p], b1[2 * p], b0[2 * p + 1], b1[2 * p + 1],
                      bAddr[p] + st * bStride + kk * 2);
            #pragma unroll
            for (int mi = 0; mi < MF; mi++) {
                uint32_t a0, a1, a2, a3;
                ldsm4(a0, a1, a2, a3, aAddr[mi] + st * aStride + kk * 2);
                #pragma unroll
                for (int ni = 0; ni < NF; ni++)
                    mma16h(acc[mi][ni], a0, a1, a2, a3, b0[ni], b1[ni]);
            }
        }
    }

    #pragma unroll
    for (int mi = 0; mi < MF; mi++) {
        #pragma unroll
        for (int ni = 0; ni < NF; ni++) {
            int col = n0 + n_warp + ni * 8 + 2 * t;
            float bz0 = 0.f, bz1 = 0.f;
            if (nsplit == 1) { bz0 = bias[col]; bz1 = bias[col + 1]; }
            int r0 = m0 + m_warp + mi * 16 + g;
            int r1 = r0 + 8;
            float v0 = acc[mi][ni][0] + bz0, v1 = acc[mi][ni][1] + bz1;
            float v2 = acc[mi][ni][2] + bz0, v3 = acc[mi][ni][3] + bz1;
            if (relu) {
                v0 = fmaxf(v0, 0.f); v1 = fmaxf(v1, 0.f);
                v2 = fmaxf(v2, 0.f); v3 = fmaxf(v3, 0.f);
            }
            if (Cout) {
                if (r0 < M) *reinterpret_cast<float2*>(Cout + (size_t)r0 * N + col) = make_float2(v0, v1);
                if (r1 < M) *reinterpret_cast<float2*>(Cout + (size_t)r1 * N + col) = make_float2(v2, v3);
            }
            if (Ch) {
                if (r0 < M) {
                    uint32_t hv = h2bits(v0, v1);
                    *reinterpret_cast<uint32_t*>(Ch + (size_t)r0 * N + col) = hv;
                }
                if (r1 < M) {
                    uint32_t hv = h2bits(v2, v3);
                    *reinterpret_cast<uint32_t*>(Ch + (size_t)r1 * N + col) = hv;
                }
            }
        }
    }
}

// ---------------- warp-per-row LayerNorm core ----------------
__device__ __forceinline__ void lnw_finish(
    float v[8], int lane, const float* g, const float* bt,
    float* out, __half* outh, size_t row)
{
    float s1 = 0.f, s2 = 0.f;
    #pragma unroll
    for (int i = 0; i < 8; i++) { s1 += v[i]; s2 += v[i] * v[i]; }
    #pragma unroll
    for (int o = 16; o > 0; o >>= 1) {
        s1 += __shfl_xor_sync(0xffffffffu, s1, o);
        s2 += __shfl_xor_sync(0xffffffffu, s2, o);
    }
    float mean = s1 * (1.f / DD);
    float var = s2 * (1.f / DD) - mean * mean;
    float rstd = rsqrtf(var + 1e-5f);
    int c0 = lane * 8;
    float r[8];
    #pragma unroll
    for (int i = 0; i < 8; i++)
        r[i] = (v[i] - mean) * rstd * g[c0 + i] + bt[c0 + i];
    if (out) {
        *reinterpret_cast<float4*>(out + row * DD + c0) = make_float4(r[0], r[1], r[2], r[3]);
        *reinterpret_cast<float4*>(out + row * DD + c0 + 4) = make_float4(r[4], r[5], r[6], r[7]);
    }
    if (outh) {
        uint4 u;
        u.x = h2bits(r[0], r[1]);
        u.y = h2bits(r[2], r[3]);
        u.z = h2bits(r[4], r[5]);
        u.w = h2bits(r[6], r[7]);
        *reinterpret_cast<uint4*>(outh + row * DD + c0) = u;
    }
}

__global__ __launch_bounds__(256) void ln_split_kernel(
    const float* __restrict__ X, const float* __restrict__ parts,
    const float* __restrict__ fbias,
    const float* __restrict__ g, const float* __restrict__ bt,
    float* out, __half* outh, int nsplit)
{
    gdep_wait();
    const int lane = threadIdx.x & 31;
    const size_t row = blockIdx.x * 8 + (threadIdx.x >> 5);
    const size_t stride = (size_t)BB * QQ * DD;
    int c0 = lane * 8;
    float v[8];
    float4 x0 = *reinterpret_cast<const float4*>(X + row * DD + c0);
    float4 x1 = *reinterpret_cast<const float4*>(X + row * DD + c0 + 4);
    float4 f0 = *reinterpret_cast<const float4*>(fbias + c0);
    float4 f1 = *reinterpret_cast<const float4*>(fbias + c0 + 4);
    v[0] = x0.x + f0.x; v[1] = x0.y + f0.y; v[2] = x0.z + f0.z; v[3] = x0.w + f0.w;
    v[4] = x1.x + f1.x; v[5] = x1.y + f1.y; v[6] = x1.z + f1.z; v[7] = x1.w + f1.w;
    for (int s = 0; s < nsplit; s++) {
        float4 p0 = *reinterpret_cast<const float4*>(parts + s * stride + row * DD + c0);
        float4 p1 = *reinterpret_cast<const float4*>(parts + s * stride + row * DD + c0 + 4);
        v[0] += p0.x; v[1] += p0.y; v[2] += p0.z; v[3] += p0.w;
        v[4] += p1.x; v[5] += p1.y; v[6] += p1.z; v[7] += p1.w;
    }
    lnw_finish(v, lane, g, bt, out, outh, row);
}

// ---------------- GASA geometric bias ----------------
__global__ __launch_bounds__(128) void gasa_bias_kernel(
    const float* __restrict__ qpos, const float* __restrict__ mpos,
    const float* __restrict__ w1, const float* __restrict__ b1,
    const float* __restrict__ w2, const float* __restrict__ b2,
    const float* __restrict__ betap, float* __restrict__ biasT)
{
    const int l = blockIdx.x;
    const int b = blockIdx.y;
    const int tid = threadIdx.x;

    __shared__ float sw1[KD], sb1[KD], sw2[KD], smp[3], sb2, sbeta;
    if (tid < KD) {
        sw1[tid] = w1[tid];
        sb1[tid] = b1[tid];
        sw2[tid] = w2[tid];
    }
    if (tid < 3) smp[tid] = mpos[((size_t)b * LL + l) * 3 + tid];
    if (tid == 3) sb2 = b2[0];
    if (tid == 4) sbeta = betap[0];
    __syncthreads();

    const float mx = smp[0], my = smp[1], mz = smp[2];
    const float bb2 = sb2, bet = sbeta;
    float* orow = biasT + ((size_t)b * LL + l) * QQ;

    for (int q = tid; q < QQ; q += 128) {
        const float* qp = qpos + ((size_t)b * QQ + q) * 3;
        float dx = qp[0] - mx, dy = qp[1] - my, dz = qp[2] - mz;
        float dist = sqrtf(fmaxf(dx * dx + dy * dy + dz * dz, 0.f));
        float s = 0.f;
        #pragma unroll
        for (int k = 0; k < KD; k++) {
            float h = fmaxf(dist * sw1[k] + sb1[k], 0.f);
            s += h * sw2[k];
        }
        s += bb2;
        s = fminf(fmaxf(s, -10.f), 0.f);
        orow[q] = s * bet;
    }
}

// ---------------- fp16 flash attention (32-key chunks) ----------------
__global__ __launch_bounds__(128) void attn_mma_kernel(
    const __half* __restrict__ Qp, int qstride,
    const __half* __restrict__ Kp, const __half* __restrict__ Vp, int kvstride,
    const float* __restrict__ biasT, int Lk, int S, int step,
    float* __restrict__ pm, float* __restrict__ pl, float* __restrict__ pacc,
    int useBias)
{
    const int b = blockIdx.z, h = blockIdx.y;
    const int sp = blockIdx.x / NQT;
    const int qt = blockIdx.x % NQT;
    const int tid = threadIdx.x;
    const int lane = tid & 31;
    const int warp = tid >> 5;
    const int g = lane >> 2;
    const int t = lane & 3;

    const int q0 = qt * 64 + warp * 16;
    const int qg  = q0 + g;
    const int qg8 = q0 + g + 8;
    const int qgc  = min(qg, QQ - 1);
    const int qg8c = min(qg8, QQ - 1);

    const int ls = sp * step;
    const int le = min(ls + step, Lk);

    gdep_wait();

    uint32_t qa[2][4];
    {
        const uint32_t s2 = h2bits(SCALE, SCALE);
        const __half* q0p = Qp + ((size_t)(b * QQ + qgc)) * qstride + h * HD;
        const __half* q1p = Qp + ((size_t)(b * QQ + qg8c)) * qstride + h * HD;
        #pragma unroll
        for (int ks = 0; ks < 2; ks++) {
            int d = ks * 16 + 2 * t;
            qa[ks][0] = hmul2b(*reinterpret_cast<const uint32_t*>(q0p + d), s2);
            qa[ks][1] = hmul2b(*reinterpret_cast<const uint32_t*>(q1p + d), s2);
            qa[ks][2] = hmul2b(*reinterpret_cast<const uint32_t*>(q0p + d + 8), s2);
            qa[ks][3] = hmul2b(*reinterpret_cast<const uint32_t*>(q1p + d + 8), s2);
        }
    }

    __shared__ __align__(16) __half Kh[32][40];   // [key][d]
    __shared__ __align__(16) __half Vh[HD][40];   // [d][key], 32 keys used
    __shared__ float Bsm[32][68];

    float oacc[4][4];
    #pragma unroll
    for (int i = 0; i < 4; i++)
        #pragma unroll
        for (int j = 0; j < 4; j++) oacc[i][j] = 0.f;
    float om0 = -INFINITY, om1 = -INFINITY;
    float ol0 = 0.f, ol1 = 0.f;

    const int key_l = tid >> 3;          // 0..15 (+16 for second row)
    const int d0 = (tid & 7) * 4;
    const int bq0 = (tid & 7) * 8;
    const bool qtail = (qt == NQT - 1);

    const uint32_t kh_base = (uint32_t)__cvta_generic_to_shared(&Kh[0][0]);
    const uint32_t vh_base = (uint32_t)__cvta_generic_to_shared(&Vh[0][0]);
    const int lr8 = lane & 7;
    const int lb1 = (lane >> 3) & 1;
    const int lb2 = (lane >> 4) & 1;
    const uint32_t kAddr = kh_base + ((lb2 * 8 + lr8) * 40 + lb1 * 8) * 2;
    uint32_t vAddr[2];
    #pragma unroll
    for (int p = 0; p < 2; p++)
        vAddr[p] = vh_base + ((p * 16 + lb2 * 8 + lr8) * 40 + lb1 * 8) * 2;

    uint2 kreg[2], vreg[2];
    float4 bregA[2], bregB[2];

    auto prefetch = [&](int l0) {
        #pragma unroll
        for (int j = 0; j < 2; j++) {
            int grow = b * Lk + min(l0 + key_l + j * 16, Lk - 1);
            kreg[j] = *reinterpret_cast<const uint2*>(
                Kp + (size_t)grow * kvstride + h * HD + d0);
            vreg[j] = *reinterpret_cast<const uint2*>(
                Vp + (size_t)grow * kvstride + h * HD + d0);
            if (useBias) {
                const float* brow = biasT
                    + ((size_t)(b * Lk + l0 + key_l + j * 16)) * QQ
                    + qt * 64 + bq0;
                if (!qtail) {
                    bregA[j] = *reinterpret_cast<const float4*>(brow);
                    bregB[j] = *reinterpret_cast<const float4*>(brow + 4);
                } else {
                    int qb = qt * 64 + bq0;
                    float e[8];
                    #pragma unroll
                    for (int i = 0; i < 8; i++)
                        e[i] = (qb + i < QQ) ? brow[i] : 0.f;
                    bregA[j] = make_float4(e[0], e[1], e[2], e[3]);
                    bregB[j] = make_float4(e[4], e[5], e[6], e[7]);
                }
            }
        }
    };

    prefetch(ls);

    for (int l0 = ls; l0 < le; l0 += 32) {
        __syncthreads();
        #pragma unroll
        for (int j = 0; j < 2; j++) {
            int kr = key_l + j * 16;
            *reinterpret_cast<uint2*>(&Kh[kr][d0]) = kreg[j];
            const __half* vh = reinterpret_cast<const __half*>(&vreg[j]);
            Vh[d0 + 0][kr] = vh[0];
            Vh[d0 + 1][kr] = vh[1];
            Vh[d0 + 2][kr] = vh[2];
            Vh[d0 + 3][kr] = vh[3];
            if (useBias) {
                *reinterpret_cast<float4*>(&Bsm[kr][bq0]) = bregA[j];
                *reinterpret_cast<float4*>(&Bsm[kr][bq0 + 4]) = bregB[j];
            }
        }
        if (l0 + 32 < le) prefetch(l0 + 32);
        __syncthreads();

        // --- scores for 32 keys: 2 key-blocks x (2 ldsm + 2 mma pairs) ---
        float sc[2][2][4];
        #pragma unroll
        for (int kb = 0; kb < 2; kb++) {
            sc[kb][0][0] = sc[kb][0][1] = sc[kb][0][2] = sc[kb][0][3] = 0.f;
            sc[kb][1][0] = sc[kb][1][1] = sc[kb][1][2] = sc[kb][1][3] = 0.f;
            #pragma unroll
            for (int ks = 0; ks < 2; ks++) {
                uint32_t r0, r1, r2, r3;
                ldsm4(r0, r1, r2, r3, kAddr + kb * 1280 + ks * 32);
                mma16h(sc[kb][0], qa[ks][0], qa[ks][1], qa[ks][2], qa[ks][3], r0, r1);
                mma16h(sc[kb][1], qa[ks][0], qa[ks][1], qa[ks][2], qa[ks][3], r2, r3);
            }
        }

        // --- bias + key-bound mask ---
        #pragma unroll
        for (int kb = 0; kb < 2; kb++)
            #pragma unroll
            for (int nf = 0; nf < 2; nf++) {
                if (useBias) {
                    int brow = kb * 16 + nf * 8 + 2 * t;
                    int c0 = warp * 16 + g;
                    sc[kb][nf][0] += Bsm[brow][c0];
                    sc[kb][nf][1] += Bsm[brow + 1][c0];
                    sc[kb][nf][2] += Bsm[brow][c0 + 8];
                    sc[kb][nf][3] += Bsm[brow + 1][c0 + 8];
                }
                int kc = l0 + kb * 16 + nf * 8 + 2 * t;
                if (kc >= le)     { sc[kb][nf][0] = -1e30f; sc[kb][nf][2] = -1e30f; }
                if (kc + 1 >= le) { sc[kb][nf][1] = -1e30f; sc[kb][nf][3] = -1e30f; }
            }

        // --- row max + online rescale ---
        float mx0 = -INFINITY, mx1 = -INFINITY;
        #pragma unroll
        for (int kb = 0; kb < 2; kb++)
            #pragma unroll
            for (int nf = 0; nf < 2; nf++) {
                mx0 = fmaxf(mx0, fmaxf(sc[kb][nf][0], sc[kb][nf][1]));
                mx1 = fmaxf(mx1, fmaxf(sc[kb][nf][2], sc[kb][nf][3]));
            }
        mx0 = fmaxf(mx0, __shfl_xor_sync(0xffffffffu, mx0, 1));
        mx0 = fmaxf(mx0, __shfl_xor_sync(0xffffffffu, mx0, 2));
        mx1 = fmaxf(mx1, __shfl_xor_sync(0xffffffffu, mx1, 1));
        mx1 = fmaxf(mx1, __shfl_xor_sync(0xffffffffu, mx1, 2));

        float nm0 = fmaxf(om0, mx0), nm1 = fmaxf(om1, mx1);
        float cr0 = __expf(om0 - nm0), cr1 = __expf(om1 - nm1);
        om0 = nm0; om1 = nm1;
        ol0 *= cr0; ol1 *= cr1;
        #pragma unroll
        for (int nd = 0; nd < 4; nd++) {
            oacc[nd][0] *= cr0; oacc[nd][1] *= cr0;
            oacc[nd][2] *= cr1; oacc[nd][3] *= cr1;
        }

        // --- P = exp(S - m) ---
        #pragma unroll
        for (int kb = 0; kb < 2; kb++)
            #pragma unroll
            for (int nf = 0; nf < 2; nf++) {
                sc[kb][nf][0] = __expf(sc[kb][nf][0] - nm0);
                sc[kb][nf][1] = __expf(sc[kb][nf][1] - nm0);
                sc[kb][nf][2] = __expf(sc[kb][nf][2] - nm1);
                sc[kb][nf][3] = __expf(sc[kb][nf][3] - nm1);
                ol0 += sc[kb][nf][0] + sc[kb][nf][1];
                ol1 += sc[kb][nf][2] + sc[kb][nf][3];
            }

        // --- PV per key-block: C-frag == A-frag ---
        #pragma unroll
        for (int kb = 0; kb < 2; kb++) {
            uint32_t pa0 = h2bits(sc[kb][0][0], sc[kb][0][1]);
            uint32_t pa1 = h2bits(sc[kb][0][2], sc[kb][0][3]);
            uint32_t pa2 = h2bits(sc[kb][1][0], sc[kb][1][1]);
            uint32_t pa3 = h2bits(sc[kb][1][2], sc[kb][1][3]);
            uint32_t b0[4], b1[4];
            ldsm4(b0[0], b1[0], b0[1], b1[1], vAddr[0] + kb * 32);
            ldsm4(b0[2], b1[2], b0[3], b1[3], vAddr[1] + kb * 32);
            #pragma unroll
            for (int nd = 0; nd < 4; nd++)
                mma16h(oacc[nd], pa0, pa1, pa2, pa3, b0[nd], b1[nd]);
        }
    }

    ol0 += __shfl_xor_sync(0xffffffffu, ol0, 1);
    ol0 += __shfl_xor_sync(0xffffffffu, ol0, 2);
    ol1 += __shfl_xor_sync(0xffffffffu, ol1, 1);
    ol1 += __shfl_xor_sync(0xffffffffu, ol1, 2);

    size_t pbase = ((size_t)((b * HH + h) * S + sp)) * QQ;
    if (qg < QQ) {
        if (t == 0) { pm[pbase + qg] = om0; pl[pbase + qg] = ol0; }
        float* ap = pacc + (pbase + qg) * HD;
        #pragma unroll
        for (int nd = 0; nd < 4; nd++)
            *reinterpret_cast<float2*>(ap + nd * 8 + 2 * t) =
                make_float2(oacc[nd][0], oacc[nd][1]);
    }
    if (qg8 < QQ) {
        if (t == 0) { pm[pbase + qg8] = om1; pl[pbase + qg8] = ol1; }
        float* ap = pacc + (pbase + qg8) * HD;
        #pragma unroll
        for (int nd = 0; nd < 4; nd++)
            *reinterpret_cast<float2*>(ap + nd * 8 + 2 * t) =
                make_float2(oacc[nd][2], oacc[nd][3]);
    }
}

// ---------------- split combine ----------------
__global__ __launch_bounds__(256) void attn_combine_kernel(
    const float* __restrict__ pm, const float* __restrict__ pl,
    const float* __restrict__ pacc, int S, __half* __restrict__ out)
{
    gdep_wait();
    int tt = blockIdx.x * 256 + threadIdx.x;
    if (tt >= BB * HH * QQ * (HD / 2)) return;
    int dp = tt & (HD / 2 - 1);
    int idx = tt >> 4;
    int q = idx % QQ;
    int bh = idx / QQ;
    int b = bh / HH, h = bh % HH;

    float mg = -INFINITY;
    for (int s = 0; s < S; s++)
        mg = fmaxf(mg, pm[((size_t)bh * S + s) * QQ + q]);
    float Lsum = 0.f;
    float olo = 0.f, ohi = 0.f;
    for (int s = 0; s < S; s++) {
        size_t pidx = ((size_t)bh * S + s) * QQ + q;
        float w = __expf(pm[pidx] - mg);
        Lsum += pl[pidx] * w;
        float2 a = *reinterpret_cast<const float2*>(pacc + pidx * HD + 2 * dp);
        olo += w * a.x; ohi += w * a.y;
    }
    float inv = 1.f / Lsum;
    uint32_t hv = h2bits(olo * inv, ohi * inv);
    *reinterpret_cast<uint32_t*>(
        out + ((size_t)(b * QQ + q)) * DD + h * HD + 2 * dp) = hv;
}

// ---------------- host launcher ----------------
static inline int cdiv(int a, int b) { return (a + b - 1) / b; }

#define SMEM_G28 (4 * (128 + 128) * KP * 2)   // 81920 (NSTG=4)
#define SMEM_G14 (3 * (64 + 64) * KP * 2)     // 30720 (NSTG=3)

template<typename F, typename... Args>
static inline void lpdl(F kernel, dim3 grid, dim3 block, cudaStream_t st,
                        size_t smem, Args... args)
{
    cudaLaunchConfig_t cfg = {};
    cfg.gridDim = grid;
    cfg.blockDim = block;
    cfg.dynamicSmemBytes = smem;
    cfg.stream = st;
    cudaLaunchAttribute attr[1];
    attr[0].id = cudaLaunchAttributeProgrammaticStreamSerialization;
    attr[0].val.programmaticStreamSerializationAllowed = 1;
    cfg.attrs = attr;
    cfg.numAttrs = 1;
    cudaLaunchKernelEx(&cfg, kernel, args...);
}

extern "C" void kernel_launch(void* const* d_in, const int* in_sizes, int n_in,
                              void* d_out, int out_size)
{
    const float* queries   = (const float*)d_in[0];
    const float* memory    = (const float*)d_in[1];
    const float* memory_pos= (const float*)d_in[2];
    const float* query_pos = (const float*)d_in[3];
    const float* sa_in_w   = (const float*)d_in[4];
    const float* sa_in_b   = (const float*)d_in[5];
    const float* sa_out_w  = (const float*)d_in[6];
    const float* sa_out_b  = (const float*)d_in[7];
    const float* norm1_g   = (const float*)d_in[8];
    const float* norm1_b   = (const float*)d_in[9];
    const float* q_w       = (const float*)d_in[10];
    const float* q_b       = (const float*)d_in[11];
    const float* k_w       = (const float*)d_in[12];
    const float* k_b       = (const float*)d_in[13];
    const float* v_w       = (const float*)d_in[14];
    const float* v_b       = (const float*)d_in[15];
    const float* o_w       = (const float*)d_in[16];
    const float* o_b       = (const float*)d_in[17];
    const float* norm2_g   = (const float*)d_in[18];
    const float* norm2_b   = (const float*)d_in[19];
    const float* beta      = (const float*)d_in[20];
    const float* dk_w1     = (const float*)d_in[21];
    const float* dk_b1     = (const float*)d_in[22];
    const float* dk_w2     = (const float*)d_in[23];
    const float* dk_b2     = (const float*)d_in[24];
    const float* ffn_w1    = (const float*)d_in[25];
    const float* ffn_b1    = (const float*)d_in[26];
    const float* ffn_w2    = (const float*)d_in[27];
    const float* ffn_b2    = (const float*)d_in[28];
    const float* norm3_g   = (const float*)d_in[29];
    const float* norm3_b   = (const float*)d_in[30];

    float *g_x1, *g_x2, *g_bias, *g_part, *g_pm, *g_pl, *g_pacc;
    cudaGetSymbolAddress((void**)&g_x1,   s_x1);
    cudaGetSymbolAddress((void**)&g_x2,   s_x2);
    cudaGetSymbolAddress((void**)&g_bias, s_bias);
    cudaGetSymbolAddress((void**)&g_part, s_part);
    cudaGetSymbolAddress((void**)&g_pm,   s_pm);
    cudaGetSymbolAddress((void**)&g_pl,   s_pl);
    cudaGetSymbolAddress((void**)&g_pacc, s_pacc);

    __half *hq, *hm, *h_siw, *h_sow, *h_qw, *h_kw, *h_vw, *h_ow,
           *h_fw1, *h_fw2, *hqkv, *hqx, *hkk, *hvv, *hsa, *hca,
           *hx1, *hx2, *hffn;
    cudaGetSymbolAddress((void**)&hq,    h_queries);
    cudaGetSymbolAddress((void**)&hm,    h_memory);
    cudaGetSymbolAddress((void**)&h_siw, h_sa_in_w);
    cudaGetSymbolAddress((void**)&h_sow, h_sa_out_w);
    cudaGetSymbolAddress((void**)&h_qw,  h_q_w);
    cudaGetSymbolAddress((void**)&h_kw,  h_k_w);
    cudaGetSymbolAddress((void**)&h_vw,  h_v_w);
    cudaGetSymbolAddress((void**)&h_ow,  h_o_w);
    cudaGetSymbolAddress((void**)&h_fw1, h_ffn_w1);
    cudaGetSymbolAddress((void**)&h_fw2, h_ffn_w2);
    cudaGetSymbolAddress((void**)&hqkv,  h_qkv);
    cudaGetSymbolAddress((void**)&hqx,   h_qx);
    cudaGetSymbolAddress((void**)&hkk,   h_kk);
    cudaGetSymbolAddress((void**)&hvv,   h_vv);
    cudaGetSymbolAddress((void**)&hsa,   h_sa);
    cudaGetSymbolAddress((void**)&hca,   h_ca);
    cudaGetSymbolAddress((void**)&hx1,   h_x1);
    cudaGetSymbolAddress((void**)&hx2,   h_x2);
    cudaGetSymbolAddress((void**)&hffn,  h_ffn);

    static cudaStream_t st2 = nullptr, st3 = nullptr, st4 = nullptr;
    static cudaEvent_t ev0 = nullptr, ev2 = nullptr, ev3 = nullptr,
                       ev4 = nullptr, ev5 = nullptr;
    if (st2 == nullptr) {
        cudaStreamCreateWithFlags(&st2, cudaStreamNonBlocking);
        cudaStreamCreateWithFlags(&st3, cudaStreamNonBlocking);
        cudaStreamCreateWithFlags(&st4, cudaStreamNonBlocking);
        cudaEventCreateWithFlags(&ev0, cudaEventDisableTiming);
        cudaEventCreateWithFlags(&ev2, cudaEventDisableTiming);
        cudaEventCreateWithFlags(&ev3, cudaEventDisableTiming);
        cudaEventCreateWithFlags(&ev4, cudaEventDisableTiming);
        cudaEventCreateWithFlags(&ev5, cudaEventDisableTiming);
        cudaFuncSetAttribute(gemm_f16_kernel<2, 8, 4>,
                             cudaFuncAttributeMaxDynamicSharedMemorySize,
                             SMEM_G28);
        cudaFuncSetAttribute(gemm_f16_kernel<1, 4, 3>,
                             cudaFuncAttributeMaxDynamicSharedMemorySize,
                             SMEM_G14);
    }

    const int Mq = BB * QQ;   // 2400
    const int Mm = BB * LL;   // 8192
    const int NCOMB = BB * HH * QQ * (HD / 2);

    // ---- fork ----
    cudaEventRecord(ev0, 0);
    cudaStreamWaitEvent(st2, ev0, 0);
    cudaStreamWaitEvent(st3, ev0, 0);
    cudaStreamWaitEvent(st4, ev0, 0);

    // st2: memory + KV weights conversion, then fused KV GEMM (fp16 out)
    lpdl(f2h_kernel, cdiv(Mm * DD / 8, 256), 256, st2, 0, memory, hm, Mm * DD);
    lpdl(f2h_kernel, cdiv(WSEG / 8, 256), 256, st2, 0, k_w, h_kw, WSEG);
    lpdl(f2h_kernel, cdiv(WSEG / 8, 256), 256, st2, 0, v_w, h_vw, WSEG);
    lpdl(gemm_f16_kernel<2, 8, 4>, dim3(2 * DD / 128, cdiv(Mm, 128), 1), 256, st2,
         SMEM_G28,
         (const __half*)hm, (const __half*)h_kw, k_b, (float*)nullptr, hkk,
         Mm, DD, DD, 0,
         (const __half*)h_vw, v_b, (float*)nullptr, hvv);
    cudaEventRecord(ev2, st2);

    // st3: GASA bias
    lpdl(gasa_bias_kernel, dim3(LL, BB), 128, st3, 0,
         query_pos, memory_pos, dk_w1, dk_b1, dk_w2, dk_b2, beta, g_bias);
    cudaEventRecord(ev3, st3);

    // st4: queries + sa_in_w first, then rest
    lpdl(f2h_kernel, cdiv(Mq * DD / 8, 256), 256, st4, 0, queries, hq, Mq * DD);
    lpdl(f2h_kernel, cdiv(3 * WSEG / 8, 256), 256, st4, 0, sa_in_w, h_siw, 3 * WSEG);
    cudaEventRecord(ev5, st4);
    {
        int total = 3 * WSEG + 2 * WF;
        lpdl(f2h_weights_kernel, cdiv(total / 8, 256), 256, st4, 0,
             sa_out_w, q_w, o_w, ffn_w1, ffn_w2,
             h_sow, h_qw, h_ow, h_fw1, h_fw2);
    }
    cudaEventRecord(ev4, st4);

    // ---- main chain (PDL-linked) ----
    cudaStreamWaitEvent(0, ev5, 0);

    // 1) self-attn packed in-proj -> fp16 qkv (128x128 tile)
    lpdl(gemm_f16_kernel<2, 8, 4>, dim3(3 * DD / 128, cdiv(Mq, 128), 1), 256,
         (cudaStream_t)0, SMEM_G28,
         (const __half*)hq, (const __half*)h_siw, sa_in_b, (float*)nullptr, hqkv,
         Mq, 3 * DD, DD, 0,
         (const __half*)nullptr, (const float*)nullptr, (float*)nullptr, (__half*)nullptr);

    // 2) self-attention, split S=2 -> combine -> h_sa (fp16)
    {
        int S = 2, step = cdiv(QQ, S * 16) * 16;   // 304
        lpdl(attn_mma_kernel, dim3(NQT * S, HH, BB), 128, (cudaStream_t)0, 0,
             (const __half*)hqkv, 3 * DD,
             (const __half*)(hqkv + DD), (const __half*)(hqkv + 2 * DD), 3 * DD,
             (const float*)nullptr, QQ, S, step, g_pm, g_pl, g_pacc, 0);
        lpdl(attn_combine_kernel, cdiv(NCOMB, 256), 256, (cudaStream_t)0, 0,
             (const float*)g_pm, (const float*)g_pl, (const float*)g_pacc, S, hsa);
    }

    cudaStreamWaitEvent(0, ev4, 0);

    // 3) SA out-proj split-K=2 + LN1 (x1 fp32 + fp16)
    lpdl(gemm_f16_kernel<1, 4, 3>, dim3(DD / 64, cdiv(Mq, 64), 2), 256,
         (cudaStream_t)0, SMEM_G14,
         (const __half*)hsa, (const __half*)h_sow, sa_out_b, g_part, (__half*)nullptr,
         Mq, DD, DD, 0,
         (const __half*)nullptr, (const float*)nullptr, (float*)nullptr, (__half*)nullptr);
    lpdl(ln_split_kernel, Mq / 8, 256, (cudaStream_t)0, 0,
         queries, (const float*)g_part, sa_out_b, norm1_g, norm1_b,
         g_x1, hx1, 2);

    // 4) Q projection -> fp16
    lpdl(gemm_f16_kernel<1, 4, 3>, dim3(DD / 64, cdiv(Mq, 64), 1), 256,
         (cudaStream_t)0, SMEM_G14,
         (const __half*)hx1, (const __half*)h_qw, q_b, (float*)nullptr, hqx,
         Mq, DD, DD, 0,
         (const __half*)nullptr, (const float*)nullptr, (float*)nullptr, (__half*)nullptr);

    cudaStreamWaitEvent(0, ev2, 0);
    cudaStreamWaitEvent(0, ev3, 0);

    // 5) cross-attention, split S=4 -> combine -> h_ca (fp16)
    {
        int S = 4, step = cdiv(LL, S * 16) * 16;
        lpdl(attn_mma_kernel, dim3(NQT * S, HH, BB), 128, (cudaStream_t)0, 0,
             (const __half*)hqx, DD, (const __half*)hkk, (const __half*)hvv, DD,
             (const float*)g_bias, LL, S, step, g_pm, g_pl, g_pacc, 1);
        lpdl(attn_combine_kernel, cdiv(NCOMB, 256), 256, (cudaStream_t)0, 0,
             (const float*)g_pm, (const float*)g_pl, (const float*)g_pacc, S, hca);
    }

    // 6) O proj split-K=2 + LN2 (x2 fp32 + fp16)
    lpdl(gemm_f16_kernel<1, 4, 3>, dim3(DD / 64, cdiv(Mq, 64), 2), 256,
         (cudaStream_t)0, SMEM_G14,
         (const __half*)hca, (const __half*)h_ow, o_b, g_part, (__half*)nullptr,
         Mq, DD, DD, 0,
         (const __half*)nullptr, (const float*)nullptr, (float*)nullptr, (__half*)nullptr);
    lpdl(ln_split_kernel, Mq / 8, 256, (cudaStream_t)0, 0,
         (const float*)g_x1, (const float*)g_part, o_b, norm2_g, norm2_b,
         g_x2, hx2, 2);

    // 7) FFN1 (relu) -> fp16 only (128x128 tile)
    lpdl(gemm_f16_kernel<2, 8, 4>, dim3(DFF / 128, cdiv(Mq, 128), 1), 256,
         (cudaStream_t)0, SMEM_G28,
         (const __half*)hx2, (const __half*)h_fw1, ffn_b1, (float*)nullptr, hffn,
         Mq, DFF, DD, 1,
         (const __half*)nullptr, (const float*)nullptr, (float*)nullptr, (__half*)nullptr);

    // 8) FFN2 split-K=4 partials + fused combine in LN3 -> output
    lpdl(gemm_f16_kernel<1, 4, 3>, dim3(DD / 64, cdiv(Mq, 64), 4), 256,
         (cudaStream_t)0, SMEM_G14,
         (const __half*)hffn, (const __half*)h_fw2, ffn_b2, g_part, (__half*)nullptr,
         Mq, DD, DFF, 0,
         (const __half*)nullptr, (const float*)nullptr, (float*)nullptr, (__half*)nullptr);
    lpdl(ln_split_kernel, Mq / 8, 256, (cudaStream_t)0, 0,
         (const float*)g_x2, (const float*)g_part, ffn_b2, norm3_g, norm3_b,
         (float*)d_out, (__half*)nullptr, 4);
}